// round 2
// baseline (speedup 1.0000x reference)
#include <cuda_runtime.h>
#include <cstdint>
#include <cstddef>

// Problem constants (fixed by the dataset)
static constexpr int NN  = 8000;    // nodes
static constexpr int EE  = 64000;   // directed edges (pre self-loop)
static constexpr int ET  = 72000;   // edges + self loops
static constexpr int FIN = 3201;    // input feature dim
static constexpr int CH  = 512;     // channels per head

// ---------------- scratch (device globals; no allocation allowed) ----------
__device__ float g_hbn [(size_t)NN * FIN];   // BN0 output
__device__ float g_xl  [(size_t)NN * 1024];
__device__ float g_xr  [(size_t)NN * 1024];
__device__ float g_h   [(size_t)NN * 1024];  // layer activations
__device__ float g_agg [(size_t)NN * 1024];
__device__ float g_sum [FIN];
__device__ float g_sq  [FIN];
__device__ float g_scale[FIN];
__device__ float g_shift[FIN];
__device__ int   g_src [ET];
__device__ int   g_dst [ET];
__device__ float g_deg [NN];
__device__ float g_e   [ET * 2];
__device__ int   g_emax[NN * 2];
__device__ float g_denom[NN * 2];
__device__ float g_pred[NN];

// ---------------- helpers ---------------------------------------------------
__device__ __forceinline__ int fkey(float f) {
    unsigned u = __float_as_uint(f);
    unsigned U = (u & 0x80000000u) ? ~u : (u | 0x80000000u);
    return (int)(U ^ 0x80000000u);
}
__device__ __forceinline__ float fdecode(int k) {
    unsigned u = (k >= 0) ? (unsigned)k : ~((unsigned)k ^ 0x80000000u);
    return __uint_as_float(u);
}

__global__ void k_zero_f(float* p, size_t n) {
    for (size_t i = (size_t)blockIdx.x * blockDim.x + threadIdx.x; i < n;
         i += (size_t)gridDim.x * blockDim.x)
        p[i] = 0.f;
}
__global__ void k_fill_i(int* p, int v, size_t n) {
    for (size_t i = (size_t)blockIdx.x * blockDim.x + threadIdx.x; i < n;
         i += (size_t)gridDim.x * blockDim.x)
        p[i] = v;
}

// build edge list with self loops; zero deg
__global__ void k_build_edges(const int* __restrict__ ei, int* src, int* dst, float* deg) {
    int i = blockIdx.x * blockDim.x + threadIdx.x;
    if (i < EE) { src[i] = ei[i]; dst[i] = ei[EE + i]; }
    if (i < NN) { src[EE + i] = i; dst[EE + i] = i; deg[i] = 0.f; }
}
__global__ void k_deg(const int* __restrict__ dst, float* deg) {
    int i = blockIdx.x * blockDim.x + threadIdx.x;
    if (i < ET) atomicAdd(&deg[dst[i]], 1.f);
}

// ---------------- batchnorm ------------------------------------------------
__global__ void k_col_stats(const float* __restrict__ X, float* sum, float* sq,
                            int M, int F) {
    int col = blockIdx.x * blockDim.x + threadIdx.x;
    if (col >= F) return;
    int chunks = gridDim.y;
    int per = (M + chunks - 1) / chunks;
    int r0 = blockIdx.y * per;
    int r1 = min(M, r0 + per);
    float s = 0.f, q = 0.f;
    for (int r = r0; r < r1; r++) {
        float v = X[(size_t)r * F + col];
        s += v; q += v * v;
    }
    atomicAdd(&sum[col], s);
    atomicAdd(&sq[col], q);
}
__global__ void k_bn_coeffs(const float* __restrict__ g, const float* __restrict__ b,
                            const float* __restrict__ sum, const float* __restrict__ sq,
                            float* scale, float* shift, float invM, int F) {
    int c = blockIdx.x * blockDim.x + threadIdx.x;
    if (c >= F) return;
    float m = sum[c] * invM;
    float v = sq[c] * invM - m * m;
    float r = rsqrtf(v + 1e-5f);
    float sc = g[c] * r;
    scale[c] = sc;
    shift[c] = b[c] - m * sc;
}
__global__ void k_bn_apply(const float* __restrict__ in, float* __restrict__ out,
                           const float* __restrict__ scale, const float* __restrict__ shift,
                           size_t total, int F, int relu) {
    for (size_t i = (size_t)blockIdx.x * blockDim.x + threadIdx.x; i < total;
         i += (size_t)gridDim.x * blockDim.x) {
        int c = (int)(i % (size_t)F);
        float v = in[i] * scale[c] + shift[c];
        if (relu) v = fmaxf(v, 0.f);
        out[i] = v;
    }
}

// ---------------- SGEMM: C[M,N] = A[M,K] @ B[K,N] (row major, fp32) --------
#define TM 128
#define TN 128
#define TK 16
__global__ __launch_bounds__(256) void k_sgemm(const float* __restrict__ A,
                                               const float* __restrict__ B,
                                               float* __restrict__ C,
                                               int M, int N, int K) {
    __shared__ float As[TK][TM];
    __shared__ float Bs[TK][TN];
    int tid = threadIdx.x;
    int tx = tid & 15, ty = tid >> 4;
    int row0 = blockIdx.y * TM, col0 = blockIdx.x * TN;
    float acc[8][8];
#pragma unroll
    for (int i = 0; i < 8; i++)
#pragma unroll
        for (int j = 0; j < 8; j++) acc[i][j] = 0.f;

    for (int k0 = 0; k0 < K; k0 += TK) {
#pragma unroll
        for (int i = 0; i < 8; i++) {
            int idx = tid + i * 256;
            int r = idx >> 4, c = idx & 15;
            int gr = row0 + r, gk = k0 + c;
            As[c][r] = (gr < M && gk < K) ? __ldg(&A[(size_t)gr * K + gk]) : 0.f;
        }
#pragma unroll
        for (int i = 0; i < 8; i++) {
            int idx = tid + i * 256;
            int r = idx >> 7, c = idx & 127;
            int gk = k0 + r, gc = col0 + c;
            Bs[r][c] = (gk < K && gc < N) ? __ldg(&B[(size_t)gk * N + gc]) : 0.f;
        }
        __syncthreads();
#pragma unroll
        for (int kk = 0; kk < TK; kk++) {
            float a[8], b[8];
#pragma unroll
            for (int i = 0; i < 8; i++) a[i] = As[kk][ty * 8 + i];
#pragma unroll
            for (int j = 0; j < 8; j++) b[j] = Bs[kk][tx * 8 + j];
#pragma unroll
            for (int i = 0; i < 8; i++)
#pragma unroll
                for (int j = 0; j < 8; j++) acc[i][j] += a[i] * b[j];
        }
        __syncthreads();
    }
#pragma unroll
    for (int i = 0; i < 8; i++) {
        int gr = row0 + ty * 8 + i;
        if (gr >= M) break;
#pragma unroll
        for (int j = 0; j < 8; j++) {
            int gc = col0 + tx * 8 + j;
            if (gc < N) C[(size_t)gr * N + gc] = acc[i][j];
        }
    }
}

// ---------------- GATv2 edge kernels ---------------------------------------
template <int H>
__global__ void k_edge_scores(const float* __restrict__ xl, const float* __restrict__ xr,
                              const float* __restrict__ att,
                              const int* __restrict__ src, const int* __restrict__ dst,
                              float* __restrict__ e, int* __restrict__ emax) {
    int gw = (blockIdx.x * blockDim.x + threadIdx.x) >> 5;
    int lane = threadIdx.x & 31;
    if (gw >= ET * H) return;
    int edge = gw / H, h = gw % H;
    int s = src[edge], d = dst[edge];
    const float* pl = xl + (size_t)s * (H * CH) + h * CH;
    const float* pr = xr + (size_t)d * (H * CH) + h * CH;
    const float* pa = att + h * CH;
    float acc = 0.f;
#pragma unroll
    for (int c = lane; c < CH; c += 32) {
        float z = pl[c] + pr[c];
        z = z > 0.f ? z : 0.2f * z;
        acc += z * pa[c];
    }
#pragma unroll
    for (int o = 16; o; o >>= 1) acc += __shfl_xor_sync(0xFFFFFFFFu, acc, o);
    if (lane == 0) {
        e[(size_t)edge * H + h] = acc;
        atomicMax(&emax[d * H + h], fkey(acc));
    }
}

template <int H>
__global__ void k_edge_exp(const int* __restrict__ dst, const int* __restrict__ emax,
                           float* __restrict__ e, float* __restrict__ denom) {
    int i = blockIdx.x * blockDim.x + threadIdx.x;
    if (i >= ET * H) return;
    int edge = i / H, h = i % H;
    int d = dst[edge];
    float mx = fdecode(emax[d * H + h]);
    float ex = expf(e[i] - mx);
    e[i] = ex;
    atomicAdd(&denom[d * H + h], ex);
}

template <int H>
__global__ void k_edge_agg(const float* __restrict__ xl, const float* __restrict__ e,
                           const float* __restrict__ denom,
                           const int* __restrict__ src, const int* __restrict__ dst,
                           float* __restrict__ agg) {
    int gw = (blockIdx.x * blockDim.x + threadIdx.x) >> 5;
    int lane = threadIdx.x & 31;
    if (gw >= ET * H) return;
    int edge = gw / H, h = gw % H;
    int s = src[edge], d = dst[edge];
    float alpha = e[(size_t)edge * H + h] / denom[d * H + h];
    const float* pl = xl + (size_t)s * (H * CH) + h * CH;
    float* pa = agg + (size_t)d * (H * CH) + h * CH;
#pragma unroll
    for (int c = lane; c < CH; c += 32)
        atomicAdd(&pa[c], alpha * pl[c]);
}

__global__ void k_gat_out(const float* __restrict__ agg, const float* __restrict__ deg,
                          const float* __restrict__ bias, float* __restrict__ hout,
                          size_t total, int HC, int relu) {
    for (size_t i = (size_t)blockIdx.x * blockDim.x + threadIdx.x; i < total;
         i += (size_t)gridDim.x * blockDim.x) {
        int n = (int)(i / (size_t)HC);
        int f = (int)(i % (size_t)HC);
        float v = agg[i] / deg[n] + bias[f];
        if (relu) v = fmaxf(v, 0.f);
        hout[i] = v;
    }
}

// ---------------- head + gather --------------------------------------------
__global__ void k_head(const float* __restrict__ h, const float* __restrict__ Wh,
                       const float* __restrict__ bh, float* __restrict__ pred) {
    int gw = (blockIdx.x * blockDim.x + threadIdx.x) >> 5;
    int lane = threadIdx.x & 31;
    if (gw >= NN) return;
    const float* ph = h + (size_t)gw * CH;
    float acc = 0.f;
#pragma unroll
    for (int c = lane; c < CH; c += 32) acc += ph[c] * Wh[c];
#pragma unroll
    for (int o = 16; o; o >>= 1) acc += __shfl_xor_sync(0xFFFFFFFFu, acc, o);
    if (lane == 0) {
        float t = acc + bh[0];
        pred[gw] = 1.f / (1.f + expf(-t));
    }
}
__global__ void k_gather(const float* __restrict__ pred, const float* __restrict__ y,
                         const int* __restrict__ tidx, float* __restrict__ out, int ntr) {
    int i = blockIdx.x * blockDim.x + threadIdx.x;
    if (i >= ntr) return;
    int j = tidx[i];
    out[i] = pred[j];
    out[ntr + i] = y[j];
}

// ---------------- host-side orchestration ----------------------------------
static inline int gblocks(size_t n, int tpb) {
    size_t b = (n + tpb - 1) / tpb;
    if (b > 65535u * 4u) b = 65535u * 4u;
    return (int)b;
}

struct Ptrs {
    float *hbn, *xl, *xr, *h, *agg, *sum, *sq, *scale, *shift, *deg, *e, *denom, *pred;
    int *src, *dst, *emax;
};

static void bn_stats_apply(const float* in, float* out, const float* g, const float* b,
                           int F, bool relu, Ptrs& P) {
    k_zero_f<<<gblocks(F, 256), 256>>>(P.sum, (size_t)F);
    k_zero_f<<<gblocks(F, 256), 256>>>(P.sq, (size_t)F);
    dim3 sg((F + 255) / 256, 32);
    k_col_stats<<<sg, 256>>>(in, P.sum, P.sq, NN, F);
    k_bn_coeffs<<<(F + 255) / 256, 256>>>(g, b, P.sum, P.sq, P.scale, P.shift,
                                          1.f / (float)NN, F);
    size_t total = (size_t)NN * F;
    k_bn_apply<<<gblocks(total, 256), 256>>>(in, out, P.scale, P.shift, total, F,
                                             relu ? 1 : 0);
}

static void gat_layer(const float* hin, int Fin, const float* Wl, const float* Wr,
                      const float* att, const float* bias, int H, float* hout,
                      bool relu_out, Ptrs& P) {
    int HC = H * CH;
    dim3 gg(HC / TN, (NN + TM - 1) / TM);
    k_sgemm<<<gg, 256>>>(hin, Wl, P.xl, NN, HC, Fin);
    k_sgemm<<<gg, 256>>>(hin, Wr, P.xr, NN, HC, Fin);
    k_fill_i<<<gblocks((size_t)NN * H, 256), 256>>>(P.emax, (int)0x80000000, (size_t)NN * H);
    k_zero_f<<<gblocks((size_t)NN * H, 256), 256>>>(P.denom, (size_t)NN * H);
    k_zero_f<<<gblocks((size_t)NN * HC, 256), 256>>>(P.agg, (size_t)NN * HC);

    int nwork = ET * H;
    int thr = nwork * 32;
    int bl = (thr + 255) / 256;
    if (H == 2) {
        k_edge_scores<2><<<bl, 256>>>(P.xl, P.xr, att, P.src, P.dst, P.e, P.emax);
        k_edge_exp<2><<<(nwork + 255) / 256, 256>>>(P.dst, P.emax, P.e, P.denom);
        k_edge_agg<2><<<bl, 256>>>(P.xl, P.e, P.denom, P.src, P.dst, P.agg);
    } else {
        k_edge_scores<1><<<bl, 256>>>(P.xl, P.xr, att, P.src, P.dst, P.e, P.emax);
        k_edge_exp<1><<<(nwork + 255) / 256, 256>>>(P.dst, P.emax, P.e, P.denom);
        k_edge_agg<1><<<bl, 256>>>(P.xl, P.e, P.denom, P.src, P.dst, P.agg);
    }
    size_t total = (size_t)NN * HC;
    k_gat_out<<<gblocks(total, 256), 256>>>(P.agg, P.deg, bias, hout, total, HC,
                                            relu_out ? 1 : 0);
}

extern "C" void kernel_launch(void* const* d_in, const int* in_sizes, int n_in,
                              void* d_out, int out_size) {
    // inputs in metadata order
    const float* x     = (const float*)d_in[0];
    const int*   ei    = (const int*)d_in[1];
    const float* y     = (const float*)d_in[2];
    const int*   tidx  = (const int*)d_in[3];
    const float* bn0_g = (const float*)d_in[4];
    const float* bn0_b = (const float*)d_in[5];
    const float* W1l   = (const float*)d_in[6];
    const float* W1r   = (const float*)d_in[7];
    const float* a1    = (const float*)d_in[8];
    const float* b1    = (const float*)d_in[9];
    const float* bn1_g = (const float*)d_in[10];
    const float* bn1_b = (const float*)d_in[11];
    const float* W2l   = (const float*)d_in[12];
    const float* W2r   = (const float*)d_in[13];
    const float* a2    = (const float*)d_in[14];
    const float* b2    = (const float*)d_in[15];
    const float* bn2_g = (const float*)d_in[16];
    const float* bn2_b = (const float*)d_in[17];
    const float* W3l   = (const float*)d_in[18];
    const float* W3r   = (const float*)d_in[19];
    const float* a3    = (const float*)d_in[20];
    const float* b3    = (const float*)d_in[21];
    const float* bn3_g = (const float*)d_in[22];
    const float* bn3_b = (const float*)d_in[23];
    const float* W4l   = (const float*)d_in[24];
    const float* W4r   = (const float*)d_in[25];
    const float* a4    = (const float*)d_in[26];
    const float* b4    = (const float*)d_in[27];
    const float* Wh    = (const float*)d_in[28];
    const float* bh    = (const float*)d_in[29];
    float* out = (float*)d_out;
    int ntr = in_sizes[3];

    Ptrs P;
    cudaGetSymbolAddress((void**)&P.hbn, g_hbn);
    cudaGetSymbolAddress((void**)&P.xl, g_xl);
    cudaGetSymbolAddress((void**)&P.xr, g_xr);
    cudaGetSymbolAddress((void**)&P.h, g_h);
    cudaGetSymbolAddress((void**)&P.agg, g_agg);
    cudaGetSymbolAddress((void**)&P.sum, g_sum);
    cudaGetSymbolAddress((void**)&P.sq, g_sq);
    cudaGetSymbolAddress((void**)&P.scale, g_scale);
    cudaGetSymbolAddress((void**)&P.shift, g_shift);
    cudaGetSymbolAddress((void**)&P.deg, g_deg);
    cudaGetSymbolAddress((void**)&P.e, g_e);
    cudaGetSymbolAddress((void**)&P.denom, g_denom);
    cudaGetSymbolAddress((void**)&P.pred, g_pred);
    cudaGetSymbolAddress((void**)&P.src, g_src);
    cudaGetSymbolAddress((void**)&P.dst, g_dst);
    cudaGetSymbolAddress((void**)&P.emax, g_emax);

    // edges + degree
    int mx = (EE > NN ? EE : NN);
    k_build_edges<<<(mx + 255) / 256, 256>>>(ei, P.src, P.dst, P.deg);
    k_deg<<<(ET + 255) / 256, 256>>>(P.dst, P.deg);

    // BN0 (no relu) -> g_hbn
    bn_stats_apply(x, P.hbn, bn0_g, bn0_b, FIN, false, P);

    // Layer 1: H=2, Fin=3201 -> g_h [N,1024]
    gat_layer(P.hbn, FIN, W1l, W1r, a1, b1, 2, P.h, false, P);
    bn_stats_apply(P.h, P.h, bn1_g, bn1_b, 1024, true, P);

    // Layer 2: H=1, Fin=1024 -> g_h [N,512]
    gat_layer(P.h, 1024, W2l, W2r, a2, b2, 1, P.h, false, P);
    bn_stats_apply(P.h, P.h, bn2_g, bn2_b, 512, true, P);

    // Layer 3
    gat_layer(P.h, 512, W3l, W3r, a3, b3, 1, P.h, false, P);
    bn_stats_apply(P.h, P.h, bn3_g, bn3_b, 512, true, P);

    // Layer 4 (relu on output, no BN)
    gat_layer(P.h, 512, W4l, W4r, a4, b4, 1, P.h, true, P);

    // head + gather
    k_head<<<(NN * 32 + 255) / 256, 256>>>(P.h, Wh, bh, P.pred);
    k_gather<<<(ntr + 255) / 256, 256>>>(P.pred, y, tidx, out, ntr);
}

// round 3
// speedup vs baseline: 1.3653x; 1.3653x over previous
#include <cuda_runtime.h>
#include <cstdint>
#include <cstddef>

// Problem constants (fixed by the dataset)
static constexpr int NN  = 8000;    // nodes
static constexpr int EE  = 64000;   // directed edges (pre self-loop)
static constexpr int ET  = 72000;   // edges + self loops
static constexpr int FIN = 3201;    // input feature dim
static constexpr int CH  = 512;     // channels per head

// ---------------- scratch (device globals; no allocation allowed) ----------
__device__ float g_hbn [(size_t)NN * FIN];   // BN0 output
__device__ float g_xl  [(size_t)NN * 1024];
__device__ float g_xr  [(size_t)NN * 1024];
__device__ float g_h   [(size_t)NN * 1024];  // layer activations
__device__ float g_agg [(size_t)NN * 1024];
__device__ float g_sum [FIN];
__device__ float g_sq  [FIN];
__device__ float g_scale[FIN];
__device__ float g_shift[FIN];
__device__ int   g_src [ET];
__device__ int   g_dst [ET];
__device__ float g_deg [NN];
__device__ float g_e   [ET * 2];
__device__ int   g_emax[NN * 2];
__device__ float g_denom[NN * 2];
__device__ float g_pred[NN];

// ---------------- helpers ---------------------------------------------------
__device__ __forceinline__ int fkey(float f) {
    unsigned u = __float_as_uint(f);
    unsigned U = (u & 0x80000000u) ? ~u : (u | 0x80000000u);
    return (int)(U ^ 0x80000000u);
}
__device__ __forceinline__ float fdecode(int k) {
    unsigned u = (k >= 0) ? (unsigned)k : ~((unsigned)k ^ 0x80000000u);
    return __uint_as_float(u);
}
__device__ __forceinline__ unsigned f2tf32(float x) {
    unsigned r;
    asm("cvt.rna.tf32.f32 %0, %1;" : "=r"(r) : "f"(x));
    return r;
}

__global__ void k_zero_f(float* p, size_t n) {
    for (size_t i = (size_t)blockIdx.x * blockDim.x + threadIdx.x; i < n;
         i += (size_t)gridDim.x * blockDim.x)
        p[i] = 0.f;
}
__global__ void k_fill_i(int* p, int v, size_t n) {
    for (size_t i = (size_t)blockIdx.x * blockDim.x + threadIdx.x; i < n;
         i += (size_t)gridDim.x * blockDim.x)
        p[i] = v;
}

// build edge list with self loops; zero deg
__global__ void k_build_edges(const int* __restrict__ ei, int* src, int* dst, float* deg) {
    int i = blockIdx.x * blockDim.x + threadIdx.x;
    if (i < EE) { src[i] = ei[i]; dst[i] = ei[EE + i]; }
    if (i < NN) { src[EE + i] = i; dst[EE + i] = i; deg[i] = 0.f; }
}
__global__ void k_deg(const int* __restrict__ dst, float* deg) {
    int i = blockIdx.x * blockDim.x + threadIdx.x;
    if (i < ET) atomicAdd(&deg[dst[i]], 1.f);
}

// ---------------- batchnorm ------------------------------------------------
__global__ void k_col_stats(const float* __restrict__ X, float* sum, float* sq,
                            int M, int F) {
    int col = blockIdx.x * blockDim.x + threadIdx.x;
    if (col >= F) return;
    int chunks = gridDim.y;
    int per = (M + chunks - 1) / chunks;
    int r0 = blockIdx.y * per;
    int r1 = min(M, r0 + per);
    float s = 0.f, q = 0.f;
    for (int r = r0; r < r1; r++) {
        float v = X[(size_t)r * F + col];
        s += v; q += v * v;
    }
    atomicAdd(&sum[col], s);
    atomicAdd(&sq[col], q);
}
__global__ void k_bn_coeffs(const float* __restrict__ g, const float* __restrict__ b,
                            const float* __restrict__ sum, const float* __restrict__ sq,
                            float* scale, float* shift, float invM, int F) {
    int c = blockIdx.x * blockDim.x + threadIdx.x;
    if (c >= F) return;
    float m = sum[c] * invM;
    float v = sq[c] * invM - m * m;
    float r = rsqrtf(v + 1e-5f);
    float sc = g[c] * r;
    scale[c] = sc;
    shift[c] = b[c] - m * sc;
}
__global__ void k_bn_apply(const float* __restrict__ in, float* __restrict__ out,
                           const float* __restrict__ scale, const float* __restrict__ shift,
                           size_t total, int F, int relu) {
    for (size_t i = (size_t)blockIdx.x * blockDim.x + threadIdx.x; i < total;
         i += (size_t)gridDim.x * blockDim.x) {
        int c = (int)(i % (size_t)F);
        float v = in[i] * scale[c] + shift[c];
        if (relu) v = fmaxf(v, 0.f);
        out[i] = v;
    }
}

// ---------------- 3xTF32 tensor-core GEMM ----------------------------------
// C[M,N] = A[M,K] @ B[K,N], row-major fp32, fp32 accuracy via hi/lo tf32 split.
// Block tile 128x128xK16, 8 warps (2x4), warp tile 64x32 = 4x4 m16n8 frags.
#define BM 128
#define BN 128
#define BK 16
#define APAD 8
#define BPAD 8

__device__ __forceinline__ void mma_tf32(float* c, const unsigned* a, const unsigned* b) {
    asm volatile(
        "mma.sync.aligned.m16n8k8.row.col.f32.tf32.tf32.f32 "
        "{%0,%1,%2,%3}, {%4,%5,%6,%7}, {%8,%9}, {%0,%1,%2,%3};\n"
        : "+f"(c[0]), "+f"(c[1]), "+f"(c[2]), "+f"(c[3])
        : "r"(a[0]), "r"(a[1]), "r"(a[2]), "r"(a[3]), "r"(b[0]), "r"(b[1]));
}

__global__ __launch_bounds__(256, 1) void k_gemm_tf32(
    const float* __restrict__ A, const float* __restrict__ B,
    float* __restrict__ C, int M, int N, int K) {
    __shared__ unsigned As[2][BK][BM + APAD];  // [hi/lo][k][m]
    __shared__ unsigned Bs[2][BK][BN + BPAD];  // [hi/lo][k][n]

    int tid = threadIdx.x;
    int lane = tid & 31;
    int warp = tid >> 5;
    int wm = warp >> 2;        // 0..1
    int wn = warp & 3;         // 0..3
    int gid = lane >> 2;       // 0..7
    int tig = lane & 3;        // 0..3

    int row0 = blockIdx.y * BM;
    int col0 = blockIdx.x * BN;

    float acc[4][4][4];
#pragma unroll
    for (int i = 0; i < 4; i++)
#pragma unroll
        for (int j = 0; j < 4; j++)
#pragma unroll
            for (int q = 0; q < 4; q++) acc[i][j][q] = 0.f;

    for (int k0 = 0; k0 < K; k0 += BK) {
        // load + convert A tile (BM x BK) and B tile (BK x BN)
#pragma unroll
        for (int i = 0; i < 8; i++) {
            int idx = tid + i * 256;
            int r = idx >> 4, c = idx & 15;
            int gr = row0 + r, gk = k0 + c;
            float v = (gr < M && gk < K) ? __ldg(&A[(size_t)gr * K + gk]) : 0.f;
            unsigned hi = f2tf32(v);
            float lo = v - __uint_as_float(hi);
            As[0][c][r] = hi;
            As[1][c][r] = f2tf32(lo);
        }
#pragma unroll
        for (int i = 0; i < 8; i++) {
            int idx = tid + i * 256;
            int r = idx >> 7, c = idx & 127;
            int gk = k0 + r, gc = col0 + c;
            float v = (gk < K && gc < N) ? __ldg(&B[(size_t)gk * N + gc]) : 0.f;
            unsigned hi = f2tf32(v);
            float lo = v - __uint_as_float(hi);
            Bs[0][r][c] = hi;
            Bs[1][r][c] = f2tf32(lo);
        }
        __syncthreads();

#pragma unroll
        for (int kk = 0; kk < BK; kk += 8) {
            unsigned ah[4][4], al[4][4], bh[4][2], bl[4][2];
#pragma unroll
            for (int mt = 0; mt < 4; mt++) {
                int r = wm * 64 + mt * 16 + gid;
                ah[mt][0] = As[0][kk + tig][r];
                ah[mt][1] = As[0][kk + tig][r + 8];
                ah[mt][2] = As[0][kk + tig + 4][r];
                ah[mt][3] = As[0][kk + tig + 4][r + 8];
                al[mt][0] = As[1][kk + tig][r];
                al[mt][1] = As[1][kk + tig][r + 8];
                al[mt][2] = As[1][kk + tig + 4][r];
                al[mt][3] = As[1][kk + tig + 4][r + 8];
            }
#pragma unroll
            for (int nt = 0; nt < 4; nt++) {
                int c = wn * 32 + nt * 8 + gid;
                bh[nt][0] = Bs[0][kk + tig][c];
                bh[nt][1] = Bs[0][kk + tig + 4][c];
                bl[nt][0] = Bs[1][kk + tig][c];
                bl[nt][1] = Bs[1][kk + tig + 4][c];
            }
#pragma unroll
            for (int mt = 0; mt < 4; mt++)
#pragma unroll
                for (int nt = 0; nt < 4; nt++) {
                    mma_tf32(acc[mt][nt], al[mt], bh[nt]);  // lo*hi
                    mma_tf32(acc[mt][nt], ah[mt], bl[nt]);  // hi*lo
                    mma_tf32(acc[mt][nt], ah[mt], bh[nt]);  // hi*hi
                }
        }
        __syncthreads();
    }

    // epilogue
#pragma unroll
    for (int mt = 0; mt < 4; mt++) {
        int gr0 = row0 + wm * 64 + mt * 16 + gid;
#pragma unroll
        for (int nt = 0; nt < 4; nt++) {
            int gc = col0 + wn * 32 + nt * 8 + tig * 2;
            if (gr0 < M) {
                C[(size_t)gr0 * N + gc]     = acc[mt][nt][0];
                C[(size_t)gr0 * N + gc + 1] = acc[mt][nt][1];
            }
            if (gr0 + 8 < M) {
                C[(size_t)(gr0 + 8) * N + gc]     = acc[mt][nt][2];
                C[(size_t)(gr0 + 8) * N + gc + 1] = acc[mt][nt][3];
            }
        }
    }
}

// ---------------- GATv2 edge kernels ---------------------------------------
template <int H>
__global__ void k_edge_scores(const float* __restrict__ xl, const float* __restrict__ xr,
                              const float* __restrict__ att,
                              const int* __restrict__ src, const int* __restrict__ dst,
                              float* __restrict__ e, int* __restrict__ emax) {
    int gw = (blockIdx.x * blockDim.x + threadIdx.x) >> 5;
    int lane = threadIdx.x & 31;
    if (gw >= ET * H) return;
    int edge = gw / H, h = gw % H;
    int s = src[edge], d = dst[edge];
    const float* pl = xl + (size_t)s * (H * CH) + h * CH;
    const float* pr = xr + (size_t)d * (H * CH) + h * CH;
    const float* pa = att + h * CH;
    float acc = 0.f;
#pragma unroll
    for (int c = lane; c < CH; c += 32) {
        float z = pl[c] + pr[c];
        z = z > 0.f ? z : 0.2f * z;
        acc += z * pa[c];
    }
#pragma unroll
    for (int o = 16; o; o >>= 1) acc += __shfl_xor_sync(0xFFFFFFFFu, acc, o);
    if (lane == 0) {
        e[(size_t)edge * H + h] = acc;
        atomicMax(&emax[d * H + h], fkey(acc));
    }
}

template <int H>
__global__ void k_edge_exp(const int* __restrict__ dst, const int* __restrict__ emax,
                           float* __restrict__ e, float* __restrict__ denom) {
    int i = blockIdx.x * blockDim.x + threadIdx.x;
    if (i >= ET * H) return;
    int edge = i / H, h = i % H;
    int d = dst[edge];
    float mx = fdecode(emax[d * H + h]);
    float ex = expf(e[i] - mx);
    e[i] = ex;
    atomicAdd(&denom[d * H + h], ex);
}

template <int H>
__global__ void k_edge_agg(const float* __restrict__ xl, const float* __restrict__ e,
                           const float* __restrict__ denom,
                           const int* __restrict__ src, const int* __restrict__ dst,
                           float* __restrict__ agg) {
    int gw = (blockIdx.x * blockDim.x + threadIdx.x) >> 5;
    int lane = threadIdx.x & 31;
    if (gw >= ET * H) return;
    int edge = gw / H, h = gw % H;
    int s = src[edge], d = dst[edge];
    float alpha = e[(size_t)edge * H + h] / denom[d * H + h];
    const float* pl = xl + (size_t)s * (H * CH) + h * CH;
    float* pa = agg + (size_t)d * (H * CH) + h * CH;
#pragma unroll
    for (int c = lane; c < CH; c += 32)
        atomicAdd(&pa[c], alpha * pl[c]);
}

__global__ void k_gat_out(const float* __restrict__ agg, const float* __restrict__ deg,
                          const float* __restrict__ bias, float* __restrict__ hout,
                          size_t total, int HC, int relu) {
    for (size_t i = (size_t)blockIdx.x * blockDim.x + threadIdx.x; i < total;
         i += (size_t)gridDim.x * blockDim.x) {
        int n = (int)(i / (size_t)HC);
        int f = (int)(i % (size_t)HC);
        float v = agg[i] / deg[n] + bias[f];
        if (relu) v = fmaxf(v, 0.f);
        hout[i] = v;
    }
}

// ---------------- head + gather --------------------------------------------
__global__ void k_head(const float* __restrict__ h, const float* __restrict__ Wh,
                       const float* __restrict__ bh, float* __restrict__ pred) {
    int gw = (blockIdx.x * blockDim.x + threadIdx.x) >> 5;
    int lane = threadIdx.x & 31;
    if (gw >= NN) return;
    const float* ph = h + (size_t)gw * CH;
    float acc = 0.f;
#pragma unroll
    for (int c = lane; c < CH; c += 32) acc += ph[c] * Wh[c];
#pragma unroll
    for (int o = 16; o; o >>= 1) acc += __shfl_xor_sync(0xFFFFFFFFu, acc, o);
    if (lane == 0) {
        float t = acc + bh[0];
        pred[gw] = 1.f / (1.f + expf(-t));
    }
}
__global__ void k_gather(const float* __restrict__ pred, const float* __restrict__ y,
                         const int* __restrict__ tidx, float* __restrict__ out, int ntr) {
    int i = blockIdx.x * blockDim.x + threadIdx.x;
    if (i >= ntr) return;
    int j = tidx[i];
    out[i] = pred[j];
    out[ntr + i] = y[j];
}

// ---------------- host-side orchestration ----------------------------------
static inline int gblocks(size_t n, int tpb) {
    size_t b = (n + tpb - 1) / tpb;
    if (b > 65535u * 4u) b = 65535u * 4u;
    return (int)b;
}

struct Ptrs {
    float *hbn, *xl, *xr, *h, *agg, *sum, *sq, *scale, *shift, *deg, *e, *denom, *pred;
    int *src, *dst, *emax;
};

static void bn_stats_apply(const float* in, float* out, const float* g, const float* b,
                           int F, bool relu, Ptrs& P) {
    k_zero_f<<<gblocks(F, 256), 256>>>(P.sum, (size_t)F);
    k_zero_f<<<gblocks(F, 256), 256>>>(P.sq, (size_t)F);
    dim3 sg((F + 255) / 256, 32);
    k_col_stats<<<sg, 256>>>(in, P.sum, P.sq, NN, F);
    k_bn_coeffs<<<(F + 255) / 256, 256>>>(g, b, P.sum, P.sq, P.scale, P.shift,
                                          1.f / (float)NN, F);
    size_t total = (size_t)NN * F;
    k_bn_apply<<<gblocks(total, 256), 256>>>(in, out, P.scale, P.shift, total, F,
                                             relu ? 1 : 0);
}

static void gat_layer(const float* hin, int Fin, const float* Wl, const float* Wr,
                      const float* att, const float* bias, int H, float* hout,
                      bool relu_out, Ptrs& P) {
    int HC = H * CH;
    dim3 gg(HC / BN, (NN + BM - 1) / BM);
    k_gemm_tf32<<<gg, 256>>>(hin, Wl, P.xl, NN, HC, Fin);
    k_gemm_tf32<<<gg, 256>>>(hin, Wr, P.xr, NN, HC, Fin);
    k_fill_i<<<gblocks((size_t)NN * H, 256), 256>>>(P.emax, (int)0x80000000, (size_t)NN * H);
    k_zero_f<<<gblocks((size_t)NN * H, 256), 256>>>(P.denom, (size_t)NN * H);
    k_zero_f<<<gblocks((size_t)NN * HC, 256), 256>>>(P.agg, (size_t)NN * HC);

    int nwork = ET * H;
    int thr = nwork * 32;
    int bl = (thr + 255) / 256;
    if (H == 2) {
        k_edge_scores<2><<<bl, 256>>>(P.xl, P.xr, att, P.src, P.dst, P.e, P.emax);
        k_edge_exp<2><<<(nwork + 255) / 256, 256>>>(P.dst, P.emax, P.e, P.denom);
        k_edge_agg<2><<<bl, 256>>>(P.xl, P.e, P.denom, P.src, P.dst, P.agg);
    } else {
        k_edge_scores<1><<<bl, 256>>>(P.xl, P.xr, att, P.src, P.dst, P.e, P.emax);
        k_edge_exp<1><<<(nwork + 255) / 256, 256>>>(P.dst, P.emax, P.e, P.denom);
        k_edge_agg<1><<<bl, 256>>>(P.xl, P.e, P.denom, P.src, P.dst, P.agg);
    }
    size_t total = (size_t)NN * HC;
    k_gat_out<<<gblocks(total, 256), 256>>>(P.agg, P.deg, bias, hout, total, HC,
                                            relu_out ? 1 : 0);
}

extern "C" void kernel_launch(void* const* d_in, const int* in_sizes, int n_in,
                              void* d_out, int out_size) {
    // inputs in metadata order
    const float* x     = (const float*)d_in[0];
    const int*   ei    = (const int*)d_in[1];
    const float* y     = (const float*)d_in[2];
    const int*   tidx  = (const int*)d_in[3];
    const float* bn0_g = (const float*)d_in[4];
    const float* bn0_b = (const float*)d_in[5];
    const float* W1l   = (const float*)d_in[6];
    const float* W1r   = (const float*)d_in[7];
    const float* a1    = (const float*)d_in[8];
    const float* b1    = (const float*)d_in[9];
    const float* bn1_g = (const float*)d_in[10];
    const float* bn1_b = (const float*)d_in[11];
    const float* W2l   = (const float*)d_in[12];
    const float* W2r   = (const float*)d_in[13];
    const float* a2    = (const float*)d_in[14];
    const float* b2    = (const float*)d_in[15];
    const float* bn2_g = (const float*)d_in[16];
    const float* bn2_b = (const float*)d_in[17];
    const float* W3l   = (const float*)d_in[18];
    const float* W3r   = (const float*)d_in[19];
    const float* a3    = (const float*)d_in[20];
    const float* b3    = (const float*)d_in[21];
    const float* bn3_g = (const float*)d_in[22];
    const float* bn3_b = (const float*)d_in[23];
    const float* W4l   = (const float*)d_in[24];
    const float* W4r   = (const float*)d_in[25];
    const float* a4    = (const float*)d_in[26];
    const float* b4    = (const float*)d_in[27];
    const float* Wh    = (const float*)d_in[28];
    const float* bh    = (const float*)d_in[29];
    float* out = (float*)d_out;
    int ntr = in_sizes[3];

    Ptrs P;
    cudaGetSymbolAddress((void**)&P.hbn, g_hbn);
    cudaGetSymbolAddress((void**)&P.xl, g_xl);
    cudaGetSymbolAddress((void**)&P.xr, g_xr);
    cudaGetSymbolAddress((void**)&P.h, g_h);
    cudaGetSymbolAddress((void**)&P.agg, g_agg);
    cudaGetSymbolAddress((void**)&P.sum, g_sum);
    cudaGetSymbolAddress((void**)&P.sq, g_sq);
    cudaGetSymbolAddress((void**)&P.scale, g_scale);
    cudaGetSymbolAddress((void**)&P.shift, g_shift);
    cudaGetSymbolAddress((void**)&P.deg, g_deg);
    cudaGetSymbolAddress((void**)&P.e, g_e);
    cudaGetSymbolAddress((void**)&P.denom, g_denom);
    cudaGetSymbolAddress((void**)&P.pred, g_pred);
    cudaGetSymbolAddress((void**)&P.src, g_src);
    cudaGetSymbolAddress((void**)&P.dst, g_dst);
    cudaGetSymbolAddress((void**)&P.emax, g_emax);

    // edges + degree
    int mx = (EE > NN ? EE : NN);
    k_build_edges<<<(mx + 255) / 256, 256>>>(ei, P.src, P.dst, P.deg);
    k_deg<<<(ET + 255) / 256, 256>>>(P.dst, P.deg);

    // BN0 (no relu) -> g_hbn
    bn_stats_apply(x, P.hbn, bn0_g, bn0_b, FIN, false, P);

    // Layer 1: H=2, Fin=3201 -> g_h [N,1024]
    gat_layer(P.hbn, FIN, W1l, W1r, a1, b1, 2, P.h, false, P);
    bn_stats_apply(P.h, P.h, bn1_g, bn1_b, 1024, true, P);

    // Layer 2: H=1, Fin=1024 -> g_h [N,512]
    gat_layer(P.h, 1024, W2l, W2r, a2, b2, 1, P.h, false, P);
    bn_stats_apply(P.h, P.h, bn2_g, bn2_b, 512, true, P);

    // Layer 3
    gat_layer(P.h, 512, W3l, W3r, a3, b3, 1, P.h, false, P);
    bn_stats_apply(P.h, P.h, bn3_g, bn3_b, 512, true, P);

    // Layer 4 (relu on output, no BN)
    gat_layer(P.h, 512, W4l, W4r, a4, b4, 1, P.h, true, P);

    // head + gather
    k_head<<<(NN * 32 + 255) / 256, 256>>>(P.h, Wh, bh, P.pred);
    k_gather<<<(ntr + 255) / 256, 256>>>(P.pred, y, tidx, out, ntr);
}

// round 4
// speedup vs baseline: 1.7978x; 1.3168x over previous
#include <cuda_runtime.h>
#include <cstdint>
#include <cstddef>

// Problem constants (fixed by the dataset)
static constexpr int NN  = 8000;    // nodes
static constexpr int EE  = 64000;   // directed edges (pre self-loop)
static constexpr int ET  = 72000;   // edges + self loops
static constexpr int FIN = 3201;    // input feature dim
static constexpr int FINP = 3216;   // padded to mult of 16
static constexpr int MT  = 8064;    // padded node rows (63*128)
static constexpr int CH  = 512;     // channels per head

// ---------------- scratch (device globals; no allocation allowed) ----------
__device__ unsigned g_Ahi[(size_t)MT * FINP];
__device__ unsigned g_Alo[(size_t)MT * FINP];
__device__ unsigned g_Whi[(size_t)FINP * 1024];
__device__ unsigned g_Wlo[(size_t)FINP * 1024];
__device__ float g_xl  [(size_t)NN * 1024];
__device__ float g_xr  [(size_t)NN * 1024];
__device__ float g_h   [(size_t)NN * 1024];
__device__ float g_agg [(size_t)NN * 1024];
__device__ float g_sum [FIN];
__device__ float g_sq  [FIN];
__device__ float g_scale[FIN];
__device__ float g_shift[FIN];
__device__ int   g_src [ET];
__device__ int   g_dst [ET];
__device__ float g_deg [NN];
__device__ float g_e   [ET * 2];
__device__ int   g_emax[NN * 2];
__device__ float g_denom[NN * 2];
__device__ float g_pred[NN];

// ---------------- helpers ---------------------------------------------------
__device__ __forceinline__ int fkey(float f) {
    unsigned u = __float_as_uint(f);
    unsigned U = (u & 0x80000000u) ? ~u : (u | 0x80000000u);
    return (int)(U ^ 0x80000000u);
}
__device__ __forceinline__ float fdecode(int k) {
    unsigned u = (k >= 0) ? (unsigned)k : ~((unsigned)k ^ 0x80000000u);
    return __uint_as_float(u);
}
__device__ __forceinline__ unsigned f2tf32(float x) {
    unsigned r;
    asm("cvt.rna.tf32.f32 %0, %1;" : "=r"(r) : "f"(x));
    return r;
}
__device__ __forceinline__ void cp_async16(unsigned saddr, const void* gptr) {
    asm volatile("cp.async.cg.shared.global [%0], [%1], 16;\n" ::"r"(saddr), "l"(gptr));
}
__device__ __forceinline__ void cp_commit() {
    asm volatile("cp.async.commit_group;\n");
}
template <int N>
__device__ __forceinline__ void cp_wait() {
    asm volatile("cp.async.wait_group %0;\n" ::"n"(N));
}

__global__ void k_zero_f(float* p, size_t n) {
    for (size_t i = (size_t)blockIdx.x * blockDim.x + threadIdx.x; i < n;
         i += (size_t)gridDim.x * blockDim.x)
        p[i] = 0.f;
}
__global__ void k_fill_i(int* p, int v, size_t n) {
    for (size_t i = (size_t)blockIdx.x * blockDim.x + threadIdx.x; i < n;
         i += (size_t)gridDim.x * blockDim.x)
        p[i] = v;
}

// build edge list with self loops; zero deg + bn-stat accumulators
__global__ void k_build_edges(const int* __restrict__ ei, int* src, int* dst,
                              float* deg, float* sum, float* sq) {
    int i = blockIdx.x * blockDim.x + threadIdx.x;
    if (i < EE) { src[i] = ei[i]; dst[i] = ei[EE + i]; }
    if (i < NN) { src[EE + i] = i; dst[EE + i] = i; deg[i] = 0.f; }
    if (i < FIN) { sum[i] = 0.f; sq[i] = 0.f; }
}
__global__ void k_deg(const int* __restrict__ dst, float* deg) {
    int i = blockIdx.x * blockDim.x + threadIdx.x;
    if (i < ET) atomicAdd(&deg[dst[i]], 1.f);
}

// ---------------- batchnorm ------------------------------------------------
__global__ void k_col_stats(const float* __restrict__ X, float* sum, float* sq,
                            int M, int F) {
    int col = blockIdx.x * blockDim.x + threadIdx.x;
    if (col >= F) return;
    int chunks = gridDim.y;
    int per = (M + chunks - 1) / chunks;
    int r0 = blockIdx.y * per;
    int r1 = min(M, r0 + per);
    float s = 0.f, q = 0.f;
    for (int r = r0; r < r1; r++) {
        float v = X[(size_t)r * F + col];
        s += v; q += v * v;
    }
    atomicAdd(&sum[col], s);
    atomicAdd(&sq[col], q);
}
__global__ void k_bn_coeffs(const float* __restrict__ g, const float* __restrict__ b,
                            const float* __restrict__ sum, const float* __restrict__ sq,
                            float* scale, float* shift, float invM, int F) {
    int c = blockIdx.x * blockDim.x + threadIdx.x;
    if (c >= F) return;
    float m = sum[c] * invM;
    float v = sq[c] * invM - m * m;
    float r = rsqrtf(v + 1e-5f);
    float sc = g[c] * r;
    scale[c] = sc;
    shift[c] = b[c] - m * sc;
}
// BN apply + tf32 hi/lo split into padded plane buffers [Mt, Fp]
__global__ void k_bn_apply_split(const float* __restrict__ in,
                                 const float* __restrict__ scale,
                                 const float* __restrict__ shift,
                                 unsigned* __restrict__ Ahi, unsigned* __restrict__ Alo,
                                 int M, int F, int Fp, int Mt, int relu) {
    size_t total = (size_t)Mt * Fp;
    for (size_t i = (size_t)blockIdx.x * blockDim.x + threadIdx.x; i < total;
         i += (size_t)gridDim.x * blockDim.x) {
        int r = (int)(i / (size_t)Fp);
        int c = (int)(i % (size_t)Fp);
        float v = 0.f;
        if (r < M && c < F) {
            v = in[(size_t)r * F + c] * scale[c] + shift[c];
            if (relu) v = fmaxf(v, 0.f);
        }
        unsigned hi = f2tf32(v);
        Ahi[i] = hi;
        Alo[i] = f2tf32(v - __uint_as_float(hi));
    }
}
// weight split into padded [Kp, N] planes
__global__ void k_split_w(const float* __restrict__ W, unsigned* __restrict__ Whi,
                          unsigned* __restrict__ Wlo, int K, int Kp, int N) {
    size_t total = (size_t)Kp * N;
    for (size_t i = (size_t)blockIdx.x * blockDim.x + threadIdx.x; i < total;
         i += (size_t)gridDim.x * blockDim.x) {
        int k = (int)(i / (size_t)N);
        float v = (k < K) ? W[i] : 0.f;
        unsigned hi = f2tf32(v);
        Whi[i] = hi;
        Wlo[i] = f2tf32(v - __uint_as_float(hi));
    }
}

// ---------------- 3xTF32 tensor-core GEMM (pipelined, pre-split planes) -----
// C[M,N] = A[M,Kp] @ B[Kp,N]; A planes [Mt,Kp] row-major, B planes [Kp,N].
// Block 128x128, BK=16, 8 warps 2x4, warp tile 64x32, cp.async double buffer.
#define BM 128
#define BN 128
#define BK 16
#define ASTR 20            // As row stride (floats): conflict-free
#define BSTR 136           // Bs row stride
#define A_PL (BM * ASTR)   // 2560
#define B_PL (BK * BSTR)   // 2176
#define STAGE_U32 (2 * A_PL + 2 * B_PL)  // 9472

__device__ __forceinline__ void mma_tf32(float* c, const unsigned* a, const unsigned* b) {
    asm volatile(
        "mma.sync.aligned.m16n8k8.row.col.f32.tf32.tf32.f32 "
        "{%0,%1,%2,%3}, {%4,%5,%6,%7}, {%8,%9}, {%0,%1,%2,%3};\n"
        : "+f"(c[0]), "+f"(c[1]), "+f"(c[2]), "+f"(c[3])
        : "r"(a[0]), "r"(a[1]), "r"(a[2]), "r"(a[3]), "r"(b[0]), "r"(b[1]));
}

__global__ __launch_bounds__(256, 1) void k_gemm3(
    const unsigned* __restrict__ Ahi, const unsigned* __restrict__ Alo,
    const unsigned* __restrict__ Bhi, const unsigned* __restrict__ Blo,
    float* __restrict__ C, int M, int N, int Kp) {
    extern __shared__ unsigned sm[];

    int tid = threadIdx.x;
    int lane = tid & 31;
    int warp = tid >> 5;
    int wm = warp >> 2;
    int wn = warp & 3;
    int gid = lane >> 2;
    int tig = lane & 3;

    int row0 = blockIdx.y * BM;
    int col0 = blockIdx.x * BN;

    // precompute this thread's 8 load slots (4 A chunks + 4 B chunks)
    int a_pl[4], a_row[4], a_kc[4];
    int b_pl[4], b_kr[4], b_nc[4];
#pragma unroll
    for (int i = 0; i < 4; i++) {
        int ch = tid + i * 256;
        a_pl[i] = ch >> 9; int rem = ch & 511;
        a_row[i] = rem >> 2; a_kc[i] = rem & 3;
        b_pl[i] = ch >> 9; rem = ch & 511;
        b_kr[i] = rem >> 5; b_nc[i] = rem & 31;
    }

    float acc[4][4][4];
#pragma unroll
    for (int i = 0; i < 4; i++)
#pragma unroll
        for (int j = 0; j < 4; j++)
#pragma unroll
            for (int q = 0; q < 4; q++) acc[i][j][q] = 0.f;

    int niter = Kp / BK;

    auto prefetch = [&](int stage, int k0) {
        unsigned sbase = stage * STAGE_U32;
#pragma unroll
        for (int i = 0; i < 4; i++) {
            const unsigned* Ap = a_pl[i] ? Alo : Ahi;
            const unsigned* gp = Ap + (size_t)(row0 + a_row[i]) * Kp + k0 + a_kc[i] * 4;
            unsigned didx = sbase + a_pl[i] * A_PL + a_row[i] * ASTR + a_kc[i] * 4;
            cp_async16((unsigned)__cvta_generic_to_shared(&sm[didx]), gp);
        }
#pragma unroll
        for (int i = 0; i < 4; i++) {
            const unsigned* Bp = b_pl[i] ? Blo : Bhi;
            const unsigned* gp = Bp + (size_t)(k0 + b_kr[i]) * N + col0 + b_nc[i] * 4;
            unsigned didx = sbase + 2 * A_PL + b_pl[i] * B_PL + b_kr[i] * BSTR + b_nc[i] * 4;
            cp_async16((unsigned)__cvta_generic_to_shared(&sm[didx]), gp);
        }
        cp_commit();
    };

    prefetch(0, 0);

    for (int it = 0; it < niter; it++) {
        if (it + 1 < niter) {
            prefetch((it + 1) & 1, (it + 1) * BK);
            cp_wait<1>();
        } else {
            cp_wait<0>();
        }
        __syncthreads();

        unsigned sbase = (it & 1) * STAGE_U32;
        const unsigned* As0 = sm + sbase;            // hi plane
        const unsigned* As1 = sm + sbase + A_PL;     // lo plane
        const unsigned* Bs0 = sm + sbase + 2 * A_PL;
        const unsigned* Bs1 = sm + sbase + 2 * A_PL + B_PL;

#pragma unroll
        for (int kk = 0; kk < BK; kk += 8) {
            unsigned ah[4][4], al[4][4], bh[4][2], bl[4][2];
#pragma unroll
            for (int mt = 0; mt < 4; mt++) {
                int r = wm * 64 + mt * 16 + gid;
                int k1 = kk + tig, k2 = kk + tig + 4;
                ah[mt][0] = As0[r * ASTR + k1];
                ah[mt][1] = As0[(r + 8) * ASTR + k1];
                ah[mt][2] = As0[r * ASTR + k2];
                ah[mt][3] = As0[(r + 8) * ASTR + k2];
                al[mt][0] = As1[r * ASTR + k1];
                al[mt][1] = As1[(r + 8) * ASTR + k1];
                al[mt][2] = As1[r * ASTR + k2];
                al[mt][3] = As1[(r + 8) * ASTR + k2];
            }
#pragma unroll
            for (int nt = 0; nt < 4; nt++) {
                int c = wn * 32 + nt * 8 + gid;
                int k1 = kk + tig, k2 = kk + tig + 4;
                bh[nt][0] = Bs0[k1 * BSTR + c];
                bh[nt][1] = Bs0[k2 * BSTR + c];
                bl[nt][0] = Bs1[k1 * BSTR + c];
                bl[nt][1] = Bs1[k2 * BSTR + c];
            }
#pragma unroll
            for (int mt = 0; mt < 4; mt++)
#pragma unroll
                for (int nt = 0; nt < 4; nt++) {
                    mma_tf32(acc[mt][nt], al[mt], bh[nt]);
                    mma_tf32(acc[mt][nt], ah[mt], bl[nt]);
                    mma_tf32(acc[mt][nt], ah[mt], bh[nt]);
                }
        }
        __syncthreads();
    }

#pragma unroll
    for (int mt = 0; mt < 4; mt++) {
        int gr0 = row0 + wm * 64 + mt * 16 + gid;
#pragma unroll
        for (int nt = 0; nt < 4; nt++) {
            int gc = col0 + wn * 32 + nt * 8 + tig * 2;
            if (gr0 < M) {
                C[(size_t)gr0 * N + gc]     = acc[mt][nt][0];
                C[(size_t)gr0 * N + gc + 1] = acc[mt][nt][1];
            }
            if (gr0 + 8 < M) {
                C[(size_t)(gr0 + 8) * N + gc]     = acc[mt][nt][2];
                C[(size_t)(gr0 + 8) * N + gc + 1] = acc[mt][nt][3];
            }
        }
    }
}

// ---------------- GATv2 edge kernels ---------------------------------------
template <int H>
__global__ void k_edge_scores(const float* __restrict__ xl, const float* __restrict__ xr,
                              const float* __restrict__ att,
                              const int* __restrict__ src, const int* __restrict__ dst,
                              float* __restrict__ e, int* __restrict__ emax) {
    int gw = (blockIdx.x * blockDim.x + threadIdx.x) >> 5;
    int lane = threadIdx.x & 31;
    if (gw >= ET * H) return;
    int edge = gw / H, h = gw % H;
    int s = src[edge], d = dst[edge];
    const float* pl = xl + (size_t)s * (H * CH) + h * CH;
    const float* pr = xr + (size_t)d * (H * CH) + h * CH;
    const float* pa = att + h * CH;
    float acc = 0.f;
#pragma unroll
    for (int c = lane; c < CH; c += 32) {
        float z = pl[c] + pr[c];
        z = z > 0.f ? z : 0.2f * z;
        acc += z * pa[c];
    }
#pragma unroll
    for (int o = 16; o; o >>= 1) acc += __shfl_xor_sync(0xFFFFFFFFu, acc, o);
    if (lane == 0) {
        e[(size_t)edge * H + h] = acc;
        atomicMax(&emax[d * H + h], fkey(acc));
    }
}

template <int H>
__global__ void k_edge_exp(const int* __restrict__ dst, const int* __restrict__ emax,
                           float* __restrict__ e, float* __restrict__ denom) {
    int i = blockIdx.x * blockDim.x + threadIdx.x;
    if (i >= ET * H) return;
    int edge = i / H, h = i % H;
    int d = dst[edge];
    float mx = fdecode(emax[d * H + h]);
    float ex = expf(e[i] - mx);
    e[i] = ex;
    atomicAdd(&denom[d * H + h], ex);
}

template <int H>
__global__ void k_edge_agg(const float* __restrict__ xl, const float* __restrict__ e,
                           const float* __restrict__ denom,
                           const int* __restrict__ src, const int* __restrict__ dst,
                           float* __restrict__ agg) {
    int gw = (blockIdx.x * blockDim.x + threadIdx.x) >> 5;
    int lane = threadIdx.x & 31;
    if (gw >= ET * H) return;
    int edge = gw / H, h = gw % H;
    int s = src[edge], d = dst[edge];
    float alpha = e[(size_t)edge * H + h] / denom[d * H + h];
    const float* pl = xl + (size_t)s * (H * CH) + h * CH;
    float* pa = agg + (size_t)d * (H * CH) + h * CH;
#pragma unroll
    for (int c = lane; c < CH; c += 32)
        atomicAdd(&pa[c], alpha * pl[c]);
}

// gat output + zero bn accumulators for the NEXT layer
__global__ void k_gat_out(const float* __restrict__ agg, const float* __restrict__ deg,
                          const float* __restrict__ bias, float* __restrict__ hout,
                          float* __restrict__ sum, float* __restrict__ sq,
                          size_t total, int HC, int relu) {
    size_t i0 = (size_t)blockIdx.x * blockDim.x + threadIdx.x;
    if (i0 < (size_t)FIN) { sum[i0] = 0.f; sq[i0] = 0.f; }
    for (size_t i = i0; i < total; i += (size_t)gridDim.x * blockDim.x) {
        int n = (int)(i / (size_t)HC);
        int f = (int)(i % (size_t)HC);
        float v = agg[i] / deg[n] + bias[f];
        if (relu) v = fmaxf(v, 0.f);
        hout[i] = v;
    }
}

// ---------------- head + gather --------------------------------------------
__global__ void k_head(const float* __restrict__ h, const float* __restrict__ Wh,
                       const float* __restrict__ bh, float* __restrict__ pred) {
    int gw = (blockIdx.x * blockDim.x + threadIdx.x) >> 5;
    int lane = threadIdx.x & 31;
    if (gw >= NN) return;
    const float* ph = h + (size_t)gw * CH;
    float acc = 0.f;
#pragma unroll
    for (int c = lane; c < CH; c += 32) acc += ph[c] * Wh[c];
#pragma unroll
    for (int o = 16; o; o >>= 1) acc += __shfl_xor_sync(0xFFFFFFFFu, acc, o);
    if (lane == 0) {
        float t = acc + bh[0];
        pred[gw] = 1.f / (1.f + expf(-t));
    }
}
__global__ void k_gather(const float* __restrict__ pred, const float* __restrict__ y,
                         const int* __restrict__ tidx, float* __restrict__ out, int ntr) {
    int i = blockIdx.x * blockDim.x + threadIdx.x;
    if (i >= ntr) return;
    int j = tidx[i];
    out[i] = pred[j];
    out[ntr + i] = y[j];
}

// ---------------- host-side orchestration ----------------------------------
static inline int gblocks(size_t n, int tpb) {
    size_t b = (n + tpb - 1) / tpb;
    if (b > 65535u * 4u) b = 65535u * 4u;
    return (int)b;
}

struct Ptrs {
    unsigned *Ahi, *Alo, *Whi, *Wlo;
    float *xl, *xr, *h, *agg, *sum, *sq, *scale, *shift, *deg, *e, *denom, *pred;
    int *src, *dst, *emax;
};

static void gemm3(const Ptrs& P, float* C, int N, int Kp) {
    dim3 gg(N / BN, MT / BM);
    size_t smem = STAGE_U32 * 2 * sizeof(unsigned);
    k_gemm3<<<gg, 256, smem>>>(P.Ahi, P.Alo, P.Whi, P.Wlo, C, NN, N, Kp);
}

static void edge_phase(const float* att, const float* bias, int H, float* hout,
                       bool relu_out, Ptrs& P) {
    int HC = H * CH;
    k_fill_i<<<gblocks((size_t)NN * H, 256), 256>>>(P.emax, (int)0x80000000, (size_t)NN * H);
    k_zero_f<<<gblocks((size_t)NN * H, 256), 256>>>(P.denom, (size_t)NN * H);
    k_zero_f<<<gblocks((size_t)NN * HC, 256), 256>>>(P.agg, (size_t)NN * HC);
    int nwork = ET * H;
    int bl = (nwork * 32 + 255) / 256;
    if (H == 2) {
        k_edge_scores<2><<<bl, 256>>>(P.xl, P.xr, att, P.src, P.dst, P.e, P.emax);
        k_edge_exp<2><<<(nwork + 255) / 256, 256>>>(P.dst, P.emax, P.e, P.denom);
        k_edge_agg<2><<<bl, 256>>>(P.xl, P.e, P.denom, P.src, P.dst, P.agg);
    } else {
        k_edge_scores<1><<<bl, 256>>>(P.xl, P.xr, att, P.src, P.dst, P.e, P.emax);
        k_edge_exp<1><<<(nwork + 255) / 256, 256>>>(P.dst, P.emax, P.e, P.denom);
        k_edge_agg<1><<<bl, 256>>>(P.xl, P.e, P.denom, P.src, P.dst, P.agg);
    }
    size_t total = (size_t)NN * HC;
    k_gat_out<<<gblocks(total, 256), 256>>>(P.agg, P.deg, bias, hout, P.sum, P.sq,
                                            total, HC, relu_out ? 1 : 0);
}

static void bn_split(const float* in, const float* g, const float* b, int F, int Fp,
                     bool relu, Ptrs& P) {
    dim3 sg((F + 255) / 256, 32);
    k_col_stats<<<sg, 256>>>(in, P.sum, P.sq, NN, F);
    k_bn_coeffs<<<(F + 255) / 256, 256>>>(g, b, P.sum, P.sq, P.scale, P.shift,
                                          1.f / (float)NN, F);
    size_t total = (size_t)MT * Fp;
    k_bn_apply_split<<<gblocks(total, 256), 256>>>(in, P.scale, P.shift, P.Ahi, P.Alo,
                                                   NN, F, Fp, MT, relu ? 1 : 0);
}

static void split_w(const float* W, int K, int Kp, int N, Ptrs& P) {
    size_t total = (size_t)Kp * N;
    k_split_w<<<gblocks(total, 256), 256>>>(W, P.Whi, P.Wlo, K, Kp, N);
}

extern "C" void kernel_launch(void* const* d_in, const int* in_sizes, int n_in,
                              void* d_out, int out_size) {
    const float* x     = (const float*)d_in[0];
    const int*   ei    = (const int*)d_in[1];
    const float* y     = (const float*)d_in[2];
    const int*   tidx  = (const int*)d_in[3];
    const float* bn0_g = (const float*)d_in[4];
    const float* bn0_b = (const float*)d_in[5];
    const float* W1l   = (const float*)d_in[6];
    const float* W1r   = (const float*)d_in[7];
    const float* a1    = (const float*)d_in[8];
    const float* b1    = (const float*)d_in[9];
    const float* bn1_g = (const float*)d_in[10];
    const float* bn1_b = (const float*)d_in[11];
    const float* W2l   = (const float*)d_in[12];
    const float* W2r   = (const float*)d_in[13];
    const float* a2    = (const float*)d_in[14];
    const float* b2    = (const float*)d_in[15];
    const float* bn2_g = (const float*)d_in[16];
    const float* bn2_b = (const float*)d_in[17];
    const float* W3l   = (const float*)d_in[18];
    const float* W3r   = (const float*)d_in[19];
    const float* a3    = (const float*)d_in[20];
    const float* b3    = (const float*)d_in[21];
    const float* bn3_g = (const float*)d_in[22];
    const float* bn3_b = (const float*)d_in[23];
    const float* W4l   = (const float*)d_in[24];
    const float* W4r   = (const float*)d_in[25];
    const float* a4    = (const float*)d_in[26];
    const float* b4    = (const float*)d_in[27];
    const float* Wh    = (const float*)d_in[28];
    const float* bh    = (const float*)d_in[29];
    float* out = (float*)d_out;
    int ntr = in_sizes[3];

    static bool attr_done = false;
    (void)attr_done;
    cudaFuncSetAttribute(k_gemm3, cudaFuncAttributeMaxDynamicSharedMemorySize,
                         (int)(STAGE_U32 * 2 * sizeof(unsigned)));

    Ptrs P;
    cudaGetSymbolAddress((void**)&P.Ahi, g_Ahi);
    cudaGetSymbolAddress((void**)&P.Alo, g_Alo);
    cudaGetSymbolAddress((void**)&P.Whi, g_Whi);
    cudaGetSymbolAddress((void**)&P.Wlo, g_Wlo);
    cudaGetSymbolAddress((void**)&P.xl, g_xl);
    cudaGetSymbolAddress((void**)&P.xr, g_xr);
    cudaGetSymbolAddress((void**)&P.h, g_h);
    cudaGetSymbolAddress((void**)&P.agg, g_agg);
    cudaGetSymbolAddress((void**)&P.sum, g_sum);
    cudaGetSymbolAddress((void**)&P.sq, g_sq);
    cudaGetSymbolAddress((void**)&P.scale, g_scale);
    cudaGetSymbolAddress((void**)&P.shift, g_shift);
    cudaGetSymbolAddress((void**)&P.deg, g_deg);
    cudaGetSymbolAddress((void**)&P.e, g_e);
    cudaGetSymbolAddress((void**)&P.denom, g_denom);
    cudaGetSymbolAddress((void**)&P.pred, g_pred);
    cudaGetSymbolAddress((void**)&P.src, g_src);
    cudaGetSymbolAddress((void**)&P.dst, g_dst);
    cudaGetSymbolAddress((void**)&P.emax, g_emax);

    // launch 0: edges + zero deg/sum/sq
    k_build_edges<<<(EE + 255) / 256, 256>>>(ei, P.src, P.dst, P.deg, P.sum, P.sq);

    // launches 1-3: BN0 stats/coeffs/apply+split  (A planes = bn(x), Kp=3216)
    bn_split(x, bn0_g, bn0_b, FIN, FINP, false, P);

    // launch 4: split W1l; launch 5: GEMM (ncu -s 5 captures this)
    split_w(W1l, FIN, FINP, 1024, P);
    gemm3(P, P.xl, 1024, FINP);
    split_w(W1r, FIN, FINP, 1024, P);
    gemm3(P, P.xr, 1024, FINP);
    k_deg<<<(ET + 255) / 256, 256>>>(P.dst, P.deg);
    edge_phase(a1, b1, 2, P.h, false, P);

    // layer 2
    bn_split(P.h, bn1_g, bn1_b, 1024, 1024, true, P);
    split_w(W2l, 1024, 1024, 512, P);
    gemm3(P, P.xl, 512, 1024);
    split_w(W2r, 1024, 1024, 512, P);
    gemm3(P, P.xr, 512, 1024);
    edge_phase(a2, b2, 1, P.h, false, P);

    // layer 3
    bn_split(P.h, bn2_g, bn2_b, 512, 512, true, P);
    split_w(W3l, 512, 512, 512, P);
    gemm3(P, P.xl, 512, 512);
    split_w(W3r, 512, 512, 512, P);
    gemm3(P, P.xr, 512, 512);
    edge_phase(a3, b3, 1, P.h, false, P);

    // layer 4
    bn_split(P.h, bn3_g, bn3_b, 512, 512, true, P);
    split_w(W4l, 512, 512, 512, P);
    gemm3(P, P.xl, 512, 512);
    split_w(W4r, 512, 512, 512, P);
    gemm3(P, P.xr, 512, 512);
    edge_phase(a4, b4, 1, P.h, true, P);

    // head + gather
    k_head<<<(NN * 32 + 255) / 256, 256>>>(P.h, Wh, bh, P.pred);
    k_gather<<<(ntr + 255) / 256, 256>>>(P.pred, y, tidx, out, ntr);
}

// round 5
// speedup vs baseline: 2.1449x; 1.1930x over previous
#include <cuda_runtime.h>
#include <cuda_bf16.h>
#include <cstdint>
#include <cstddef>

// Problem constants (fixed by the dataset)
static constexpr int NN  = 8000;
static constexpr int EE  = 64000;
static constexpr int ET  = 72000;
static constexpr int FIN = 3201;
static constexpr int FINP = 3216;   // padded K, mult of 16
static constexpr int MT  = 8064;    // padded rows (63*128)
static constexpr int CH  = 512;

// ---------------- scratch (device globals) ----------------------------------
__device__ __nv_bfloat16 g_Ahi[(size_t)MT * FINP];
__device__ __nv_bfloat16 g_Alo[(size_t)MT * FINP];
__device__ __nv_bfloat16 g_Whi[(size_t)2048 * FINP];  // transposed [n][k]
__device__ __nv_bfloat16 g_Wlo[(size_t)2048 * FINP];
__device__ float g_xlr [(size_t)NN * 2048];  // xl | xr concatenated
__device__ float g_h   [(size_t)NN * 1024];
__device__ float g_agg [(size_t)NN * 1024];
__device__ float g_sum [FIN];
__device__ float g_sq  [FIN];
__device__ float g_scale[FIN];
__device__ float g_shift[FIN];
__device__ int   g_src [ET];
__device__ int   g_dst [ET];
__device__ float g_deg [NN];
__device__ float g_e   [ET * 2];
__device__ int   g_emax[NN * 2];
__device__ float g_denom[NN * 2];
__device__ float g_pred[NN];

// ---------------- helpers ----------------------------------------------------
__device__ __forceinline__ int fkey(float f) {
    unsigned u = __float_as_uint(f);
    unsigned U = (u & 0x80000000u) ? ~u : (u | 0x80000000u);
    return (int)(U ^ 0x80000000u);
}
__device__ __forceinline__ float fdecode(int k) {
    unsigned u = (k >= 0) ? (unsigned)k : ~((unsigned)k ^ 0x80000000u);
    return __uint_as_float(u);
}
__device__ __forceinline__ void bf16split(float v, __nv_bfloat16& hi, __nv_bfloat16& lo) {
    hi = __float2bfloat16_rn(v);
    lo = __float2bfloat16_rn(v - __bfloat162float(hi));
}
__device__ __forceinline__ void cp_async16(unsigned saddr, const void* gptr) {
    asm volatile("cp.async.cg.shared.global [%0], [%1], 16;\n" ::"r"(saddr), "l"(gptr));
}
__device__ __forceinline__ void cp_commit() { asm volatile("cp.async.commit_group;\n"); }
template <int N>
__device__ __forceinline__ void cp_wait() {
    asm volatile("cp.async.wait_group %0;\n" ::"n"(N));
}

__global__ void k_zero_f(float* p, size_t n) {
    for (size_t i = (size_t)blockIdx.x * blockDim.x + threadIdx.x; i < n;
         i += (size_t)gridDim.x * blockDim.x)
        p[i] = 0.f;
}
__global__ void k_fill_i(int* p, int v, size_t n) {
    for (size_t i = (size_t)blockIdx.x * blockDim.x + threadIdx.x; i < n;
         i += (size_t)gridDim.x * blockDim.x)
        p[i] = v;
}

__global__ void k_build_edges(const int* __restrict__ ei, int* src, int* dst,
                              float* deg, float* sum, float* sq) {
    int i = blockIdx.x * blockDim.x + threadIdx.x;
    if (i < EE) { src[i] = ei[i]; dst[i] = ei[EE + i]; }
    if (i < NN) { src[EE + i] = i; dst[EE + i] = i; deg[i] = 0.f; }
    if (i < FIN) { sum[i] = 0.f; sq[i] = 0.f; }
}
__global__ void k_deg(const int* __restrict__ dst, float* deg) {
    int i = blockIdx.x * blockDim.x + threadIdx.x;
    if (i < ET) atomicAdd(&deg[dst[i]], 1.f);
}

// ---------------- batchnorm --------------------------------------------------
__global__ void k_col_stats(const float* __restrict__ X, float* sum, float* sq,
                            int M, int F) {
    int col = blockIdx.x * blockDim.x + threadIdx.x;
    if (col >= F) return;
    int chunks = gridDim.y;
    int per = (M + chunks - 1) / chunks;
    int r0 = blockIdx.y * per;
    int r1 = min(M, r0 + per);
    float s = 0.f, q = 0.f;
    for (int r = r0; r < r1; r++) {
        float v = X[(size_t)r * F + col];
        s += v; q += v * v;
    }
    atomicAdd(&sum[col], s);
    atomicAdd(&sq[col], q);
}
__global__ void k_bn_coeffs(const float* __restrict__ g, const float* __restrict__ b,
                            const float* __restrict__ sum, const float* __restrict__ sq,
                            float* scale, float* shift, float invM, int F) {
    int c = blockIdx.x * blockDim.x + threadIdx.x;
    if (c >= F) return;
    float m = sum[c] * invM;
    float v = sq[c] * invM - m * m;
    float r = rsqrtf(v + 1e-5f);
    float sc = g[c] * r;
    scale[c] = sc;
    shift[c] = b[c] - m * sc;
}
// BN apply + bf16 hi/lo split into padded planes [MT, Fp]; 2D grid (no div/mod)
__global__ void k_bn_apply_split(const float* __restrict__ in,
                                 const float* __restrict__ scale,
                                 const float* __restrict__ shift,
                                 __nv_bfloat16* __restrict__ Ahi,
                                 __nv_bfloat16* __restrict__ Alo,
                                 int M, int F, int Fp, int relu) {
    int c = blockIdx.x * blockDim.x + threadIdx.x;
    int r = blockIdx.y;
    if (c >= Fp) return;
    float v = 0.f;
    if (r < M && c < F) {
        v = in[(size_t)r * F + c] * scale[c] + shift[c];
        if (relu) v = fmaxf(v, 0.f);
    }
    __nv_bfloat16 hi, lo;
    bf16split(v, hi, lo);
    size_t o = (size_t)r * Fp + c;
    Ahi[o] = hi;
    Alo[o] = lo;
}
// transpose+split BOTH weights into Wt planes [2N][Kp]: rows 0..N-1 = Wl cols,
// N..2N-1 = Wr cols.
__global__ void k_splitw2(const float* __restrict__ Wl, const float* __restrict__ Wr,
                          __nv_bfloat16* __restrict__ Whi, __nv_bfloat16* __restrict__ Wlo,
                          int K, int Kp, int N) {
    __shared__ float tile[32][33];
    int kt = blockIdx.x * 32;
    int nt = blockIdx.y * 32;  // over 2N, blocks never straddle N (N mult of 32)
    const float* W = (nt < N) ? Wl : Wr;
    int ncol0 = (nt < N) ? nt : nt - N;
    int tx = threadIdx.x, ty = threadIdx.y;
    int k_in = kt + ty;
    tile[ty][tx] = (k_in < K) ? W[(size_t)k_in * N + ncol0 + tx] : 0.f;
    __syncthreads();
    int k_out = kt + tx;
    if (k_out < Kp) {
        float v = tile[tx][ty];
        __nv_bfloat16 hi, lo;
        bf16split(v, hi, lo);
        size_t o = (size_t)(nt + ty) * Kp + k_out;
        Whi[o] = hi;
        Wlo[o] = lo;
    }
}

// ---------------- 3xBF16 tensor-core GEMM (3-stage cp.async pipeline) --------
// C[M,Ncols] = A[M,Kp] @ Wt^T ; A planes [MT][Kp] bf16, Wt planes [Ncols][Kp] bf16.
// Block 128x128, BK=16, 8 warps (2x4), warp tile 64x32.
// smem per stage (words): A 2 planes*128 rows*8 + B same = 4096. 3 stages.
#define APL 1024
#define STG 4096

__device__ __forceinline__ void mma_bf16(float* c, const unsigned* a, const unsigned* b) {
    asm volatile(
        "mma.sync.aligned.m16n8k16.row.col.f32.bf16.bf16.f32 "
        "{%0,%1,%2,%3}, {%4,%5,%6,%7}, {%8,%9}, {%0,%1,%2,%3};\n"
        : "+f"(c[0]), "+f"(c[1]), "+f"(c[2]), "+f"(c[3])
        : "r"(a[0]), "r"(a[1]), "r"(a[2]), "r"(a[3]), "r"(b[0]), "r"(b[1]));
}

__global__ __launch_bounds__(256, 1) void k_gemm3bf(
    const __nv_bfloat16* __restrict__ Ahi, const __nv_bfloat16* __restrict__ Alo,
    const __nv_bfloat16* __restrict__ Bhi, const __nv_bfloat16* __restrict__ Blo,
    float* __restrict__ C, int M, int Ncols, int Kp) {
    extern __shared__ unsigned sm[];

    int tid = threadIdx.x;
    int lane = tid & 31;
    int warp = tid >> 5;
    int wm = warp >> 2;
    int wn = warp & 3;
    int gid = lane >> 2;
    int tig = lane & 3;

    int row0 = blockIdx.y * 128;
    int col0 = blockIdx.x * 128;

    // loader mapping: thread t handles plane p=t>>7, row r=t&127, chunks c=0,1
    int lp = tid >> 7;
    int lr = tid & 127;
    int lsw = (lr >> 2) & 1;  // chunk swizzle bit for this row

    const __nv_bfloat16* Asrc = lp ? Alo : Ahi;
    const __nv_bfloat16* Bsrc = lp ? Blo : Bhi;
    const __nv_bfloat16* aRow = Asrc + (size_t)(row0 + lr) * Kp;
    const __nv_bfloat16* bRow = Bsrc + (size_t)(col0 + lr) * Kp;
    // dest word offsets within stage
    int aDst0 = lp * APL + lr * 8 + lsw * 4;
    int aDst1 = lp * APL + lr * 8 + (1 - lsw) * 4;
    int bDst0 = 2048 + aDst0;
    int bDst1 = 2048 + aDst1;

    // fragment LDS offsets (words within stage, hi plane; lo = +APL)
    int aoff0[4], aoff2[4], boff0[4], boff1[4];
#pragma unroll
    for (int mt = 0; mt < 4; mt++) {
        int m = wm * 64 + mt * 16 + gid;
        int p = (m >> 2) & 1;
        aoff0[mt] = m * 8 + tig + 4 * p;        // kw=tig
        aoff2[mt] = m * 8 + tig + 4 * (1 - p);  // kw=tig+4
    }
#pragma unroll
    for (int nt = 0; nt < 4; nt++) {
        int n = wn * 32 + nt * 8 + gid;
        int q = (n >> 2) & 1;
        boff0[nt] = 2048 + n * 8 + tig + 4 * q;
        boff1[nt] = 2048 + n * 8 + tig + 4 * (1 - q);
    }

    float acc[4][4][4];
#pragma unroll
    for (int i = 0; i < 4; i++)
#pragma unroll
        for (int j = 0; j < 4; j++)
#pragma unroll
            for (int q = 0; q < 4; q++) acc[i][j][q] = 0.f;

    int niter = Kp >> 4;

    auto prefetch = [&](int stage, int k0) {
        unsigned sb = stage * STG;
        cp_async16((unsigned)__cvta_generic_to_shared(&sm[sb + aDst0]), aRow + k0);
        cp_async16((unsigned)__cvta_generic_to_shared(&sm[sb + aDst1]), aRow + k0 + 8);
        cp_async16((unsigned)__cvta_generic_to_shared(&sm[sb + bDst0]), bRow + k0);
        cp_async16((unsigned)__cvta_generic_to_shared(&sm[sb + bDst1]), bRow + k0 + 8);
        cp_commit();
    };

    prefetch(0, 0);
    if (niter > 1) prefetch(1, 16);

    for (int it = 0; it < niter; it++) {
        if (it + 2 < niter) {
            prefetch((it + 2) % 3, (it + 2) * 16);
            cp_wait<2>();
        } else if (it + 1 < niter) {
            cp_wait<1>();
        } else {
            cp_wait<0>();
        }
        __syncthreads();

        const unsigned* s0 = sm + (it % 3) * STG;       // hi planes
        const unsigned* s1 = s0 + APL;                  // A lo (B lo = s1 + ...)

        unsigned ah[4][4], al[4][4], bh[4][2], bl[4][2];
#pragma unroll
        for (int mt = 0; mt < 4; mt++) {
            ah[mt][0] = s0[aoff0[mt]];
            ah[mt][1] = s0[aoff0[mt] + 64];
            ah[mt][2] = s0[aoff2[mt]];
            ah[mt][3] = s0[aoff2[mt] + 64];
            al[mt][0] = s1[aoff0[mt]];
            al[mt][1] = s1[aoff0[mt] + 64];
            al[mt][2] = s1[aoff2[mt]];
            al[mt][3] = s1[aoff2[mt] + 64];
        }
#pragma unroll
        for (int nt = 0; nt < 4; nt++) {
            bh[nt][0] = s0[boff0[nt]];
            bh[nt][1] = s0[boff1[nt]];
            bl[nt][0] = s1[boff0[nt]];
            bl[nt][1] = s1[boff1[nt]];
        }
#pragma unroll
        for (int mt = 0; mt < 4; mt++)
#pragma unroll
            for (int nt = 0; nt < 4; nt++) {
                mma_bf16(acc[mt][nt], al[mt], bh[nt]);
                mma_bf16(acc[mt][nt], ah[mt], bl[nt]);
                mma_bf16(acc[mt][nt], ah[mt], bh[nt]);
            }
        __syncthreads();
    }

#pragma unroll
    for (int mt = 0; mt < 4; mt++) {
        int gr0 = row0 + wm * 64 + mt * 16 + gid;
#pragma unroll
        for (int nt = 0; nt < 4; nt++) {
            int gc = col0 + wn * 32 + nt * 8 + tig * 2;
            if (gr0 < M) {
                C[(size_t)gr0 * Ncols + gc]     = acc[mt][nt][0];
                C[(size_t)gr0 * Ncols + gc + 1] = acc[mt][nt][1];
            }
            if (gr0 + 8 < M) {
                C[(size_t)(gr0 + 8) * Ncols + gc]     = acc[mt][nt][2];
                C[(size_t)(gr0 + 8) * Ncols + gc + 1] = acc[mt][nt][3];
            }
        }
    }
}

// ---------------- GATv2 edge kernels -----------------------------------------
// xlr layout: [NN][2*HC]; xl = cols [0,HC), xr = cols [HC,2HC)
template <int H>
__global__ void k_edge_scores(const float* __restrict__ xlr,
                              const float* __restrict__ att,
                              const int* __restrict__ src, const int* __restrict__ dst,
                              float* __restrict__ e, int* __restrict__ emax) {
    int gw = (blockIdx.x * blockDim.x + threadIdx.x) >> 5;
    int lane = threadIdx.x & 31;
    if (gw >= ET * H) return;
    int edge = gw / H, h = gw % H;
    int s = src[edge], d = dst[edge];
    const int stride = 2 * H * CH;
    const float4* pl = (const float4*)(xlr + (size_t)s * stride + h * CH);
    const float4* pr = (const float4*)(xlr + (size_t)d * stride + H * CH + h * CH);
    const float4* pa = (const float4*)(att + h * CH);
    float acc = 0.f;
#pragma unroll
    for (int c = lane; c < CH / 4; c += 32) {
        float4 a = pl[c], b = pr[c], w = pa[c];
        float z0 = a.x + b.x; z0 = z0 > 0.f ? z0 : 0.2f * z0;
        float z1 = a.y + b.y; z1 = z1 > 0.f ? z1 : 0.2f * z1;
        float z2 = a.z + b.z; z2 = z2 > 0.f ? z2 : 0.2f * z2;
        float z3 = a.w + b.w; z3 = z3 > 0.f ? z3 : 0.2f * z3;
        acc += z0 * w.x + z1 * w.y + z2 * w.z + z3 * w.w;
    }
#pragma unroll
    for (int o = 16; o; o >>= 1) acc += __shfl_xor_sync(0xFFFFFFFFu, acc, o);
    if (lane == 0) {
        e[(size_t)edge * H + h] = acc;
        atomicMax(&emax[d * H + h], fkey(acc));
    }
}

template <int H>
__global__ void k_edge_exp(const int* __restrict__ dst, const int* __restrict__ emax,
                           float* __restrict__ e, float* __restrict__ denom) {
    int i = blockIdx.x * blockDim.x + threadIdx.x;
    if (i >= ET * H) return;
    int edge = i / H, h = i % H;
    int d = dst[edge];
    float mx = fdecode(emax[d * H + h]);
    float ex = expf(e[i] - mx);
    e[i] = ex;
    atomicAdd(&denom[d * H + h], ex);
}

template <int H>
__global__ void k_edge_agg(const float* __restrict__ xlr, const float* __restrict__ e,
                           const float* __restrict__ denom,
                           const int* __restrict__ src, const int* __restrict__ dst,
                           float* __restrict__ agg) {
    int gw = (blockIdx.x * blockDim.x + threadIdx.x) >> 5;
    int lane = threadIdx.x & 31;
    if (gw >= ET * H) return;
    int edge = gw / H, h = gw % H;
    int s = src[edge], d = dst[edge];
    float alpha = e[(size_t)edge * H + h] / denom[d * H + h];
    const int stride = 2 * H * CH;
    const float4* pl = (const float4*)(xlr + (size_t)s * stride + h * CH);
    float* pa = agg + (size_t)d * (H * CH) + h * CH;
#pragma unroll
    for (int c = lane; c < CH / 4; c += 32) {
        float4 v = pl[c];
        atomicAdd(&pa[c * 4 + 0], alpha * v.x);
        atomicAdd(&pa[c * 4 + 1], alpha * v.y);
        atomicAdd(&pa[c * 4 + 2], alpha * v.z);
        atomicAdd(&pa[c * 4 + 3], alpha * v.w);
    }
}

__global__ void k_gat_out(const float* __restrict__ agg, const float* __restrict__ deg,
                          const float* __restrict__ bias, float* __restrict__ hout,
                          float* __restrict__ sum, float* __restrict__ sq,
                          size_t total, int HC, int relu) {
    size_t i0 = (size_t)blockIdx.x * blockDim.x + threadIdx.x;
    if (i0 < (size_t)FIN) { sum[i0] = 0.f; sq[i0] = 0.f; }
    for (size_t i = i0; i < total; i += (size_t)gridDim.x * blockDim.x) {
        int n = (int)(i / (size_t)HC);
        int f = (int)(i % (size_t)HC);
        float v = agg[i] / deg[n] + bias[f];
        if (relu) v = fmaxf(v, 0.f);
        hout[i] = v;
    }
}

// ---------------- head + gather ----------------------------------------------
__global__ void k_head(const float* __restrict__ h, const float* __restrict__ Wh,
                       const float* __restrict__ bh, float* __restrict__ pred) {
    int gw = (blockIdx.x * blockDim.x + threadIdx.x) >> 5;
    int lane = threadIdx.x & 31;
    if (gw >= NN) return;
    const float* ph = h + (size_t)gw * CH;
    float acc = 0.f;
#pragma unroll
    for (int c = lane; c < CH; c += 32) acc += ph[c] * Wh[c];
#pragma unroll
    for (int o = 16; o; o >>= 1) acc += __shfl_xor_sync(0xFFFFFFFFu, acc, o);
    if (lane == 0) {
        float t = acc + bh[0];
        pred[gw] = 1.f / (1.f + expf(-t));
    }
}
__global__ void k_gather(const float* __restrict__ pred, const float* __restrict__ y,
                         const int* __restrict__ tidx, float* __restrict__ out, int ntr) {
    int i = blockIdx.x * blockDim.x + threadIdx.x;
    if (i >= ntr) return;
    int j = tidx[i];
    out[i] = pred[j];
    out[ntr + i] = y[j];
}

// ---------------- host-side orchestration ------------------------------------
static inline int gblocks(size_t n, int tpb) {
    size_t b = (n + tpb - 1) / tpb;
    if (b > 65535u * 4u) b = 65535u * 4u;
    return (int)b;
}

struct Ptrs {
    __nv_bfloat16 *Ahi, *Alo, *Whi, *Wlo;
    float *xlr, *h, *agg, *sum, *sq, *scale, *shift, *deg, *e, *denom, *pred;
    int *src, *dst, *emax;
};

static void bn_split(const float* in, const float* g, const float* b, int F, int Fp,
                     bool relu, Ptrs& P) {
    dim3 sg((F + 255) / 256, 32);
    k_col_stats<<<sg, 256>>>(in, P.sum, P.sq, NN, F);
    k_bn_coeffs<<<(F + 255) / 256, 256>>>(g, b, P.sum, P.sq, P.scale, P.shift,
                                          1.f / (float)NN, F);
    dim3 ag((Fp + 255) / 256, MT);
    k_bn_apply_split<<<ag, 256>>>(in, P.scale, P.shift, P.Ahi, P.Alo, NN, F, Fp,
                                  relu ? 1 : 0);
}

static void split_w(const float* Wl, const float* Wr, int K, int Kp, int N, Ptrs& P) {
    dim3 g((Kp + 31) / 32, (2 * N) / 32);
    k_splitw2<<<g, dim3(32, 32)>>>(Wl, Wr, P.Whi, P.Wlo, K, Kp, N);
}

static void gemm(Ptrs& P, int Ncols, int Kp) {
    dim3 gg(Ncols / 128, MT / 128);
    size_t smem = 3 * STG * sizeof(unsigned);
    k_gemm3bf<<<gg, 256, smem>>>(P.Ahi, P.Alo, P.Whi, P.Wlo, P.xlr, NN, Ncols, Kp);
}

static void edge_phase(const float* att, const float* bias, int H, float* hout,
                       bool relu_out, Ptrs& P) {
    int HC = H * CH;
    k_fill_i<<<gblocks((size_t)NN * H, 256), 256>>>(P.emax, (int)0x80000000, (size_t)NN * H);
    k_zero_f<<<gblocks((size_t)NN * H, 256), 256>>>(P.denom, (size_t)NN * H);
    k_zero_f<<<gblocks((size_t)NN * HC, 256), 256>>>(P.agg, (size_t)NN * HC);
    int nwork = ET * H;
    int bl = (nwork * 32 + 255) / 256;
    if (H == 2) {
        k_edge_scores<2><<<bl, 256>>>(P.xlr, att, P.src, P.dst, P.e, P.emax);
        k_edge_exp<2><<<(nwork + 255) / 256, 256>>>(P.dst, P.emax, P.e, P.denom);
        k_edge_agg<2><<<bl, 256>>>(P.xlr, P.e, P.denom, P.src, P.dst, P.agg);
    } else {
        k_edge_scores<1><<<bl, 256>>>(P.xlr, att, P.src, P.dst, P.e, P.emax);
        k_edge_exp<1><<<(nwork + 255) / 256, 256>>>(P.dst, P.emax, P.e, P.denom);
        k_edge_agg<1><<<bl, 256>>>(P.xlr, P.e, P.denom, P.src, P.dst, P.agg);
    }
    size_t total = (size_t)NN * HC;
    k_gat_out<<<gblocks(total, 256), 256>>>(P.agg, P.deg, bias, hout, P.sum, P.sq,
                                            total, HC, relu_out ? 1 : 0);
}

extern "C" void kernel_launch(void* const* d_in, const int* in_sizes, int n_in,
                              void* d_out, int out_size) {
    const float* x     = (const float*)d_in[0];
    const int*   ei    = (const int*)d_in[1];
    const float* y     = (const float*)d_in[2];
    const int*   tidx  = (const int*)d_in[3];
    const float* bn0_g = (const float*)d_in[4];
    const float* bn0_b = (const float*)d_in[5];
    const float* W1l   = (const float*)d_in[6];
    const float* W1r   = (const float*)d_in[7];
    const float* a1    = (const float*)d_in[8];
    const float* b1    = (const float*)d_in[9];
    const float* bn1_g = (const float*)d_in[10];
    const float* bn1_b = (const float*)d_in[11];
    const float* W2l   = (const float*)d_in[12];
    const float* W2r   = (const float*)d_in[13];
    const float* a2    = (const float*)d_in[14];
    const float* b2    = (const float*)d_in[15];
    const float* bn2_g = (const float*)d_in[16];
    const float* bn2_b = (const float*)d_in[17];
    const float* W3l   = (const float*)d_in[18];
    const float* W3r   = (const float*)d_in[19];
    const float* a3    = (const float*)d_in[20];
    const float* b3    = (const float*)d_in[21];
    const float* bn3_g = (const float*)d_in[22];
    const float* bn3_b = (const float*)d_in[23];
    const float* W4l   = (const float*)d_in[24];
    const float* W4r   = (const float*)d_in[25];
    const float* a4    = (const float*)d_in[26];
    const float* b4    = (const float*)d_in[27];
    const float* Wh    = (const float*)d_in[28];
    const float* bh    = (const float*)d_in[29];
    float* out = (float*)d_out;
    int ntr = in_sizes[3];

    cudaFuncSetAttribute(k_gemm3bf, cudaFuncAttributeMaxDynamicSharedMemorySize,
                         (int)(3 * STG * sizeof(unsigned)));

    Ptrs P;
    cudaGetSymbolAddress((void**)&P.Ahi, g_Ahi);
    cudaGetSymbolAddress((void**)&P.Alo, g_Alo);
    cudaGetSymbolAddress((void**)&P.Whi, g_Whi);
    cudaGetSymbolAddress((void**)&P.Wlo, g_Wlo);
    cudaGetSymbolAddress((void**)&P.xlr, g_xlr);
    cudaGetSymbolAddress((void**)&P.h, g_h);
    cudaGetSymbolAddress((void**)&P.agg, g_agg);
    cudaGetSymbolAddress((void**)&P.sum, g_sum);
    cudaGetSymbolAddress((void**)&P.sq, g_sq);
    cudaGetSymbolAddress((void**)&P.scale, g_scale);
    cudaGetSymbolAddress((void**)&P.shift, g_shift);
    cudaGetSymbolAddress((void**)&P.deg, g_deg);
    cudaGetSymbolAddress((void**)&P.e, g_e);
    cudaGetSymbolAddress((void**)&P.denom, g_denom);
    cudaGetSymbolAddress((void**)&P.pred, g_pred);
    cudaGetSymbolAddress((void**)&P.src, g_src);
    cudaGetSymbolAddress((void**)&P.dst, g_dst);
    cudaGetSymbolAddress((void**)&P.emax, g_emax);

    // launch 0
    k_build_edges<<<(EE + 255) / 256, 256>>>(ei, P.src, P.dst, P.deg, P.sum, P.sq);
    // launches 1-3: BN0
    bn_split(x, bn0_g, bn0_b, FIN, FINP, false, P);
    // launch 4: weight split+transpose; launch 5: the big GEMM (ncu -s 5)
    split_w(W1l, W1r, FIN, FINP, 1024, P);
    gemm(P, 2048, FINP);
    k_deg<<<(ET + 255) / 256, 256>>>(P.dst, P.deg);
    edge_phase(a1, b1, 2, P.h, false, P);

    // layer 2
    bn_split(P.h, bn1_g, bn1_b, 1024, 1024, true, P);
    split_w(W2l, W2r, 1024, 1024, 512, P);
    gemm(P, 1024, 1024);
    edge_phase(a2, b2, 1, P.h, false, P);

    // layer 3
    bn_split(P.h, bn2_g, bn2_b, 512, 512, true, P);
    split_w(W3l, W3r, 512, 512, 512, P);
    gemm(P, 1024, 512);
    edge_phase(a3, b3, 1, P.h, false, P);

    // layer 4
    bn_split(P.h, bn3_g, bn3_b, 512, 512, true, P);
    split_w(W4l, W4r, 512, 512, 512, P);
    gemm(P, 1024, 512);
    edge_phase(a4, b4, 1, P.h, true, P);

    // head + gather
    k_head<<<(NN * 32 + 255) / 256, 256>>>(P.h, Wh, bh, P.pred);
    k_gather<<<(ntr + 255) / 256, 256>>>(P.pred, y, tidx, out, ntr);
}

// round 6
// speedup vs baseline: 2.5464x; 1.1872x over previous
#include <cuda_runtime.h>
#include <cuda_bf16.h>
#include <cstdint>
#include <cstddef>

static constexpr int NN  = 8000;
static constexpr int EE  = 64000;
static constexpr int ET  = 72000;
static constexpr int FIN = 3201;
static constexpr int FINP = 3216;
static constexpr int MT  = 8064;
static constexpr int CH  = 512;

// ---------------- scratch ----------------------------------------------------
__device__ __nv_bfloat16 g_Ahi[(size_t)MT * FINP];
__device__ __nv_bfloat16 g_Alo[(size_t)MT * FINP];
__device__ __nv_bfloat16 g_Whi[(size_t)2048 * FINP];
__device__ __nv_bfloat16 g_Wlo[(size_t)2048 * FINP];
__device__ float g_xlr [(size_t)NN * 2048];   // xl | xr
__device__ float g_h   [(size_t)NN * 1024];
__device__ float g_psum[32 * FIN];
__device__ float g_psq [32 * FIN];
__device__ int   g_src [ET];
__device__ int   g_dst [ET];
__device__ int   g_cnt [NN];
__device__ int   g_rowptr[NN + 1];
__device__ int   g_wr  [NN];
__device__ int   g_csrc[ET];
__device__ int   g_cdst[ET];
__device__ float g_e   [ET * 2];
__device__ float g_pred[NN];

// ---------------- helpers ----------------------------------------------------
__device__ __forceinline__ void cp_async16(unsigned saddr, const void* gptr) {
    asm volatile("cp.async.cg.shared.global [%0], [%1], 16;\n" ::"r"(saddr), "l"(gptr));
}
__device__ __forceinline__ void cp_commit() { asm volatile("cp.async.commit_group;\n"); }
template <int N>
__device__ __forceinline__ void cp_wait() {
    asm volatile("cp.async.wait_group %0;\n" ::"n"(N));
}

// ---------------- BN: partial stats (no atomics) ------------------------------
__global__ void k_col_stats_part(const float* __restrict__ X, float* __restrict__ psum,
                                 float* __restrict__ psq, int M, int F) {
    int col = blockIdx.x * blockDim.x + threadIdx.x;
    if (col >= F) return;
    int per = (M + 31) / 32;
    int r0 = blockIdx.y * per;
    int r1 = min(M, r0 + per);
    float s = 0.f, q = 0.f;
    for (int r = r0; r < r1; r++) {
        float v = X[(size_t)r * F + col];
        s += v; q += v * v;
    }
    psum[blockIdx.y * F + col] = s;
    psq[blockIdx.y * F + col] = q;
}

// BN apply + bf16 split, coeffs computed per-block from partials.
// grid ((Fp+63)/64, 32), block 256.
__global__ void k_bn_apply_split(const float* __restrict__ in,
                                 const float* __restrict__ psum,
                                 const float* __restrict__ psq,
                                 const float* __restrict__ g, const float* __restrict__ b,
                                 __nv_bfloat16* __restrict__ Ahi,
                                 __nv_bfloat16* __restrict__ Alo,
                                 int M, int F, int Fp, int relu) {
    __shared__ float ssc[64], ssh[64];
    int tid = threadIdx.x;
    int c0 = blockIdx.x * 64;
    if (tid < 64) {
        int c = c0 + tid;
        float sc = 0.f, sh = 0.f;
        if (c < F) {
            float s = 0.f, q = 0.f;
#pragma unroll
            for (int y = 0; y < 32; y++) { s += psum[y * F + c]; q += psq[y * F + c]; }
            float invM = 1.f / (float)M;
            float m = s * invM;
            float v = q * invM - m * m;
            float r = rsqrtf(v + 1e-5f);
            sc = g[c] * r;
            sh = b[c] - m * sc;
        }
        ssc[tid] = sc; ssh[tid] = sh;
    }
    __syncthreads();
    int cl = tid & 63;
    int c = c0 + cl;
    if (c >= Fp) return;
    int rsub = tid >> 6;
    float sc = ssc[cl], sh = ssh[cl];
    int rows_per = MT / 32;  // 252
    int r0 = blockIdx.y * rows_per;
    bool colv = (c < F);
    for (int i = 0; i < rows_per / 4; i++) {
        int r = r0 + i * 4 + rsub;
        float v = 0.f;
        if (r < M && colv) {
            v = in[(size_t)r * F + c] * sc + sh;
            if (relu) v = fmaxf(v, 0.f);
        }
        __nv_bfloat16 hi = __float2bfloat16_rn(v);
        __nv_bfloat16 lo = __float2bfloat16_rn(v - __bfloat162float(hi));
        size_t o = (size_t)r * Fp + c;
        Ahi[o] = hi;
        Alo[o] = lo;
    }
}

// transpose+split both weights into [2N][Kp] planes
__global__ void k_splitw2(const float* __restrict__ Wl, const float* __restrict__ Wr,
                          __nv_bfloat16* __restrict__ Whi, __nv_bfloat16* __restrict__ Wlo,
                          int K, int Kp, int N) {
    __shared__ float tile[32][33];
    int kt = blockIdx.x * 32;
    int nt = blockIdx.y * 32;
    const float* W = (nt < N) ? Wl : Wr;
    int ncol0 = (nt < N) ? nt : nt - N;
    int tx = threadIdx.x, ty = threadIdx.y;
    int k_in = kt + ty;
    tile[ty][tx] = (k_in < K) ? W[(size_t)k_in * N + ncol0 + tx] : 0.f;
    __syncthreads();
    int k_out = kt + tx;
    if (k_out < Kp) {
        float v = tile[tx][ty];
        __nv_bfloat16 hi = __float2bfloat16_rn(v);
        __nv_bfloat16 lo = __float2bfloat16_rn(v - __bfloat162float(hi));
        size_t o = (size_t)(nt + ty) * Kp + k_out;
        Whi[o] = hi;
        Wlo[o] = lo;
    }
}

// ---------------- 3xBF16 tensor-core GEMM (unchanged from R5) -----------------
#define APL 1024
#define STG 4096

__device__ __forceinline__ void mma_bf16(float* c, const unsigned* a, const unsigned* b) {
    asm volatile(
        "mma.sync.aligned.m16n8k16.row.col.f32.bf16.bf16.f32 "
        "{%0,%1,%2,%3}, {%4,%5,%6,%7}, {%8,%9}, {%0,%1,%2,%3};\n"
        : "+f"(c[0]), "+f"(c[1]), "+f"(c[2]), "+f"(c[3])
        : "r"(a[0]), "r"(a[1]), "r"(a[2]), "r"(a[3]), "r"(b[0]), "r"(b[1]));
}

__global__ __launch_bounds__(256, 1) void k_gemm3bf(
    const __nv_bfloat16* __restrict__ Ahi, const __nv_bfloat16* __restrict__ Alo,
    const __nv_bfloat16* __restrict__ Bhi, const __nv_bfloat16* __restrict__ Blo,
    float* __restrict__ C, int M, int Ncols, int Kp) {
    extern __shared__ unsigned sm[];

    int tid = threadIdx.x;
    int lane = tid & 31;
    int warp = tid >> 5;
    int wm = warp >> 2;
    int wn = warp & 3;
    int gid = lane >> 2;
    int tig = lane & 3;

    int row0 = blockIdx.y * 128;
    int col0 = blockIdx.x * 128;

    int lp = tid >> 7;
    int lr = tid & 127;
    int lsw = (lr >> 2) & 1;

    const __nv_bfloat16* Asrc = lp ? Alo : Ahi;
    const __nv_bfloat16* Bsrc = lp ? Blo : Bhi;
    const __nv_bfloat16* aRow = Asrc + (size_t)(row0 + lr) * Kp;
    const __nv_bfloat16* bRow = Bsrc + (size_t)(col0 + lr) * Kp;
    int aDst0 = lp * APL + lr * 8 + lsw * 4;
    int aDst1 = lp * APL + lr * 8 + (1 - lsw) * 4;
    int bDst0 = 2048 + aDst0;
    int bDst1 = 2048 + aDst1;

    int aoff0[4], aoff2[4], boff0[4], boff1[4];
#pragma unroll
    for (int mt = 0; mt < 4; mt++) {
        int m = wm * 64 + mt * 16 + gid;
        int p = (m >> 2) & 1;
        aoff0[mt] = m * 8 + tig + 4 * p;
        aoff2[mt] = m * 8 + tig + 4 * (1 - p);
    }
#pragma unroll
    for (int nt = 0; nt < 4; nt++) {
        int n = wn * 32 + nt * 8 + gid;
        int q = (n >> 2) & 1;
        boff0[nt] = 2048 + n * 8 + tig + 4 * q;
        boff1[nt] = 2048 + n * 8 + tig + 4 * (1 - q);
    }

    float acc[4][4][4];
#pragma unroll
    for (int i = 0; i < 4; i++)
#pragma unroll
        for (int j = 0; j < 4; j++)
#pragma unroll
            for (int q = 0; q < 4; q++) acc[i][j][q] = 0.f;

    int niter = Kp >> 4;

    auto prefetch = [&](int stage, int k0) {
        unsigned sb = stage * STG;
        cp_async16((unsigned)__cvta_generic_to_shared(&sm[sb + aDst0]), aRow + k0);
        cp_async16((unsigned)__cvta_generic_to_shared(&sm[sb + aDst1]), aRow + k0 + 8);
        cp_async16((unsigned)__cvta_generic_to_shared(&sm[sb + bDst0]), bRow + k0);
        cp_async16((unsigned)__cvta_generic_to_shared(&sm[sb + bDst1]), bRow + k0 + 8);
        cp_commit();
    };

    prefetch(0, 0);
    if (niter > 1) prefetch(1, 16);

    for (int it = 0; it < niter; it++) {
        if (it + 2 < niter) {
            prefetch((it + 2) % 3, (it + 2) * 16);
            cp_wait<2>();
        } else if (it + 1 < niter) {
            cp_wait<1>();
        } else {
            cp_wait<0>();
        }
        __syncthreads();

        const unsigned* s0 = sm + (it % 3) * STG;
        const unsigned* s1 = s0 + APL;

        unsigned ah[4][4], al[4][4], bh[4][2], bl[4][2];
#pragma unroll
        for (int mt = 0; mt < 4; mt++) {
            ah[mt][0] = s0[aoff0[mt]];
            ah[mt][1] = s0[aoff0[mt] + 64];
            ah[mt][2] = s0[aoff2[mt]];
            ah[mt][3] = s0[aoff2[mt] + 64];
            al[mt][0] = s1[aoff0[mt]];
            al[mt][1] = s1[aoff0[mt] + 64];
            al[mt][2] = s1[aoff2[mt]];
            al[mt][3] = s1[aoff2[mt] + 64];
        }
#pragma unroll
        for (int nt = 0; nt < 4; nt++) {
            bh[nt][0] = s0[boff0[nt]];
            bh[nt][1] = s0[boff1[nt]];
            bl[nt][0] = s1[boff0[nt]];
            bl[nt][1] = s1[boff1[nt]];
        }
#pragma unroll
        for (int mt = 0; mt < 4; mt++)
#pragma unroll
            for (int nt = 0; nt < 4; nt++) {
                mma_bf16(acc[mt][nt], al[mt], bh[nt]);
                mma_bf16(acc[mt][nt], ah[mt], bl[nt]);
                mma_bf16(acc[mt][nt], ah[mt], bh[nt]);
            }
        __syncthreads();
    }

#pragma unroll
    for (int mt = 0; mt < 4; mt++) {
        int gr0 = row0 + wm * 64 + mt * 16 + gid;
#pragma unroll
        for (int nt = 0; nt < 4; nt++) {
            int gc = col0 + wn * 32 + nt * 8 + tig * 2;
            if (gr0 < M) {
                C[(size_t)gr0 * Ncols + gc]     = acc[mt][nt][0];
                C[(size_t)gr0 * Ncols + gc + 1] = acc[mt][nt][1];
            }
            if (gr0 + 8 < M) {
                C[(size_t)(gr0 + 8) * Ncols + gc]     = acc[mt][nt][2];
                C[(size_t)(gr0 + 8) * Ncols + gc + 1] = acc[mt][nt][3];
            }
        }
    }
}

// ---------------- CSR construction -------------------------------------------
__global__ void k_build_edges(const int* __restrict__ ei, int* src, int* dst, int* cnt) {
    int i = blockIdx.x * blockDim.x + threadIdx.x;
    if (i < EE) { src[i] = ei[i]; dst[i] = ei[EE + i]; }
    if (i < NN) { src[EE + i] = i; dst[EE + i] = i; cnt[i] = 0; }
}
__global__ void k_count(const int* __restrict__ dst, int* cnt) {
    int i = blockIdx.x * blockDim.x + threadIdx.x;
    if (i < ET) atomicAdd(&cnt[dst[i]], 1);
}
__global__ void k_scan(const int* __restrict__ cnt, int* rowptr, int* wr) {
    __shared__ int sm[1024];
    __shared__ int carry;
    int tid = threadIdx.x;
    if (tid == 0) carry = 0;
    __syncthreads();
    for (int base = 0; base < NN; base += 1024) {
        int i = base + tid;
        int x = (i < NN) ? cnt[i] : 0;
        sm[tid] = x;
        __syncthreads();
        for (int off = 1; off < 1024; off <<= 1) {
            int v = (tid >= off) ? sm[tid - off] : 0;
            __syncthreads();
            sm[tid] += v;
            __syncthreads();
        }
        int excl = sm[tid] - x + carry;
        if (i < NN) { rowptr[i] = excl; wr[i] = excl; }
        __syncthreads();
        if (tid == 1023) carry += sm[1023];
        __syncthreads();
    }
    if (tid == 0) rowptr[NN] = carry;
}
__global__ void k_scatter(const int* __restrict__ src, const int* __restrict__ dst,
                          int* wr, int* csrc, int* cdst) {
    int i = blockIdx.x * blockDim.x + threadIdx.x;
    if (i >= ET) return;
    int d = dst[i];
    int pos = atomicAdd(&wr[d], 1);
    csrc[pos] = src[i];
    cdst[pos] = d;
}

// ---------------- GATv2 edge scores (per CSR position) ------------------------
template <int H>
__global__ void k_edge_scores(const float* __restrict__ xlr,
                              const float* __restrict__ att,
                              const int* __restrict__ csrc, const int* __restrict__ cdst,
                              float* __restrict__ e) {
    int gw = (blockIdx.x * blockDim.x + threadIdx.x) >> 5;
    int lane = threadIdx.x & 31;
    if (gw >= ET * H) return;
    int edge = gw / H, h = gw % H;
    int s = csrc[edge], d = cdst[edge];
    const int stride = 2 * H * CH;
    const float4* pl = (const float4*)(xlr + (size_t)s * stride + h * CH);
    const float4* pr = (const float4*)(xlr + (size_t)d * stride + H * CH + h * CH);
    const float4* pa = (const float4*)(att + h * CH);
    float acc = 0.f;
#pragma unroll
    for (int c = lane; c < CH / 4; c += 32) {
        float4 a = pl[c], b = pr[c], w = pa[c];
        float z0 = a.x + b.x; z0 = z0 > 0.f ? z0 : 0.2f * z0;
        float z1 = a.y + b.y; z1 = z1 > 0.f ? z1 : 0.2f * z1;
        float z2 = a.z + b.z; z2 = z2 > 0.f ? z2 : 0.2f * z2;
        float z3 = a.w + b.w; z3 = z3 > 0.f ? z3 : 0.2f * z3;
        acc += z0 * w.x + z1 * w.y + z2 * w.z + z3 * w.w;
    }
#pragma unroll
    for (int o = 16; o; o >>= 1) acc += __shfl_xor_sync(0xFFFFFFFFu, acc, o);
    if (lane == 0) e[(size_t)edge * H + h] = acc;
}

// ---------------- fused segment softmax + aggregate + bias(+relu) -------------
// one warp per (dst, head); writes hout directly.
template <int H>
__global__ void k_seg(const float* __restrict__ xlr, const float* __restrict__ e,
                      const int* __restrict__ rowptr, const int* __restrict__ csrc,
                      const float* __restrict__ bias, float* __restrict__ hout,
                      int relu) {
    int gw = (blockIdx.x * blockDim.x + threadIdx.x) >> 5;
    int lane = threadIdx.x & 31;
    if (gw >= NN * H) return;
    int d = gw / H, h = gw % H;
    int lo = rowptr[d], hi = rowptr[d + 1];

    float m = -3.4e38f;
    for (int p = lo + lane; p < hi; p += 32) m = fmaxf(m, e[(size_t)p * H + h]);
#pragma unroll
    for (int o = 16; o; o >>= 1) m = fmaxf(m, __shfl_xor_sync(0xFFFFFFFFu, m, o));

    float s = 0.f;
    for (int p = lo + lane; p < hi; p += 32) s += expf(e[(size_t)p * H + h] - m);
#pragma unroll
    for (int o = 16; o; o >>= 1) s += __shfl_xor_sync(0xFFFFFFFFu, s, o);
    float inv = 1.f / s;

    const int stride = 2 * H * CH;
    float4 acc[4];
#pragma unroll
    for (int j = 0; j < 4; j++) acc[j] = make_float4(0.f, 0.f, 0.f, 0.f);

    for (int p = lo; p < hi; p++) {
        float a = expf(e[(size_t)p * H + h] - m) * inv;
        const float4* pl = (const float4*)(xlr + (size_t)csrc[p] * stride + h * CH);
#pragma unroll
        for (int j = 0; j < 4; j++) {
            float4 v = pl[lane + 32 * j];
            acc[j].x += a * v.x;
            acc[j].y += a * v.y;
            acc[j].z += a * v.z;
            acc[j].w += a * v.w;
        }
    }

    float invdeg = 1.f / (float)(hi - lo);
    float4* po = (float4*)(hout + (size_t)d * (H * CH) + h * CH);
    const float4* pb = (const float4*)(bias + h * CH);
#pragma unroll
    for (int j = 0; j < 4; j++) {
        float4 b4 = pb[lane + 32 * j];
        float4 w;
        w.x = acc[j].x * invdeg + b4.x;
        w.y = acc[j].y * invdeg + b4.y;
        w.z = acc[j].z * invdeg + b4.z;
        w.w = acc[j].w * invdeg + b4.w;
        if (relu) {
            w.x = fmaxf(w.x, 0.f); w.y = fmaxf(w.y, 0.f);
            w.z = fmaxf(w.z, 0.f); w.w = fmaxf(w.w, 0.f);
        }
        po[lane + 32 * j] = w;
    }
}

// ---------------- head + gather ----------------------------------------------
__global__ void k_head(const float* __restrict__ h, const float* __restrict__ Wh,
                       const float* __restrict__ bh, float* __restrict__ pred) {
    int gw = (blockIdx.x * blockDim.x + threadIdx.x) >> 5;
    int lane = threadIdx.x & 31;
    if (gw >= NN) return;
    const float* ph = h + (size_t)gw * CH;
    float acc = 0.f;
#pragma unroll
    for (int c = lane; c < CH; c += 32) acc += ph[c] * Wh[c];
#pragma unroll
    for (int o = 16; o; o >>= 1) acc += __shfl_xor_sync(0xFFFFFFFFu, acc, o);
    if (lane == 0) {
        float t = acc + bh[0];
        pred[gw] = 1.f / (1.f + expf(-t));
    }
}
__global__ void k_gather(const float* __restrict__ pred, const float* __restrict__ y,
                         const int* __restrict__ tidx, float* __restrict__ out, int ntr) {
    int i = blockIdx.x * blockDim.x + threadIdx.x;
    if (i >= ntr) return;
    int j = tidx[i];
    out[i] = pred[j];
    out[ntr + i] = y[j];
}

// ---------------- host orchestration ------------------------------------------
struct Ptrs {
    __nv_bfloat16 *Ahi, *Alo, *Whi, *Wlo;
    float *xlr, *h, *psum, *psq, *e, *pred;
    int *src, *dst, *cnt, *rowptr, *wr, *csrc, *cdst;
};

static void bn_split(const float* in, const float* g, const float* b, int F, int Fp,
                     bool relu, Ptrs& P) {
    dim3 sg((F + 255) / 256, 32);
    k_col_stats_part<<<sg, 256>>>(in, P.psum, P.psq, NN, F);
    dim3 ag((Fp + 63) / 64, 32);
    k_bn_apply_split<<<ag, 256>>>(in, P.psum, P.psq, g, b, P.Ahi, P.Alo, NN, F, Fp,
                                  relu ? 1 : 0);
}

static void split_w(const float* Wl, const float* Wr, int K, int Kp, int N, Ptrs& P) {
    dim3 g((Kp + 31) / 32, (2 * N) / 32);
    k_splitw2<<<g, dim3(32, 32)>>>(Wl, Wr, P.Whi, P.Wlo, K, Kp, N);
}

static void gemm(Ptrs& P, int Ncols, int Kp) {
    dim3 gg(Ncols / 128, MT / 128);
    size_t smem = 3 * STG * sizeof(unsigned);
    k_gemm3bf<<<gg, 256, smem>>>(P.Ahi, P.Alo, P.Whi, P.Wlo, P.xlr, NN, Ncols, Kp);
}

static void edge_phase(const float* att, const float* bias, int H, float* hout,
                       bool relu_out, Ptrs& P) {
    int bl = (ET * H * 32 + 255) / 256;
    int sb = (NN * H * 32 + 255) / 256;
    if (H == 2) {
        k_edge_scores<2><<<bl, 256>>>(P.xlr, att, P.csrc, P.cdst, P.e);
        k_seg<2><<<sb, 256>>>(P.xlr, P.e, P.rowptr, P.csrc, bias, hout, relu_out ? 1 : 0);
    } else {
        k_edge_scores<1><<<bl, 256>>>(P.xlr, att, P.csrc, P.cdst, P.e);
        k_seg<1><<<sb, 256>>>(P.xlr, P.e, P.rowptr, P.csrc, bias, hout, relu_out ? 1 : 0);
    }
}

extern "C" void kernel_launch(void* const* d_in, const int* in_sizes, int n_in,
                              void* d_out, int out_size) {
    const float* x     = (const float*)d_in[0];
    const int*   ei    = (const int*)d_in[1];
    const float* y     = (const float*)d_in[2];
    const int*   tidx  = (const int*)d_in[3];
    const float* bn0_g = (const float*)d_in[4];
    const float* bn0_b = (const float*)d_in[5];
    const float* W1l   = (const float*)d_in[6];
    const float* W1r   = (const float*)d_in[7];
    const float* a1    = (const float*)d_in[8];
    const float* b1    = (const float*)d_in[9];
    const float* bn1_g = (const float*)d_in[10];
    const float* bn1_b = (const float*)d_in[11];
    const float* W2l   = (const float*)d_in[12];
    const float* W2r   = (const float*)d_in[13];
    const float* a2    = (const float*)d_in[14];
    const float* b2    = (const float*)d_in[15];
    const float* bn2_g = (const float*)d_in[16];
    const float* bn2_b = (const float*)d_in[17];
    const float* W3l   = (const float*)d_in[18];
    const float* W3r   = (const float*)d_in[19];
    const float* a3    = (const float*)d_in[20];
    const float* b3    = (const float*)d_in[21];
    const float* bn3_g = (const float*)d_in[22];
    const float* bn3_b = (const float*)d_in[23];
    const float* W4l   = (const float*)d_in[24];
    const float* W4r   = (const float*)d_in[25];
    const float* a4    = (const float*)d_in[26];
    const float* b4    = (const float*)d_in[27];
    const float* Wh    = (const float*)d_in[28];
    const float* bh    = (const float*)d_in[29];
    float* out = (float*)d_out;
    int ntr = in_sizes[3];

    cudaFuncSetAttribute(k_gemm3bf, cudaFuncAttributeMaxDynamicSharedMemorySize,
                         (int)(3 * STG * sizeof(unsigned)));

    Ptrs P;
    cudaGetSymbolAddress((void**)&P.Ahi, g_Ahi);
    cudaGetSymbolAddress((void**)&P.Alo, g_Alo);
    cudaGetSymbolAddress((void**)&P.Whi, g_Whi);
    cudaGetSymbolAddress((void**)&P.Wlo, g_Wlo);
    cudaGetSymbolAddress((void**)&P.xlr, g_xlr);
    cudaGetSymbolAddress((void**)&P.h, g_h);
    cudaGetSymbolAddress((void**)&P.psum, g_psum);
    cudaGetSymbolAddress((void**)&P.psq, g_psq);
    cudaGetSymbolAddress((void**)&P.e, g_e);
    cudaGetSymbolAddress((void**)&P.pred, g_pred);
    cudaGetSymbolAddress((void**)&P.src, g_src);
    cudaGetSymbolAddress((void**)&P.dst, g_dst);
    cudaGetSymbolAddress((void**)&P.cnt, g_cnt);
    cudaGetSymbolAddress((void**)&P.rowptr, g_rowptr);
    cudaGetSymbolAddress((void**)&P.wr, g_wr);
    cudaGetSymbolAddress((void**)&P.csrc, g_csrc);
    cudaGetSymbolAddress((void**)&P.cdst, g_cdst);

    // launches 0-2: BN0 (stats, weight split, apply+split). launch 3: big GEMM.
    dim3 sg((FIN + 255) / 256, 32);
    k_col_stats_part<<<sg, 256>>>(x, P.psum, P.psq, NN, FIN);
    split_w(W1l, W1r, FIN, FINP, 1024, P);
    dim3 ag((FINP + 63) / 64, 32);
    k_bn_apply_split<<<ag, 256>>>(x, P.psum, P.psq, bn0_g, bn0_b, P.Ahi, P.Alo,
                                  NN, FIN, FINP, 0);
    gemm(P, 2048, FINP);   // ncu -s 5 -c 1 lands here

    // CSR build (once)
    k_build_edges<<<(EE + 255) / 256, 256>>>(ei, P.src, P.dst, P.cnt);
    k_count<<<(ET + 255) / 256, 256>>>(P.dst, P.cnt);
    k_scan<<<1, 1024>>>(P.cnt, P.rowptr, P.wr);
    k_scatter<<<(ET + 255) / 256, 256>>>(P.src, P.dst, P.wr, P.csrc, P.cdst);

    // layer 1 edge phase
    edge_phase(a1, b1, 2, P.h, false, P);

    // layer 2
    bn_split(P.h, bn1_g, bn1_b, 1024, 1024, true, P);
    split_w(W2l, W2r, 1024, 1024, 512, P);
    gemm(P, 1024, 1024);
    edge_phase(a2, b2, 1, P.h, false, P);

    // layer 3
    bn_split(P.h, bn2_g, bn2_b, 512, 512, true, P);
    split_w(W3l, W3r, 512, 512, 512, P);
    gemm(P, 1024, 512);
    edge_phase(a3, b3, 1, P.h, false, P);

    // layer 4
    bn_split(P.h, bn3_g, bn3_b, 512, 512, true, P);
    split_w(W4l, W4r, 512, 512, 512, P);
    gemm(P, 1024, 512);
    edge_phase(a4, b4, 1, P.h, true, P);

    // head + gather
    k_head<<<(NN * 32 + 255) / 256, 256>>>(P.h, Wh, bh, P.pred);
    k_gather<<<(ntr + 255) / 256, 256>>>(P.pred, y, tidx, out, ntr);
}

// round 8
// speedup vs baseline: 2.7297x; 1.0720x over previous
#include <cuda_runtime.h>
#include <cuda_bf16.h>
#include <cstdint>
#include <cstddef>

static constexpr int NN  = 8000;
static constexpr int EE  = 64000;
static constexpr int ET  = 72000;
static constexpr int FIN = 3201;
static constexpr int FINP = 3216;
static constexpr int MT  = 8064;
static constexpr int CH  = 512;

// ---------------- scratch ----------------------------------------------------
__device__ __nv_bfloat16 g_Ahi[(size_t)MT * FINP];
__device__ __nv_bfloat16 g_Alo[(size_t)MT * FINP];
__device__ __nv_bfloat16 g_Whi[(size_t)2048 * FINP];
__device__ __nv_bfloat16 g_Wlo[(size_t)2048 * FINP];
__device__ float g_xlr [(size_t)NN * 2048];   // xl | xr
__device__ float g_h   [(size_t)NN * 1024];
__device__ float g_psum[32 * FIN];
__device__ float g_psq [32 * FIN];
__device__ int   g_src [ET];
__device__ int   g_dst [ET];
__device__ int   g_cnt [NN];
__device__ int   g_rowptr[NN + 1];
__device__ int   g_wr  [NN];
__device__ int   g_csrc[ET];
__device__ int   g_cdst[ET];
__device__ float g_e   [ET * 2];
__device__ float g_pred[NN];

// ---------------- helpers ----------------------------------------------------
__device__ __forceinline__ void cp_async16(unsigned saddr, const void* gptr) {
    asm volatile("cp.async.cg.shared.global [%0], [%1], 16;\n" ::"r"(saddr), "l"(gptr));
}
__device__ __forceinline__ void cp_commit() { asm volatile("cp.async.commit_group;\n"); }
template <int N>
__device__ __forceinline__ void cp_wait() {
    asm volatile("cp.async.wait_group %0;\n" ::"n"(N));
}

// ---------------- BN: partial stats (no atomics) ------------------------------
__global__ void k_col_stats_part(const float* __restrict__ X, float* __restrict__ psum,
                                 float* __restrict__ psq, int M, int F) {
    int col = blockIdx.x * blockDim.x + threadIdx.x;
    if (col >= F) return;
    int per = (M + 31) / 32;
    int r0 = blockIdx.y * per;
    int r1 = min(M, r0 + per);
    float s = 0.f, q = 0.f;
    for (int r = r0; r < r1; r++) {
        float v = X[(size_t)r * F + col];
        s += v; q += v * v;
    }
    psum[blockIdx.y * F + col] = s;
    psq[blockIdx.y * F + col] = q;
}

// BN apply + bf16 split, coeffs computed per-block from partials.
__global__ void k_bn_apply_split(const float* __restrict__ in,
                                 const float* __restrict__ psum,
                                 const float* __restrict__ psq,
                                 const float* __restrict__ g, const float* __restrict__ b,
                                 __nv_bfloat16* __restrict__ Ahi,
                                 __nv_bfloat16* __restrict__ Alo,
                                 int M, int F, int Fp, int relu) {
    __shared__ float ssc[64], ssh[64];
    int tid = threadIdx.x;
    int c0 = blockIdx.x * 64;
    if (tid < 64) {
        int c = c0 + tid;
        float sc = 0.f, sh = 0.f;
        if (c < F) {
            float s = 0.f, q = 0.f;
#pragma unroll
            for (int y = 0; y < 32; y++) { s += psum[y * F + c]; q += psq[y * F + c]; }
            float invM = 1.f / (float)M;
            float m = s * invM;
            float v = q * invM - m * m;
            float r = rsqrtf(v + 1e-5f);
            sc = g[c] * r;
            sh = b[c] - m * sc;
        }
        ssc[tid] = sc; ssh[tid] = sh;
    }
    __syncthreads();
    int cl = tid & 63;
    int c = c0 + cl;
    if (c >= Fp) return;
    int rsub = tid >> 6;
    float sc = ssc[cl], sh = ssh[cl];
    int rows_per = MT / 32;  // 252
    int r0 = blockIdx.y * rows_per;
    bool colv = (c < F);
    for (int i = 0; i < rows_per / 4; i++) {
        int r = r0 + i * 4 + rsub;
        float v = 0.f;
        if (r < M && colv) {
            v = in[(size_t)r * F + c] * sc + sh;
            if (relu) v = fmaxf(v, 0.f);
        }
        __nv_bfloat16 hi = __float2bfloat16_rn(v);
        __nv_bfloat16 lo = __float2bfloat16_rn(v - __bfloat162float(hi));
        size_t o = (size_t)r * Fp + c;
        Ahi[o] = hi;
        Alo[o] = lo;
    }
}

// transpose+split both weights into [2N][Kp] planes
__global__ void k_splitw2(const float* __restrict__ Wl, const float* __restrict__ Wr,
                          __nv_bfloat16* __restrict__ Whi, __nv_bfloat16* __restrict__ Wlo,
                          int K, int Kp, int N) {
    __shared__ float tile[32][33];
    int kt = blockIdx.x * 32;
    int nt = blockIdx.y * 32;
    const float* W = (nt < N) ? Wl : Wr;
    int ncol0 = (nt < N) ? nt : nt - N;
    int tx = threadIdx.x, ty = threadIdx.y;
    int k_in = kt + ty;
    tile[ty][tx] = (k_in < K) ? W[(size_t)k_in * N + ncol0 + tx] : 0.f;
    __syncthreads();
    int k_out = kt + tx;
    if (k_out < Kp) {
        float v = tile[tx][ty];
        __nv_bfloat16 hi = __float2bfloat16_rn(v);
        __nv_bfloat16 lo = __float2bfloat16_rn(v - __bfloat162float(hi));
        size_t o = (size_t)(nt + ty) * Kp + k_out;
        Whi[o] = hi;
        Wlo[o] = lo;
    }
}

// ---------------- 3xBF16 tensor-core GEMM (3-stage pipeline, 2 CTAs/SM) -------
#define APL 1024
#define STG 4096

__device__ __forceinline__ void mma_bf16(float* c, const unsigned* a, const unsigned* b) {
    asm volatile(
        "mma.sync.aligned.m16n8k16.row.col.f32.bf16.bf16.f32 "
        "{%0,%1,%2,%3}, {%4,%5,%6,%7}, {%8,%9}, {%0,%1,%2,%3};\n"
        : "+f"(c[0]), "+f"(c[1]), "+f"(c[2]), "+f"(c[3])
        : "r"(a[0]), "r"(a[1]), "r"(a[2]), "r"(a[3]), "r"(b[0]), "r"(b[1]));
}

__global__ __launch_bounds__(256, 2) void k_gemm3bf(
    const __nv_bfloat16* __restrict__ Ahi, const __nv_bfloat16* __restrict__ Alo,
    const __nv_bfloat16* __restrict__ Bhi, const __nv_bfloat16* __restrict__ Blo,
    float* __restrict__ C, int M, int Ncols, int Kp) {
    extern __shared__ unsigned sm[];

    int tid = threadIdx.x;
    int lane = tid & 31;
    int warp = tid >> 5;
    int wm = warp >> 2;
    int wn = warp & 3;
    int gid = lane >> 2;
    int tig = lane & 3;

    int row0 = blockIdx.y * 128;
    int col0 = blockIdx.x * 128;

    int lp = tid >> 7;
    int lr = tid & 127;
    int lsw = (lr >> 2) & 1;

    const __nv_bfloat16* Asrc = lp ? Alo : Ahi;
    const __nv_bfloat16* Bsrc = lp ? Blo : Bhi;
    const __nv_bfloat16* aRow = Asrc + (size_t)(row0 + lr) * Kp;
    const __nv_bfloat16* bRow = Bsrc + (size_t)(col0 + lr) * Kp;
    int aDst0 = lp * APL + lr * 8 + lsw * 4;
    int aDst1 = lp * APL + lr * 8 + (1 - lsw) * 4;
    int bDst0 = 2048 + aDst0;
    int bDst1 = 2048 + aDst1;

    int aoff0[4], aoff2[4], boff0[4], boff1[4];
#pragma unroll
    for (int mt = 0; mt < 4; mt++) {
        int m = wm * 64 + mt * 16 + gid;
        int p = (m >> 2) & 1;
        aoff0[mt] = m * 8 + tig + 4 * p;
        aoff2[mt] = m * 8 + tig + 4 * (1 - p);
    }
#pragma unroll
    for (int nt = 0; nt < 4; nt++) {
        int n = wn * 32 + nt * 8 + gid;
        int q = (n >> 2) & 1;
        boff0[nt] = 2048 + n * 8 + tig + 4 * q;
        boff1[nt] = 2048 + n * 8 + tig + 4 * (1 - q);
    }

    float acc[4][4][4];
#pragma unroll
    for (int i = 0; i < 4; i++)
#pragma unroll
        for (int j = 0; j < 4; j++)
#pragma unroll
            for (int q = 0; q < 4; q++) acc[i][j][q] = 0.f;

    int niter = Kp >> 4;

    auto prefetch = [&](int stage, int k0) {
        unsigned sb = stage * STG;
        cp_async16((unsigned)__cvta_generic_to_shared(&sm[sb + aDst0]), aRow + k0);
        cp_async16((unsigned)__cvta_generic_to_shared(&sm[sb + aDst1]), aRow + k0 + 8);
        cp_async16((unsigned)__cvta_generic_to_shared(&sm[sb + bDst0]), bRow + k0);
        cp_async16((unsigned)__cvta_generic_to_shared(&sm[sb + bDst1]), bRow + k0 + 8);
        cp_commit();
    };

    prefetch(0, 0);
    if (niter > 1) prefetch(1, 16);

    for (int it = 0; it < niter; it++) {
        if (it + 2 < niter) {
            prefetch((it + 2) % 3, (it + 2) * 16);
            cp_wait<2>();
        } else if (it + 1 < niter) {
            cp_wait<1>();
        } else {
            cp_wait<0>();
        }
        __syncthreads();

        const unsigned* s0 = sm + (it % 3) * STG;
        const unsigned* s1 = s0 + APL;

        unsigned ah[4][4], al[4][4], bh[4][2], bl[4][2];
#pragma unroll
        for (int mt = 0; mt < 4; mt++) {
            ah[mt][0] = s0[aoff0[mt]];
            ah[mt][1] = s0[aoff0[mt] + 64];
            ah[mt][2] = s0[aoff2[mt]];
            ah[mt][3] = s0[aoff2[mt] + 64];
            al[mt][0] = s1[aoff0[mt]];
            al[mt][1] = s1[aoff0[mt] + 64];
            al[mt][2] = s1[aoff2[mt]];
            al[mt][3] = s1[aoff2[mt] + 64];
        }
#pragma unroll
        for (int nt = 0; nt < 4; nt++) {
            bh[nt][0] = s0[boff0[nt]];
            bh[nt][1] = s0[boff1[nt]];
            bl[nt][0] = s1[boff0[nt]];
            bl[nt][1] = s1[boff1[nt]];
        }
#pragma unroll
        for (int mt = 0; mt < 4; mt++)
#pragma unroll
            for (int nt = 0; nt < 4; nt++) {
                mma_bf16(acc[mt][nt], al[mt], bh[nt]);
                mma_bf16(acc[mt][nt], ah[mt], bl[nt]);
                mma_bf16(acc[mt][nt], ah[mt], bh[nt]);
            }
        __syncthreads();
    }

#pragma unroll
    for (int mt = 0; mt < 4; mt++) {
        int gr0 = row0 + wm * 64 + mt * 16 + gid;
#pragma unroll
        for (int nt = 0; nt < 4; nt++) {
            int gc = col0 + wn * 32 + nt * 8 + tig * 2;
            if (gr0 < M) {
                C[(size_t)gr0 * Ncols + gc]     = acc[mt][nt][0];
                C[(size_t)gr0 * Ncols + gc + 1] = acc[mt][nt][1];
            }
            if (gr0 + 8 < M) {
                C[(size_t)(gr0 + 8) * Ncols + gc]     = acc[mt][nt][2];
                C[(size_t)(gr0 + 8) * Ncols + gc + 1] = acc[mt][nt][3];
            }
        }
    }
}

// ---------------- CSR construction -------------------------------------------
__global__ void k_build_edges(const int* __restrict__ ei, int* src, int* dst, int* cnt) {
    int i = blockIdx.x * blockDim.x + threadIdx.x;
    if (i < EE) { src[i] = ei[i]; dst[i] = ei[EE + i]; }
    if (i < NN) { src[EE + i] = i; dst[EE + i] = i; cnt[i] = 0; }
}
__global__ void k_count(const int* __restrict__ dst, int* cnt) {
    int i = blockIdx.x * blockDim.x + threadIdx.x;
    if (i < ET) atomicAdd(&cnt[dst[i]], 1);
}
__global__ void k_scan(const int* __restrict__ cnt, int* rowptr, int* wr) {
    __shared__ int sm[1024];
    __shared__ int carry;
    int tid = threadIdx.x;
    if (tid == 0) carry = 0;
    __syncthreads();
    for (int base = 0; base < NN; base += 1024) {
        int i = base + tid;
        int x = (i < NN) ? cnt[i] : 0;
        sm[tid] = x;
        __syncthreads();
        for (int off = 1; off < 1024; off <<= 1) {
            int v = (tid >= off) ? sm[tid - off] : 0;
            __syncthreads();
            sm[tid] += v;
            __syncthreads();
        }
        int excl = sm[tid] - x + carry;
        if (i < NN) { rowptr[i] = excl; wr[i] = excl; }
        __syncthreads();
        if (tid == 1023) carry += sm[1023];
        __syncthreads();
    }
    if (tid == 0) rowptr[NN] = carry;
}
__global__ void k_scatter(const int* __restrict__ src, const int* __restrict__ dst,
                          int* wr, int* csrc, int* cdst) {
    int i = blockIdx.x * blockDim.x + threadIdx.x;
    if (i >= ET) return;
    int d = dst[i];
    int pos = atomicAdd(&wr[d], 1);
    csrc[pos] = src[i];
    cdst[pos] = d;
}

// ---------------- GATv2 edge scores ------------------------------------------
template <int H>
__global__ void k_edge_scores(const float* __restrict__ xlr,
                              const float* __restrict__ att,
                              const int* __restrict__ csrc, const int* __restrict__ cdst,
                              float* __restrict__ e) {
    int gw = (blockIdx.x * blockDim.x + threadIdx.x) >> 5;
    int lane = threadIdx.x & 31;
    if (gw >= ET * H) return;
    int edge = gw / H, h = gw % H;
    int s = csrc[edge], d = cdst[edge];
    const int stride = 2 * H * CH;
    const float4* pl = (const float4*)(xlr + (size_t)s * stride + h * CH);
    const float4* pr = (const float4*)(xlr + (size_t)d * stride + H * CH + h * CH);
    const float4* pa = (const float4*)(att + h * CH);
    float acc = 0.f;
#pragma unroll
    for (int c = lane; c < CH / 4; c += 32) {
        float4 a = pl[c], b = pr[c], w = pa[c];
        float z0 = a.x + b.x; z0 = z0 > 0.f ? z0 : 0.2f * z0;
        float z1 = a.y + b.y; z1 = z1 > 0.f ? z1 : 0.2f * z1;
        float z2 = a.z + b.z; z2 = z2 > 0.f ? z2 : 0.2f * z2;
        float z3 = a.w + b.w; z3 = z3 > 0.f ? z3 : 0.2f * z3;
        acc += z0 * w.x + z1 * w.y + z2 * w.z + z3 * w.w;
    }
#pragma unroll
    for (int o = 16; o; o >>= 1) acc += __shfl_xor_sync(0xFFFFFFFFu, acc, o);
    if (lane == 0) e[(size_t)edge * H + h] = acc;
}

// ---------------- fused segment softmax + aggregate + bias(+relu) -------------
template <int H>
__global__ void k_seg(const float* __restrict__ xlr, const float* __restrict__ e,
                      const int* __restrict__ rowptr, const int* __restrict__ csrc,
                      const float* __restrict__ bias, float* __restrict__ hout,
                      int relu) {
    int gw = (blockIdx.x * blockDim.x + threadIdx.x) >> 5;
    int lane = threadIdx.x & 31;
    if (gw >= NN * H) return;
    int d = gw / H, h = gw % H;
    int lo = rowptr[d], hi = rowptr[d + 1];

    float m = -3.4e38f;
    for (int p = lo + lane; p < hi; p += 32) m = fmaxf(m, e[(size_t)p * H + h]);
#pragma unroll
    for (int o = 16; o; o >>= 1) m = fmaxf(m, __shfl_xor_sync(0xFFFFFFFFu, m, o));

    float s = 0.f;
    for (int p = lo + lane; p < hi; p += 32) s += expf(e[(size_t)p * H + h] - m);
#pragma unroll
    for (int o = 16; o; o >>= 1) s += __shfl_xor_sync(0xFFFFFFFFu, s, o);
    float inv = 1.f / s;

    const int stride = 2 * H * CH;
    float4 acc[4];
#pragma unroll
    for (int j = 0; j < 4; j++) acc[j] = make_float4(0.f, 0.f, 0.f, 0.f);

    for (int p = lo; p < hi; p++) {
        float a = expf(e[(size_t)p * H + h] - m) * inv;
        const float4* pl = (const float4*)(xlr + (size_t)csrc[p] * stride + h * CH);
#pragma unroll
        for (int j = 0; j < 4; j++) {
            float4 v = pl[lane + 32 * j];
            acc[j].x += a * v.x;
            acc[j].y += a * v.y;
            acc[j].z += a * v.z;
            acc[j].w += a * v.w;
        }
    }

    float invdeg = 1.f / (float)(hi - lo);
    float4* po = (float4*)(hout + (size_t)d * (H * CH) + h * CH);
    const float4* pb = (const float4*)(bias + h * CH);
#pragma unroll
    for (int j = 0; j < 4; j++) {
        float4 b4 = pb[lane + 32 * j];
        float4 w;
        w.x = acc[j].x * invdeg + b4.x;
        w.y = acc[j].y * invdeg + b4.y;
        w.z = acc[j].z * invdeg + b4.z;
        w.w = acc[j].w * invdeg + b4.w;
        if (relu) {
            w.x = fmaxf(w.x, 0.f); w.y = fmaxf(w.y, 0.f);
            w.z = fmaxf(w.z, 0.f); w.w = fmaxf(w.w, 0.f);
        }
        po[lane + 32 * j] = w;
    }
}

// ---------------- head + gather ----------------------------------------------
__global__ void k_head(const float* __restrict__ h, const float* __restrict__ Wh,
                       const float* __restrict__ bh, float* __restrict__ pred) {
    int gw = (blockIdx.x * blockDim.x + threadIdx.x) >> 5;
    int lane = threadIdx.x & 31;
    if (gw >= NN) return;
    const float* ph = h + (size_t)gw * CH;
    float acc = 0.f;
#pragma unroll
    for (int c = lane; c < CH; c += 32) acc += ph[c] * Wh[c];
#pragma unroll
    for (int o = 16; o; o >>= 1) acc += __shfl_xor_sync(0xFFFFFFFFu, acc, o);
    if (lane == 0) {
        float t = acc + bh[0];
        pred[gw] = 1.f / (1.f + expf(-t));
    }
}
__global__ void k_gather(const float* __restrict__ pred, const float* __restrict__ y,
                         const int* __restrict__ tidx, float* __restrict__ out, int ntr) {
    int i = blockIdx.x * blockDim.x + threadIdx.x;
    if (i >= ntr) return;
    int j = tidx[i];
    out[i] = pred[j];
    out[ntr + i] = y[j];
}

// ---------------- host orchestration ------------------------------------------
struct Ptrs {
    __nv_bfloat16 *Ahi, *Alo, *Whi, *Wlo;
    float *xlr, *h, *psum, *psq, *e, *pred;
    int *src, *dst, *cnt, *rowptr, *wr, *csrc, *cdst;
};

static void bn_split(const float* in, const float* g, const float* b, int F, int Fp,
                     bool relu, Ptrs& P) {
    dim3 sg((F + 255) / 256, 32);
    k_col_stats_part<<<sg, 256>>>(in, P.psum, P.psq, NN, F);
    dim3 ag((Fp + 63) / 64, 32);
    k_bn_apply_split<<<ag, 256>>>(in, P.psum, P.psq, g, b, P.Ahi, P.Alo, NN, F, Fp,
                                  relu ? 1 : 0);
}

static void split_w(const float* Wl, const float* Wr, int K, int Kp, int N, Ptrs& P) {
    dim3 g((Kp + 31) / 32, (2 * N) / 32);
    k_splitw2<<<g, dim3(32, 32)>>>(Wl, Wr, P.Whi, P.Wlo, K, Kp, N);
}

static void gemm(Ptrs& P, int Ncols, int Kp) {
    dim3 gg(Ncols / 128, MT / 128);
    size_t smem = 3 * STG * sizeof(unsigned);
    k_gemm3bf<<<gg, 256, smem>>>(P.Ahi, P.Alo, P.Whi, P.Wlo, P.xlr, NN, Ncols, Kp);
}

static void edge_phase(const float* att, const float* bias, int H, float* hout,
                       bool relu_out, Ptrs& P) {
    int bl = (ET * H * 32 + 255) / 256;
    int sb = (NN * H * 32 + 255) / 256;
    if (H == 2) {
        k_edge_scores<2><<<bl, 256>>>(P.xlr, att, P.csrc, P.cdst, P.e);
        k_seg<2><<<sb, 256>>>(P.xlr, P.e, P.rowptr, P.csrc, bias, hout, relu_out ? 1 : 0);
    } else {
        k_edge_scores<1><<<bl, 256>>>(P.xlr, att, P.csrc, P.cdst, P.e);
        k_seg<1><<<sb, 256>>>(P.xlr, P.e, P.rowptr, P.csrc, bias, hout, relu_out ? 1 : 0);
    }
}

extern "C" void kernel_launch(void* const* d_in, const int* in_sizes, int n_in,
                              void* d_out, int out_size) {
    const float* x     = (const float*)d_in[0];
    const int*   ei    = (const int*)d_in[1];
    const float* y     = (const float*)d_in[2];
    const int*   tidx  = (const int*)d_in[3];
    const float* bn0_g = (const float*)d_in[4];
    const float* bn0_b = (const float*)d_in[5];
    const float* W1l   = (const float*)d_in[6];
    const float* W1r   = (const float*)d_in[7];
    const float* a1    = (const float*)d_in[8];
    const float* b1    = (const float*)d_in[9];
    const float* bn1_g = (const float*)d_in[10];
    const float* bn1_b = (const float*)d_in[11];
    const float* W2l   = (const float*)d_in[12];
    const float* W2r   = (const float*)d_in[13];
    const float* a2    = (const float*)d_in[14];
    const float* b2    = (const float*)d_in[15];
    const float* bn2_g = (const float*)d_in[16];
    const float* bn2_b = (const float*)d_in[17];
    const float* W3l   = (const float*)d_in[18];
    const float* W3r   = (const float*)d_in[19];
    const float* a3    = (const float*)d_in[20];
    const float* b3    = (const float*)d_in[21];
    const float* bn3_g = (const float*)d_in[22];
    const float* bn3_b = (const float*)d_in[23];
    const float* W4l   = (const float*)d_in[24];
    const float* W4r   = (const float*)d_in[25];
    const float* a4    = (const float*)d_in[26];
    const float* b4    = (const float*)d_in[27];
    const float* Wh    = (const float*)d_in[28];
    const float* bh    = (const float*)d_in[29];
    float* out = (float*)d_out;
    int ntr = in_sizes[3];

    cudaFuncSetAttribute(k_gemm3bf, cudaFuncAttributeMaxDynamicSharedMemorySize,
                         (int)(3 * STG * sizeof(unsigned)));

    Ptrs P;
    cudaGetSymbolAddress((void**)&P.Ahi, g_Ahi);
    cudaGetSymbolAddress((void**)&P.Alo, g_Alo);
    cudaGetSymbolAddress((void**)&P.Whi, g_Whi);
    cudaGetSymbolAddress((void**)&P.Wlo, g_Wlo);
    cudaGetSymbolAddress((void**)&P.xlr, g_xlr);
    cudaGetSymbolAddress((void**)&P.h, g_h);
    cudaGetSymbolAddress((void**)&P.psum, g_psum);
    cudaGetSymbolAddress((void**)&P.psq, g_psq);
    cudaGetSymbolAddress((void**)&P.e, g_e);
    cudaGetSymbolAddress((void**)&P.pred, g_pred);
    cudaGetSymbolAddress((void**)&P.src, g_src);
    cudaGetSymbolAddress((void**)&P.dst, g_dst);
    cudaGetSymbolAddress((void**)&P.cnt, g_cnt);
    cudaGetSymbolAddress((void**)&P.rowptr, g_rowptr);
    cudaGetSymbolAddress((void**)&P.wr, g_wr);
    cudaGetSymbolAddress((void**)&P.csrc, g_csrc);
    cudaGetSymbolAddress((void**)&P.cdst, g_cdst);

    // launches 0-2: BN0 path. launch 3: big GEMM (ncu target).
    dim3 sg((FIN + 255) / 256, 32);
    k_col_stats_part<<<sg, 256>>>(x, P.psum, P.psq, NN, FIN);
    split_w(W1l, W1r, FIN, FINP, 1024, P);
    dim3 ag((FINP + 63) / 64, 32);
    k_bn_apply_split<<<ag, 256>>>(x, P.psum, P.psq, bn0_g, bn0_b, P.Ahi, P.Alo,
                                  NN, FIN, FINP, 0);
    gemm(P, 2048, FINP);

    // CSR build (once)
    k_build_edges<<<(EE + 255) / 256, 256>>>(ei, P.src, P.dst, P.cnt);
    k_count<<<(ET + 255) / 256, 256>>>(P.dst, P.cnt);
    k_scan<<<1, 1024>>>(P.cnt, P.rowptr, P.wr);
    k_scatter<<<(ET + 255) / 256, 256>>>(P.src, P.dst, P.wr, P.csrc, P.cdst);

    // layer 1 edge phase
    edge_phase(a1, b1, 2, P.h, false, P);

    // layer 2
    bn_split(P.h, bn1_g, bn1_b, 1024, 1024, true, P);
    split_w(W2l, W2r, 1024, 1024, 512, P);
    gemm(P, 1024, 1024);
    edge_phase(a2, b2, 1, P.h, false, P);

    // layer 3
    bn_split(P.h, bn2_g, bn2_b, 512, 512, true, P);
    split_w(W3l, W3r, 512, 512, 512, P);
    gemm(P, 1024, 512);
    edge_phase(a3, b3, 1, P.h, false, P);

    // layer 4
    bn_split(P.h, bn3_g, bn3_b, 512, 512, true, P);
    split_w(W4l, W4r, 512, 512, 512, P);
    gemm(P, 1024, 512);
    edge_phase(a4, b4, 1, P.h, true, P);

    // head + gather
    k_head<<<(NN * 32 + 255) / 256, 256>>>(P.h, Wh, bh, P.pred);
    k_gather<<<(ntr + 255) / 256, 256>>>(P.pred, y, tidx, out, ntr);
}

// round 9
// speedup vs baseline: 3.7388x; 1.3697x over previous
#include <cuda_runtime.h>
#include <cuda_bf16.h>
#include <cstdint>
#include <cstddef>

static constexpr int NN  = 8000;
static constexpr int EE  = 64000;
static constexpr int ET  = 72000;
static constexpr int FIN = 3201;
static constexpr int FINP = 3216;
static constexpr int MT  = 8064;
static constexpr int CH  = 512;

// ---------------- scratch ----------------------------------------------------
__device__ __nv_bfloat16 g_Ahi[(size_t)MT * FINP];
__device__ __nv_bfloat16 g_Alo[(size_t)MT * FINP];
__device__ __nv_bfloat16 g_Whi[(size_t)2048 * FINP];
__device__ __nv_bfloat16 g_Wlo[(size_t)2048 * FINP];
__device__ float g_xlr [(size_t)NN * 2048];   // xl | xr
__device__ float g_h   [(size_t)NN * 1024];
__device__ float g_psum[32 * FIN];
__device__ float g_psq [32 * FIN];
__device__ int   g_src [ET];
__device__ int   g_dst [ET];
__device__ int   g_cnt [NN];
__device__ int   g_rowptr[NN + 1];
__device__ int   g_wr  [NN];
__device__ int   g_csrc[ET];
__device__ int   g_cdst[ET];
__device__ float g_e   [ET * 2];
__device__ float g_pred[NN];

// ---------------- helpers ----------------------------------------------------
__device__ __forceinline__ void cp_async16(unsigned saddr, const void* gptr) {
    asm volatile("cp.async.cg.shared.global [%0], [%1], 16;\n" ::"r"(saddr), "l"(gptr));
}
__device__ __forceinline__ void cp_commit() { asm volatile("cp.async.commit_group;\n"); }
template <int N>
__device__ __forceinline__ void cp_wait() {
    asm volatile("cp.async.wait_group %0;\n" ::"n"(N));
}
__device__ __forceinline__ void ldsm4(unsigned* d, unsigned addr) {
    asm volatile("ldmatrix.sync.aligned.m8n8.x4.shared.b16 {%0,%1,%2,%3}, [%4];\n"
                 : "=r"(d[0]), "=r"(d[1]), "=r"(d[2]), "=r"(d[3]) : "r"(addr));
}

// ---------------- BN: partial stats (no atomics) ------------------------------
__global__ void k_col_stats_part(const float* __restrict__ X, float* __restrict__ psum,
                                 float* __restrict__ psq, int M, int F) {
    int col = blockIdx.x * blockDim.x + threadIdx.x;
    if (col >= F) return;
    int per = (M + 31) / 32;
    int r0 = blockIdx.y * per;
    int r1 = min(M, r0 + per);
    float s = 0.f, q = 0.f;
    for (int r = r0; r < r1; r++) {
        float v = X[(size_t)r * F + col];
        s += v; q += v * v;
    }
    psum[blockIdx.y * F + col] = s;
    psq[blockIdx.y * F + col] = q;
}

__global__ void k_bn_apply_split(const float* __restrict__ in,
                                 const float* __restrict__ psum,
                                 const float* __restrict__ psq,
                                 const float* __restrict__ g, const float* __restrict__ b,
                                 __nv_bfloat16* __restrict__ Ahi,
                                 __nv_bfloat16* __restrict__ Alo,
                                 int M, int F, int Fp, int relu) {
    __shared__ float ssc[64], ssh[64];
    int tid = threadIdx.x;
    int c0 = blockIdx.x * 64;
    if (tid < 64) {
        int c = c0 + tid;
        float sc = 0.f, sh = 0.f;
        if (c < F) {
            float s = 0.f, q = 0.f;
#pragma unroll
            for (int y = 0; y < 32; y++) { s += psum[y * F + c]; q += psq[y * F + c]; }
            float invM = 1.f / (float)M;
            float m = s * invM;
            float v = q * invM - m * m;
            float r = rsqrtf(v + 1e-5f);
            sc = g[c] * r;
            sh = b[c] - m * sc;
        }
        ssc[tid] = sc; ssh[tid] = sh;
    }
    __syncthreads();
    int cl = tid & 63;
    int c = c0 + cl;
    if (c >= Fp) return;
    int rsub = tid >> 6;
    float sc = ssc[cl], sh = ssh[cl];
    int rows_per = MT / 32;  // 252
    int r0 = blockIdx.y * rows_per;
    bool colv = (c < F);
    for (int i = 0; i < rows_per / 4; i++) {
        int r = r0 + i * 4 + rsub;
        float v = 0.f;
        if (r < M && colv) {
            v = in[(size_t)r * F + c] * sc + sh;
            if (relu) v = fmaxf(v, 0.f);
        }
        __nv_bfloat16 hi = __float2bfloat16_rn(v);
        __nv_bfloat16 lo = __float2bfloat16_rn(v - __bfloat162float(hi));
        size_t o = (size_t)r * Fp + c;
        Ahi[o] = hi;
        Alo[o] = lo;
    }
}

// transpose+split both weights into [2N][Kp] planes
__global__ void k_splitw2(const float* __restrict__ Wl, const float* __restrict__ Wr,
                          __nv_bfloat16* __restrict__ Whi, __nv_bfloat16* __restrict__ Wlo,
                          int K, int Kp, int N) {
    __shared__ float tile[32][33];
    int kt = blockIdx.x * 32;
    int nt = blockIdx.y * 32;
    const float* W = (nt < N) ? Wl : Wr;
    int ncol0 = (nt < N) ? nt : nt - N;
    int tx = threadIdx.x, ty = threadIdx.y;
    int k_in = kt + ty;
    tile[ty][tx] = (k_in < K) ? W[(size_t)k_in * N + ncol0 + tx] : 0.f;
    __syncthreads();
    int k_out = kt + tx;
    if (k_out < Kp) {
        float v = tile[tx][ty];
        __nv_bfloat16 hi = __float2bfloat16_rn(v);
        __nv_bfloat16 lo = __float2bfloat16_rn(v - __bfloat162float(hi));
        size_t o = (size_t)(nt + ty) * Kp + k_out;
        Whi[o] = hi;
        Wlo[o] = lo;
    }
}

// ---------------- 3xBF16 GEMM: 512 thr, 4x4 warps, ldmatrix, 3-stage ---------
#define APL 1024
#define STG 4096

__device__ __forceinline__ void mma_bf16(float* c, const unsigned* a, const unsigned* b) {
    asm volatile(
        "mma.sync.aligned.m16n8k16.row.col.f32.bf16.bf16.f32 "
        "{%0,%1,%2,%3}, {%4,%5,%6,%7}, {%8,%9}, {%0,%1,%2,%3};\n"
        : "+f"(c[0]), "+f"(c[1]), "+f"(c[2]), "+f"(c[3])
        : "r"(a[0]), "r"(a[1]), "r"(a[2]), "r"(a[3]), "r"(b[0]), "r"(b[1]));
}

__global__ __launch_bounds__(512, 2) void k_gemm3bf(
    const __nv_bfloat16* __restrict__ Ahi, const __nv_bfloat16* __restrict__ Alo,
    const __nv_bfloat16* __restrict__ Bhi, const __nv_bfloat16* __restrict__ Blo,
    float* __restrict__ C, int M, int Ncols, int Kp) {
    extern __shared__ unsigned sm[];
    unsigned smb = (unsigned)__cvta_generic_to_shared(sm);

    int tid = threadIdx.x;
    int lane = tid & 31;
    int warp = tid >> 5;
    int wm = warp >> 2;        // 0..3
    int wn = warp & 3;         // 0..3
    int gid = lane >> 2;
    int tig = lane & 3;

    int row0 = blockIdx.y * 128;
    int col0 = blockIdx.x * 128;

    // ---- loader mapping: 512 threads, each 1 A chunk + 1 B chunk (16B) ----
    int lp = tid >> 8;          // plane 0=hi 1=lo
    int lr = (tid >> 1) & 127;  // row within tile
    int lc = tid & 1;           // k-chunk 0/1
    int lsw = (lr >> 2) & 1;
    int csw = (lc ^ lsw) * 4;

    const __nv_bfloat16* aRow = (lp ? Alo : Ahi) + (size_t)(row0 + lr) * Kp + lc * 8;
    const __nv_bfloat16* bRow = (lp ? Blo : Bhi) + (size_t)(col0 + lr) * Kp + lc * 8;
    unsigned aDst = (unsigned)(lp * APL + lr * 8 + csw);
    unsigned bDst = 2048u + aDst;

    // ---- ldmatrix lane addresses (word offsets within stage, hi planes) ----
    // A tiles: mt=0,1 at m0 = wm*32 + mt*16; matrices (m0-7,h0)(m8-15,h0)(m0-7,h1)(m8-15,h1)
    unsigned aLds[2], bLds[2];
    {
        int half = (lane >> 4) & 1;
        int mloc = lane & 15;
#pragma unroll
        for (int mt = 0; mt < 2; mt++) {
            int m = wm * 32 + mt * 16 + mloc;
            aLds[mt] = (unsigned)(m * 8 + ((half ^ ((m >> 2) & 1)) * 4));
        }
        int nloc = (lane & 7) | (((lane >> 4) & 1) << 3);
        int halfb = (lane >> 3) & 1;
#pragma unroll
        for (int pr = 0; pr < 2; pr++) {
            int n = wn * 32 + pr * 16 + nloc;
            bLds[pr] = (unsigned)(2048 + n * 8 + ((halfb ^ ((n >> 2) & 1)) * 4));
        }
    }

    float acc[2][4][4];
#pragma unroll
    for (int i = 0; i < 2; i++)
#pragma unroll
        for (int j = 0; j < 4; j++)
#pragma unroll
            for (int q = 0; q < 4; q++) acc[i][j][q] = 0.f;

    int niter = Kp >> 4;

    auto prefetch = [&](int stage, int k0) {
        unsigned sb = smb + (unsigned)stage * (STG * 4);
        cp_async16(sb + aDst * 4, aRow + k0);
        cp_async16(sb + bDst * 4, bRow + k0);
        cp_commit();
    };

    prefetch(0, 0);
    if (niter > 1) prefetch(1, 16);

    for (int it = 0; it < niter; it++) {
        if (it + 2 < niter) {
            prefetch((it + 2) % 3, (it + 2) * 16);
            cp_wait<2>();
        } else if (it + 1 < niter) {
            cp_wait<1>();
        } else {
            cp_wait<0>();
        }
        __syncthreads();

        unsigned sb = smb + (unsigned)(it % 3) * (STG * 4);

        unsigned ah[2][4], al[2][4], bh[2][4], bl[2][4];
#pragma unroll
        for (int mt = 0; mt < 2; mt++) {
            ldsm4(ah[mt], sb + aLds[mt] * 4);
            ldsm4(al[mt], sb + (aLds[mt] + APL) * 4);
        }
#pragma unroll
        for (int pr = 0; pr < 2; pr++) {
            ldsm4(bh[pr], sb + bLds[pr] * 4);
            ldsm4(bl[pr], sb + (bLds[pr] + APL) * 4);
        }

#pragma unroll
        for (int mt = 0; mt < 2; mt++)
#pragma unroll
            for (int nt = 0; nt < 4; nt++) {
                int pr = nt >> 1, of = (nt & 1) * 2;
                mma_bf16(acc[mt][nt], al[mt], &bh[pr][of]);
                mma_bf16(acc[mt][nt], ah[mt], &bl[pr][of]);
                mma_bf16(acc[mt][nt], ah[mt], &bh[pr][of]);
            }
        __syncthreads();
    }

#pragma unroll
    for (int mt = 0; mt < 2; mt++) {
        int gr0 = row0 + wm * 32 + mt * 16 + gid;
#pragma unroll
        for (int nt = 0; nt < 4; nt++) {
            int gc = col0 + wn * 32 + nt * 8 + tig * 2;
            if (gr0 < M) {
                C[(size_t)gr0 * Ncols + gc]     = acc[mt][nt][0];
                C[(size_t)gr0 * Ncols + gc + 1] = acc[mt][nt][1];
            }
            if (gr0 + 8 < M) {
                C[(size_t)(gr0 + 8) * Ncols + gc]     = acc[mt][nt][2];
                C[(size_t)(gr0 + 8) * Ncols + gc + 1] = acc[mt][nt][3];
            }
        }
    }
}

// ---------------- CSR construction -------------------------------------------
__global__ void k_build_edges(const int* __restrict__ ei, int* src, int* dst, int* cnt) {
    int i = blockIdx.x * blockDim.x + threadIdx.x;
    if (i < EE) { src[i] = ei[i]; dst[i] = ei[EE + i]; }
    if (i < NN) { src[EE + i] = i; dst[EE + i] = i; cnt[i] = 0; }
}
__global__ void k_count(const int* __restrict__ dst, int* cnt) {
    int i = blockIdx.x * blockDim.x + threadIdx.x;
    if (i < ET) atomicAdd(&cnt[dst[i]], 1);
}
__global__ void k_scan(const int* __restrict__ cnt, int* rowptr, int* wr) {
    __shared__ int sm[1024];
    __shared__ int carry;
    int tid = threadIdx.x;
    if (tid == 0) carry = 0;
    __syncthreads();
    for (int base = 0; base < NN; base += 1024) {
        int i = base + tid;
        int x = (i < NN) ? cnt[i] : 0;
        sm[tid] = x;
        __syncthreads();
        for (int off = 1; off < 1024; off <<= 1) {
            int v = (tid >= off) ? sm[tid - off] : 0;
            __syncthreads();
            sm[tid] += v;
            __syncthreads();
        }
        int excl = sm[tid] - x + carry;
        if (i < NN) { rowptr[i] = excl; wr[i] = excl; }
        __syncthreads();
        if (tid == 1023) carry += sm[1023];
        __syncthreads();
    }
    if (tid == 0) rowptr[NN] = carry;
}
__global__ void k_scatter(const int* __restrict__ src, const int* __restrict__ dst,
                          int* wr, int* csrc, int* cdst) {
    int i = blockIdx.x * blockDim.x + threadIdx.x;
    if (i >= ET) return;
    int d = dst[i];
    int pos = atomicAdd(&wr[d], 1);
    csrc[pos] = src[i];
    cdst[pos] = d;
}

// ---------------- GATv2 edge scores ------------------------------------------
template <int H>
__global__ void k_edge_scores(const float* __restrict__ xlr,
                              const float* __restrict__ att,
                              const int* __restrict__ csrc, const int* __restrict__ cdst,
                              float* __restrict__ e) {
    int gw = (blockIdx.x * blockDim.x + threadIdx.x) >> 5;
    int lane = threadIdx.x & 31;
    if (gw >= ET * H) return;
    int edge = gw / H, h = gw % H;
    int s = csrc[edge], d = cdst[edge];
    const int stride = 2 * H * CH;
    const float4* pl = (const float4*)(xlr + (size_t)s * stride + h * CH);
    const float4* pr = (const float4*)(xlr + (size_t)d * stride + H * CH + h * CH);
    const float4* pa = (const float4*)(att + h * CH);
    float acc = 0.f;
#pragma unroll
    for (int c = lane; c < CH / 4; c += 32) {
        float4 a = pl[c], b = pr[c], w = pa[c];
        float z0 = a.x + b.x; z0 = z0 > 0.f ? z0 : 0.2f * z0;
        float z1 = a.y + b.y; z1 = z1 > 0.f ? z1 : 0.2f * z1;
        float z2 = a.z + b.z; z2 = z2 > 0.f ? z2 : 0.2f * z2;
        float z3 = a.w + b.w; z3 = z3 > 0.f ? z3 : 0.2f * z3;
        acc += z0 * w.x + z1 * w.y + z2 * w.z + z3 * w.w;
    }
#pragma unroll
    for (int o = 16; o; o >>= 1) acc += __shfl_xor_sync(0xFFFFFFFFu, acc, o);
    if (lane == 0) e[(size_t)edge * H + h] = acc;
}

// ---------------- fused segment softmax + aggregate + bias(+relu) -------------
template <int H>
__global__ void k_seg(const float* __restrict__ xlr, const float* __restrict__ e,
                      const int* __restrict__ rowptr, const int* __restrict__ csrc,
                      const float* __restrict__ bias, float* __restrict__ hout,
                      int relu) {
    int gw = (blockIdx.x * blockDim.x + threadIdx.x) >> 5;
    int lane = threadIdx.x & 31;
    if (gw >= NN * H) return;
    int d = gw / H, h = gw % H;
    int lo = rowptr[d], hi = rowptr[d + 1];

    float m = -3.4e38f;
    for (int p = lo + lane; p < hi; p += 32) m = fmaxf(m, e[(size_t)p * H + h]);
#pragma unroll
    for (int o = 16; o; o >>= 1) m = fmaxf(m, __shfl_xor_sync(0xFFFFFFFFu, m, o));

    float s = 0.f;
    for (int p = lo + lane; p < hi; p += 32) s += expf(e[(size_t)p * H + h] - m);
#pragma unroll
    for (int o = 16; o; o >>= 1) s += __shfl_xor_sync(0xFFFFFFFFu, s, o);
    float inv = 1.f / s;

    const int stride = 2 * H * CH;
    float4 acc[4];
#pragma unroll
    for (int j = 0; j < 4; j++) acc[j] = make_float4(0.f, 0.f, 0.f, 0.f);

    for (int p = lo; p < hi; p++) {
        float a = expf(e[(size_t)p * H + h] - m) * inv;
        const float4* pl = (const float4*)(xlr + (size_t)csrc[p] * stride + h * CH);
#pragma unroll
        for (int j = 0; j < 4; j++) {
            float4 v = pl[lane + 32 * j];
            acc[j].x += a * v.x;
            acc[j].y += a * v.y;
            acc[j].z += a * v.z;
            acc[j].w += a * v.w;
        }
    }

    float invdeg = 1.f / (float)(hi - lo);
    float4* po = (float4*)(hout + (size_t)d * (H * CH) + h * CH);
    const float4* pb = (const float4*)(bias + h * CH);
#pragma unroll
    for (int j = 0; j < 4; j++) {
        float4 b4 = pb[lane + 32 * j];
        float4 w;
        w.x = acc[j].x * invdeg + b4.x;
        w.y = acc[j].y * invdeg + b4.y;
        w.z = acc[j].z * invdeg + b4.z;
        w.w = acc[j].w * invdeg + b4.w;
        if (relu) {
            w.x = fmaxf(w.x, 0.f); w.y = fmaxf(w.y, 0.f);
            w.z = fmaxf(w.z, 0.f); w.w = fmaxf(w.w, 0.f);
        }
        po[lane + 32 * j] = w;
    }
}

// ---------------- head + gather ----------------------------------------------
__global__ void k_head(const float* __restrict__ h, const float* __restrict__ Wh,
                       const float* __restrict__ bh, float* __restrict__ pred) {
    int gw = (blockIdx.x * blockDim.x + threadIdx.x) >> 5;
    int lane = threadIdx.x & 31;
    if (gw >= NN) return;
    const float* ph = h + (size_t)gw * CH;
    float acc = 0.f;
#pragma unroll
    for (int c = lane; c < CH; c += 32) acc += ph[c] * Wh[c];
#pragma unroll
    for (int o = 16; o; o >>= 1) acc += __shfl_xor_sync(0xFFFFFFFFu, acc, o);
    if (lane == 0) {
        float t = acc + bh[0];
        pred[gw] = 1.f / (1.f + expf(-t));
    }
}
__global__ void k_gather(const float* __restrict__ pred, const float* __restrict__ y,
                         const int* __restrict__ tidx, float* __restrict__ out, int ntr) {
    int i = blockIdx.x * blockDim.x + threadIdx.x;
    if (i >= ntr) return;
    int j = tidx[i];
    out[i] = pred[j];
    out[ntr + i] = y[j];
}

// ---------------- host orchestration ------------------------------------------
struct Ptrs {
    __nv_bfloat16 *Ahi, *Alo, *Whi, *Wlo;
    float *xlr, *h, *psum, *psq, *e, *pred;
    int *src, *dst, *cnt, *rowptr, *wr, *csrc, *cdst;
};

static void bn_split(const float* in, const float* g, const float* b, int F, int Fp,
                     bool relu, Ptrs& P) {
    dim3 sg((F + 255) / 256, 32);
    k_col_stats_part<<<sg, 256>>>(in, P.psum, P.psq, NN, F);
    dim3 ag((Fp + 63) / 64, 32);
    k_bn_apply_split<<<ag, 256>>>(in, P.psum, P.psq, g, b, P.Ahi, P.Alo, NN, F, Fp,
                                  relu ? 1 : 0);
}

static void split_w(const float* Wl, const float* Wr, int K, int Kp, int N, Ptrs& P) {
    dim3 g((Kp + 31) / 32, (2 * N) / 32);
    k_splitw2<<<g, dim3(32, 32)>>>(Wl, Wr, P.Whi, P.Wlo, K, Kp, N);
}

static void gemm(Ptrs& P, int Ncols, int Kp) {
    dim3 gg(Ncols / 128, MT / 128);
    size_t smem = 3 * STG * sizeof(unsigned);
    k_gemm3bf<<<gg, 512, smem>>>(P.Ahi, P.Alo, P.Whi, P.Wlo, P.xlr, NN, Ncols, Kp);
}

static void edge_phase(const float* att, const float* bias, int H, float* hout,
                       bool relu_out, Ptrs& P) {
    int bl = (ET * H * 32 + 255) / 256;
    int sb = (NN * H * 32 + 255) / 256;
    if (H == 2) {
        k_edge_scores<2><<<bl, 256>>>(P.xlr, att, P.csrc, P.cdst, P.e);
        k_seg<2><<<sb, 256>>>(P.xlr, P.e, P.rowptr, P.csrc, bias, hout, relu_out ? 1 : 0);
    } else {
        k_edge_scores<1><<<bl, 256>>>(P.xlr, att, P.csrc, P.cdst, P.e);
        k_seg<1><<<sb, 256>>>(P.xlr, P.e, P.rowptr, P.csrc, bias, hout, relu_out ? 1 : 0);
    }
}

extern "C" void kernel_launch(void* const* d_in, const int* in_sizes, int n_in,
                              void* d_out, int out_size) {
    const float* x     = (const float*)d_in[0];
    const int*   ei    = (const int*)d_in[1];
    const float* y     = (const float*)d_in[2];
    const int*   tidx  = (const int*)d_in[3];
    const float* bn0_g = (const float*)d_in[4];
    const float* bn0_b = (const float*)d_in[5];
    const float* W1l   = (const float*)d_in[6];
    const float* W1r   = (const float*)d_in[7];
    const float* a1    = (const float*)d_in[8];
    const float* b1    = (const float*)d_in[9];
    const float* bn1_g = (const float*)d_in[10];
    const float* bn1_b = (const float*)d_in[11];
    const float* W2l   = (const float*)d_in[12];
    const float* W2r   = (const float*)d_in[13];
    const float* a2    = (const float*)d_in[14];
    const float* b2    = (const float*)d_in[15];
    const float* bn2_g = (const float*)d_in[16];
    const float* bn2_b = (const float*)d_in[17];
    const float* W3l   = (const float*)d_in[18];
    const float* W3r   = (const float*)d_in[19];
    const float* a3    = (const float*)d_in[20];
    const float* b3    = (const float*)d_in[21];
    const float* bn3_g = (const float*)d_in[22];
    const float* bn3_b = (const float*)d_in[23];
    const float* W4l   = (const float*)d_in[24];
    const float* W4r   = (const float*)d_in[25];
    const float* a4    = (const float*)d_in[26];
    const float* b4    = (const float*)d_in[27];
    const float* Wh    = (const float*)d_in[28];
    const float* bh    = (const float*)d_in[29];
    float* out = (float*)d_out;
    int ntr = in_sizes[3];

    cudaFuncSetAttribute(k_gemm3bf, cudaFuncAttributeMaxDynamicSharedMemorySize,
                         (int)(3 * STG * sizeof(unsigned)));

    Ptrs P;
    cudaGetSymbolAddress((void**)&P.Ahi, g_Ahi);
    cudaGetSymbolAddress((void**)&P.Alo, g_Alo);
    cudaGetSymbolAddress((void**)&P.Whi, g_Whi);
    cudaGetSymbolAddress((void**)&P.Wlo, g_Wlo);
    cudaGetSymbolAddress((void**)&P.xlr, g_xlr);
    cudaGetSymbolAddress((void**)&P.h, g_h);
    cudaGetSymbolAddress((void**)&P.psum, g_psum);
    cudaGetSymbolAddress((void**)&P.psq, g_psq);
    cudaGetSymbolAddress((void**)&P.e, g_e);
    cudaGetSymbolAddress((void**)&P.pred, g_pred);
    cudaGetSymbolAddress((void**)&P.src, g_src);
    cudaGetSymbolAddress((void**)&P.dst, g_dst);
    cudaGetSymbolAddress((void**)&P.cnt, g_cnt);
    cudaGetSymbolAddress((void**)&P.rowptr, g_rowptr);
    cudaGetSymbolAddress((void**)&P.wr, g_wr);
    cudaGetSymbolAddress((void**)&P.csrc, g_csrc);
    cudaGetSymbolAddress((void**)&P.cdst, g_cdst);

    // launches 0-2: BN0 path. launch 3: big GEMM (ncu target).
    dim3 sg((FIN + 255) / 256, 32);
    k_col_stats_part<<<sg, 256>>>(x, P.psum, P.psq, NN, FIN);
    split_w(W1l, W1r, FIN, FINP, 1024, P);
    dim3 ag((FINP + 63) / 64, 32);
    k_bn_apply_split<<<ag, 256>>>(x, P.psum, P.psq, bn0_g, bn0_b, P.Ahi, P.Alo,
                                  NN, FIN, FINP, 0);
    gemm(P, 2048, FINP);

    // CSR build (once)
    k_build_edges<<<(EE + 255) / 256, 256>>>(ei, P.src, P.dst, P.cnt);
    k_count<<<(ET + 255) / 256, 256>>>(P.dst, P.cnt);
    k_scan<<<1, 1024>>>(P.cnt, P.rowptr, P.wr);
    k_scatter<<<(ET + 255) / 256, 256>>>(P.src, P.dst, P.wr, P.csrc, P.cdst);

    // layer 1 edge phase
    edge_phase(a1, b1, 2, P.h, false, P);

    // layer 2
    bn_split(P.h, bn1_g, bn1_b, 1024, 1024, true, P);
    split_w(W2l, W2r, 1024, 1024, 512, P);
    gemm(P, 1024, 1024);
    edge_phase(a2, b2, 1, P.h, false, P);

    // layer 3
    bn_split(P.h, bn2_g, bn2_b, 512, 512, true, P);
    split_w(W3l, W3r, 512, 512, 512, P);
    gemm(P, 1024, 512);
    edge_phase(a3, b3, 1, P.h, false, P);

    // layer 4
    bn_split(P.h, bn3_g, bn3_b, 512, 512, true, P);
    split_w(W4l, W4r, 512, 512, 512, P);
    gemm(P, 1024, 512);
    edge_phase(a4, b4, 1, P.h, true, P);

    // head + gather
    k_head<<<(NN * 32 + 255) / 256, 256>>>(P.h, Wh, bh, P.pred);
    k_gather<<<(ntr + 255) / 256, 256>>>(P.pred, y, tidx, out, ntr);
}

// round 12
// speedup vs baseline: 3.7999x; 1.0163x over previous
#include <cuda_runtime.h>
#include <cuda_bf16.h>
#include <cstdint>
#include <cstddef>

static constexpr int NN  = 8000;
static constexpr int EE  = 64000;
static constexpr int ET  = 72000;
static constexpr int FIN = 3201;
static constexpr int KP1 = 3232;    // layer-1 K padded to mult of 32
static constexpr int MT  = 8064;
static constexpr int CH  = 512;

// ---------------- scratch ----------------------------------------------------
__device__ __nv_bfloat16 g_Ahi[(size_t)MT * KP1];
__device__ __nv_bfloat16 g_Alo[(size_t)MT * KP1];
__device__ __nv_bfloat16 g_Whi[(size_t)2048 * KP1];
__device__ __nv_bfloat16 g_Wlo[(size_t)2048 * KP1];
__device__ float g_xlr [(size_t)NN * 2048];   // xl | xr
__device__ float g_h   [(size_t)NN * 1024];
__device__ float g_psum[32 * FIN];
__device__ float g_psq [32 * FIN];
__device__ int   g_src [ET];
__device__ int   g_dst [ET];
__device__ int   g_cnt [NN];
__device__ int   g_rowptr[NN + 1];
__device__ int   g_wr  [NN];
__device__ int   g_csrc[ET];
__device__ int   g_cdst[ET];
__device__ float g_e   [ET * 2];
__device__ float g_pred[NN];

// ---------------- helpers ----------------------------------------------------
__device__ __forceinline__ void cp_async16(unsigned saddr, const void* gptr) {
    asm volatile("cp.async.cg.shared.global [%0], [%1], 16;\n" ::"r"(saddr), "l"(gptr));
}
__device__ __forceinline__ void cp_commit() { asm volatile("cp.async.commit_group;\n"); }
template <int N>
__device__ __forceinline__ void cp_wait() {
    asm volatile("cp.async.wait_group %0;\n" ::"n"(N));
}
__device__ __forceinline__ void ldsm4(unsigned* d, unsigned addr) {
    asm volatile("ldmatrix.sync.aligned.m8n8.x4.shared.b16 {%0,%1,%2,%3}, [%4];\n"
                 : "=r"(d[0]), "=r"(d[1]), "=r"(d[2]), "=r"(d[3]) : "r"(addr));
}

// ---------------- BN: partial stats (no atomics) ------------------------------
__global__ void k_col_stats_part(const float* __restrict__ X, float* __restrict__ psum,
                                 float* __restrict__ psq, int M, int F) {
    int col = blockIdx.x * blockDim.x + threadIdx.x;
    if (col >= F) return;
    int per = (M + 31) / 32;
    int r0 = blockIdx.y * per;
    int r1 = min(M, r0 + per);
    float s = 0.f, q = 0.f;
    for (int r = r0; r < r1; r++) {
        float v = X[(size_t)r * F + col];
        s += v; q += v * v;
    }
    psum[blockIdx.y * F + col] = s;
    psq[blockIdx.y * F + col] = q;
}

__global__ void k_bn_apply_split(const float* __restrict__ in,
                                 const float* __restrict__ psum,
                                 const float* __restrict__ psq,
                                 const float* __restrict__ g, const float* __restrict__ b,
                                 __nv_bfloat16* __restrict__ Ahi,
                                 __nv_bfloat16* __restrict__ Alo,
                                 int M, int F, int Fp, int relu) {
    __shared__ float ssc[64], ssh[64];
    int tid = threadIdx.x;
    int c0 = blockIdx.x * 64;
    if (tid < 64) {
        int c = c0 + tid;
        float sc = 0.f, sh = 0.f;
        if (c < F) {
            float s = 0.f, q = 0.f;
#pragma unroll
            for (int y = 0; y < 32; y++) { s += psum[y * F + c]; q += psq[y * F + c]; }
            float invM = 1.f / (float)M;
            float m = s * invM;
            float v = q * invM - m * m;
            float r = rsqrtf(v + 1e-5f);
            sc = g[c] * r;
            sh = b[c] - m * sc;
        }
        ssc[tid] = sc; ssh[tid] = sh;
    }
    __syncthreads();
    int cl = tid & 63;
    int c = c0 + cl;
    if (c >= Fp) return;
    int rsub = tid >> 6;
    float sc = ssc[cl], sh = ssh[cl];
    int rows_per = MT / 32;  // 252
    int r0 = blockIdx.y * rows_per;
    bool colv = (c < F);
    for (int i = 0; i < rows_per / 4; i++) {
        int r = r0 + i * 4 + rsub;
        float v = 0.f;
        if (r < M && colv) {
            v = in[(size_t)r * F + c] * sc + sh;
            if (relu) v = fmaxf(v, 0.f);
        }
        __nv_bfloat16 hi = __float2bfloat16_rn(v);
        __nv_bfloat16 lo = __float2bfloat16_rn(v - __bfloat162float(hi));
        size_t o = (size_t)r * Fp + c;
        Ahi[o] = hi;
        Alo[o] = lo;
    }
}

// transpose+split both weights into [2N][Kp] planes
__global__ void k_splitw2(const float* __restrict__ Wl, const float* __restrict__ Wr,
                          __nv_bfloat16* __restrict__ Whi, __nv_bfloat16* __restrict__ Wlo,
                          int K, int Kp, int N) {
    __shared__ float tile[32][33];
    int kt = blockIdx.x * 32;
    int nt = blockIdx.y * 32;
    const float* W = (nt < N) ? Wl : Wr;
    int ncol0 = (nt < N) ? nt : nt - N;
    int tx = threadIdx.x, ty = threadIdx.y;
    int k_in = kt + ty;
    tile[ty][tx] = (k_in < K) ? W[(size_t)k_in * N + ncol0 + tx] : 0.f;
    __syncthreads();
    int k_out = kt + tx;
    if (k_out < Kp) {
        float v = tile[tx][ty];
        __nv_bfloat16 hi = __float2bfloat16_rn(v);
        __nv_bfloat16 lo = __float2bfloat16_rn(v - __bfloat162float(hi));
        size_t o = (size_t)(nt + ty) * Kp + k_out;
        Whi[o] = hi;
        Wlo[o] = lo;
    }
}

// ---------------- 3xBF16 GEMM: 512 thr, 4x4 warps, BK=32, ldmatrix, 3-stage ---
// stage layout (bytes): A hi 0 | A lo 8192 | B hi 16384 | B lo 24576; stage=32KB
static constexpr int STG_B = 32768;
static constexpr int GEMM_SMEM = 3 * STG_B;   // 96 KB -> 2 CTAs/SM

__device__ __forceinline__ void mma_bf16(float* c, const unsigned* a, const unsigned* b) {
    asm volatile(
        "mma.sync.aligned.m16n8k16.row.col.f32.bf16.bf16.f32 "
        "{%0,%1,%2,%3}, {%4,%5,%6,%7}, {%8,%9}, {%0,%1,%2,%3};\n"
        : "+f"(c[0]), "+f"(c[1]), "+f"(c[2]), "+f"(c[3])
        : "r"(a[0]), "r"(a[1]), "r"(a[2]), "r"(a[3]), "r"(b[0]), "r"(b[1]));
}

__global__ __launch_bounds__(512, 2) void k_gemm3bf(
    const __nv_bfloat16* __restrict__ Ahi, const __nv_bfloat16* __restrict__ Alo,
    const __nv_bfloat16* __restrict__ Bhi, const __nv_bfloat16* __restrict__ Blo,
    float* __restrict__ C, int M, int Ncols, int Kp) {
    extern __shared__ unsigned char smraw[];
    unsigned smb = (unsigned)__cvta_generic_to_shared(smraw);

    int tid = threadIdx.x;
    int lane = tid & 31;
    int warp = tid >> 5;
    int wm = warp >> 2;        // 0..3
    int wn = warp & 3;         // 0..3
    int gid = lane >> 2;
    int tig = lane & 3;

    int row0 = blockIdx.y * 128;
    int col0 = blockIdx.x * 128;

    // ---- loader mapping: 4 chunks (16B) per thread per stage ----
    int l_isB[4], l_pl[4], l_r[4], l_c[4];
    unsigned l_dst[4];
#pragma unroll
    for (int i = 0; i < 4; i++) {
        int ch = i * 512 + tid;
        l_isB[i] = ch >> 10;
        int rem = ch & 511;
        l_pl[i] = (ch >> 9) & 1;
        l_r[i] = rem >> 2;
        l_c[i] = rem & 3;
        int cs = l_c[i] ^ ((l_r[i] >> 1) & 3);
        l_dst[i] = (unsigned)(l_isB[i] * 16384 + l_pl[i] * 8192 + l_r[i] * 64 + cs * 16);
    }

    // ---- ldmatrix addresses per warp (stage-relative) ----
    unsigned aAddr[2][2], bAddr[2][2];  // [mt][kg], [pr][kg]
    {
        int arow = (lane & 7) + (((lane >> 3) & 1) << 3);
        int acb = (lane >> 4) & 1;
#pragma unroll
        for (int mt = 0; mt < 2; mt++) {
            int r = wm * 32 + mt * 16 + arow;
#pragma unroll
            for (int kg = 0; kg < 2; kg++) {
                int c = kg * 2 + acb;
                aAddr[mt][kg] = (unsigned)(r * 64 + ((c ^ ((r >> 1) & 3)) * 16));
            }
        }
        int brow = (lane & 7) + (((lane >> 4) & 1) << 3);
        int bcb = (lane >> 3) & 1;
#pragma unroll
        for (int pr = 0; pr < 2; pr++) {
            int r = wn * 32 + pr * 16 + brow;
#pragma unroll
            for (int kg = 0; kg < 2; kg++) {
                int c = kg * 2 + bcb;
                bAddr[pr][kg] = (unsigned)(16384 + r * 64 + ((c ^ ((r >> 1) & 3)) * 16));
            }
        }
    }

    float acc[2][4][4];
#pragma unroll
    for (int i = 0; i < 2; i++)
#pragma unroll
        for (int j = 0; j < 4; j++)
#pragma unroll
            for (int q = 0; q < 4; q++) acc[i][j][q] = 0.f;

    int niter = Kp >> 5;

    auto prefetch = [&](int s) {
        unsigned sb = smb + (unsigned)(s % 3) * STG_B;
        int k0 = s << 5;
#pragma unroll
        for (int i = 0; i < 4; i++) {
            const __nv_bfloat16* base =
                l_isB[i] ? (l_pl[i] ? Blo : Bhi) : (l_pl[i] ? Alo : Ahi);
            int g0 = l_isB[i] ? col0 : row0;
            const __nv_bfloat16* src = base + (size_t)(g0 + l_r[i]) * Kp + k0 + l_c[i] * 8;
            cp_async16(sb + l_dst[i], src);
        }
        cp_commit();
    };

    prefetch(0);
    if (niter > 1) prefetch(1);

    for (int it = 0; it < niter; it++) {
        if (it + 2 < niter) {
            prefetch(it + 2);
            cp_wait<2>();
        } else if (it + 1 < niter) {
            cp_wait<1>();
        } else {
            cp_wait<0>();
        }
        __syncthreads();

        unsigned sb = smb + (unsigned)(it % 3) * STG_B;

#pragma unroll
        for (int kg = 0; kg < 2; kg++) {
            unsigned ah[2][4], al[2][4], bh[2][4], bl[2][4];
#pragma unroll
            for (int mt = 0; mt < 2; mt++) {
                ldsm4(ah[mt], sb + aAddr[mt][kg]);
                ldsm4(al[mt], sb + aAddr[mt][kg] + 8192);
            }
#pragma unroll
            for (int pr = 0; pr < 2; pr++) {
                ldsm4(bh[pr], sb + bAddr[pr][kg]);
                ldsm4(bl[pr], sb + bAddr[pr][kg] + 8192);
            }
#pragma unroll
            for (int mt = 0; mt < 2; mt++)
#pragma unroll
                for (int nt = 0; nt < 4; nt++) {
                    int pr = nt >> 1, of = (nt & 1) * 2;
                    mma_bf16(acc[mt][nt], al[mt], &bh[pr][of]);
                    mma_bf16(acc[mt][nt], ah[mt], &bl[pr][of]);
                    mma_bf16(acc[mt][nt], ah[mt], &bh[pr][of]);
                }
        }
        __syncthreads();
    }

#pragma unroll
    for (int mt = 0; mt < 2; mt++) {
        int gr0 = row0 + wm * 32 + mt * 16 + gid;
#pragma unroll
        for (int nt = 0; nt < 4; nt++) {
            int gc = col0 + wn * 32 + nt * 8 + tig * 2;
            if (gr0 < M) {
                C[(size_t)gr0 * Ncols + gc]     = acc[mt][nt][0];
                C[(size_t)gr0 * Ncols + gc + 1] = acc[mt][nt][1];
            }
            if (gr0 + 8 < M) {
                C[(size_t)(gr0 + 8) * Ncols + gc]     = acc[mt][nt][2];
                C[(size_t)(gr0 + 8) * Ncols + gc + 1] = acc[mt][nt][3];
            }
        }
    }
}

// ---------------- CSR construction -------------------------------------------
__global__ void k_build_edges(const int* __restrict__ ei, int* src, int* dst, int* cnt) {
    int i = blockIdx.x * blockDim.x + threadIdx.x;
    if (i < EE) { src[i] = ei[i]; dst[i] = ei[EE + i]; }
    if (i < NN) { src[EE + i] = i; dst[EE + i] = i; cnt[i] = 0; }
}
__global__ void k_count(const int* __restrict__ dst, int* cnt) {
    int i = blockIdx.x * blockDim.x + threadIdx.x;
    if (i < ET) atomicAdd(&cnt[dst[i]], 1);
}
__global__ void k_scan(const int* __restrict__ cnt, int* rowptr, int* wr) {
    __shared__ int sm[1024];
    __shared__ int carry;
    int tid = threadIdx.x;
    if (tid == 0) carry = 0;
    __syncthreads();
    for (int base = 0; base < NN; base += 1024) {
        int i = base + tid;
        int x = (i < NN) ? cnt[i] : 0;
        sm[tid] = x;
        __syncthreads();
        for (int off = 1; off < 1024; off <<= 1) {
            int v = (tid >= off) ? sm[tid - off] : 0;
            __syncthreads();
            sm[tid] += v;
            __syncthreads();
        }
        int excl = sm[tid] - x + carry;
        if (i < NN) { rowptr[i] = excl; wr[i] = excl; }
        __syncthreads();
        if (tid == 1023) carry += sm[1023];
        __syncthreads();
    }
    if (tid == 0) rowptr[NN] = carry;
}
__global__ void k_scatter(const int* __restrict__ src, const int* __restrict__ dst,
                          int* wr, int* csrc, int* cdst) {
    int i = blockIdx.x * blockDim.x + threadIdx.x;
    if (i >= ET) return;
    int d = dst[i];
    int pos = atomicAdd(&wr[d], 1);
    csrc[pos] = src[i];
    cdst[pos] = d;
}

// ---------------- GATv2 edge scores ------------------------------------------
template <int H>
__global__ void k_edge_scores(const float* __restrict__ xlr,
                              const float* __restrict__ att,
                              const int* __restrict__ csrc, const int* __restrict__ cdst,
                              float* __restrict__ e) {
    int gw = (blockIdx.x * blockDim.x + threadIdx.x) >> 5;
    int lane = threadIdx.x & 31;
    if (gw >= ET * H) return;
    int edge = gw / H, h = gw % H;
    int s = csrc[edge], d = cdst[edge];
    const int stride = 2 * H * CH;
    const float4* pl = (const float4*)(xlr + (size_t)s * stride + h * CH);
    const float4* pr = (const float4*)(xlr + (size_t)d * stride + H * CH + h * CH);
    const float4* pa = (const float4*)(att + h * CH);
    float acc = 0.f;
#pragma unroll
    for (int c = lane; c < CH / 4; c += 32) {
        float4 a = pl[c], b = pr[c], w = pa[c];
        float z0 = a.x + b.x; z0 = z0 > 0.f ? z0 : 0.2f * z0;
        float z1 = a.y + b.y; z1 = z1 > 0.f ? z1 : 0.2f * z1;
        float z2 = a.z + b.z; z2 = z2 > 0.f ? z2 : 0.2f * z2;
        float z3 = a.w + b.w; z3 = z3 > 0.f ? z3 : 0.2f * z3;
        acc += z0 * w.x + z1 * w.y + z2 * w.z + z3 * w.w;
    }
#pragma unroll
    for (int o = 16; o; o >>= 1) acc += __shfl_xor_sync(0xFFFFFFFFu, acc, o);
    if (lane == 0) e[(size_t)edge * H + h] = acc;
}

// ---------------- fused segment softmax + aggregate + bias(+relu) -------------
template <int H>
__global__ void k_seg(const float* __restrict__ xlr, const float* __restrict__ e,
                      const int* __restrict__ rowptr, const int* __restrict__ csrc,
                      const float* __restrict__ bias, float* __restrict__ hout,
                      int relu) {
    int gw = (blockIdx.x * blockDim.x + threadIdx.x) >> 5;
    int lane = threadIdx.x & 31;
    if (gw >= NN * H) return;
    int d = gw / H, h = gw % H;
    int lo = rowptr[d], hi = rowptr[d + 1];

    float m = -3.4e38f;
    for (int p = lo + lane; p < hi; p += 32) m = fmaxf(m, e[(size_t)p * H + h]);
#pragma unroll
    for (int o = 16; o; o >>= 1) m = fmaxf(m, __shfl_xor_sync(0xFFFFFFFFu, m, o));

    float s = 0.f;
    for (int p = lo + lane; p < hi; p += 32) s += expf(e[(size_t)p * H + h] - m);
#pragma unroll
    for (int o = 16; o; o >>= 1) s += __shfl_xor_sync(0xFFFFFFFFu, s, o);
    float inv = 1.f / s;

    const int stride = 2 * H * CH;
    float4 acc[4];
#pragma unroll
    for (int j = 0; j < 4; j++) acc[j] = make_float4(0.f, 0.f, 0.f, 0.f);

    for (int p = lo; p < hi; p++) {
        float a = expf(e[(size_t)p * H + h] - m) * inv;
        const float4* pl = (const float4*)(xlr + (size_t)csrc[p] * stride + h * CH);
#pragma unroll
        for (int j = 0; j < 4; j++) {
            float4 v = pl[lane + 32 * j];
            acc[j].x += a * v.x;
            acc[j].y += a * v.y;
            acc[j].z += a * v.z;
            acc[j].w += a * v.w;
        }
    }

    float invdeg = 1.f / (float)(hi - lo);
    float4* po = (float4*)(hout + (size_t)d * (H * CH) + h * CH);
    const float4* pb = (const float4*)(bias + h * CH);
#pragma unroll
    for (int j = 0; j < 4; j++) {
        float4 b4 = pb[lane + 32 * j];
        float4 w;
        w.x = acc[j].x * invdeg + b4.x;
        w.y = acc[j].y * invdeg + b4.y;
        w.z = acc[j].z * invdeg + b4.z;
        w.w = acc[j].w * invdeg + b4.w;
        if (relu) {
            w.x = fmaxf(w.x, 0.f); w.y = fmaxf(w.y, 0.f);
            w.z = fmaxf(w.z, 0.f); w.w = fmaxf(w.w, 0.f);
        }
        po[lane + 32 * j] = w;
    }
}

// ---------------- head + gather ----------------------------------------------
__global__ void k_head(const float* __restrict__ h, const float* __restrict__ Wh,
                       const float* __restrict__ bh, float* __restrict__ pred) {
    int gw = (blockIdx.x * blockDim.x + threadIdx.x) >> 5;
    int lane = threadIdx.x & 31;
    if (gw >= NN) return;
    const float* ph = h + (size_t)gw * CH;
    float acc = 0.f;
#pragma unroll
    for (int c = lane; c < CH; c += 32) acc += ph[c] * Wh[c];
#pragma unroll
    for (int o = 16; o; o >>= 1) acc += __shfl_xor_sync(0xFFFFFFFFu, acc, o);
    if (lane == 0) {
        float t = acc + bh[0];
        pred[gw] = 1.f / (1.f + expf(-t));
    }
}
__global__ void k_gather(const float* __restrict__ pred, const float* __restrict__ y,
                         const int* __restrict__ tidx, float* __restrict__ out, int ntr) {
    int i = blockIdx.x * blockDim.x + threadIdx.x;
    if (i >= ntr) return;
    int j = tidx[i];
    out[i] = pred[j];
    out[ntr + i] = y[j];
}

// ---------------- host orchestration ------------------------------------------
struct Ptrs {
    __nv_bfloat16 *Ahi, *Alo, *Whi, *Wlo;
    float *xlr, *h, *psum, *psq, *e, *pred;
    int *src, *dst, *cnt, *rowptr, *wr, *csrc, *cdst;
};

static void bn_split(const float* in, const float* g, const float* b, int F, int Fp,
                     bool relu, Ptrs& P) {
    dim3 sg((F + 255) / 256, 32);
    k_col_stats_part<<<sg, 256>>>(in, P.psum, P.psq, NN, F);
    dim3 ag((Fp + 63) / 64, 32);
    k_bn_apply_split<<<ag, 256>>>(in, P.psum, P.psq, g, b, P.Ahi, P.Alo, NN, F, Fp,
                                  relu ? 1 : 0);
}

static void split_w(const float* Wl, const float* Wr, int K, int Kp, int N, Ptrs& P) {
    dim3 g((Kp + 31) / 32, (2 * N) / 32);
    k_splitw2<<<g, dim3(32, 32)>>>(Wl, Wr, P.Whi, P.Wlo, K, Kp, N);
}

static void gemm(Ptrs& P, int Ncols, int Kp) {
    dim3 gg(Ncols / 128, MT / 128);
    k_gemm3bf<<<gg, 512, GEMM_SMEM>>>(P.Ahi, P.Alo, P.Whi, P.Wlo, P.xlr, NN, Ncols, Kp);
}

static void edge_phase(const float* att, const float* bias, int H, float* hout,
                       bool relu_out, Ptrs& P) {
    int bl = (ET * H * 32 + 255) / 256;
    int sb = (NN * H * 32 + 255) / 256;
    if (H == 2) {
        k_edge_scores<2><<<bl, 256>>>(P.xlr, att, P.csrc, P.cdst, P.e);
        k_seg<2><<<sb, 256>>>(P.xlr, P.e, P.rowptr, P.csrc, bias, hout, relu_out ? 1 : 0);
    } else {
        k_edge_scores<1><<<bl, 256>>>(P.xlr, att, P.csrc, P.cdst, P.e);
        k_seg<1><<<sb, 256>>>(P.xlr, P.e, P.rowptr, P.csrc, bias, hout, relu_out ? 1 : 0);
    }
}

extern "C" void kernel_launch(void* const* d_in, const int* in_sizes, int n_in,
                              void* d_out, int out_size) {
    const float* x     = (const float*)d_in[0];
    const int*   ei    = (const int*)d_in[1];
    const float* y     = (const float*)d_in[2];
    const int*   tidx  = (const int*)d_in[3];
    const float* bn0_g = (const float*)d_in[4];
    const float* bn0_b = (const float*)d_in[5];
    const float* W1l   = (const float*)d_in[6];
    const float* W1r   = (const float*)d_in[7];
    const float* a1    = (const float*)d_in[8];
    const float* b1    = (const float*)d_in[9];
    const float* bn1_g = (const float*)d_in[10];
    const float* bn1_b = (const float*)d_in[11];
    const float* W2l   = (const float*)d_in[12];
    const float* W2r   = (const float*)d_in[13];
    const float* a2    = (const float*)d_in[14];
    const float* b2    = (const float*)d_in[15];
    const float* bn2_g = (const float*)d_in[16];
    const float* bn2_b = (const float*)d_in[17];
    const float* W3l   = (const float*)d_in[18];
    const float* W3r   = (const float*)d_in[19];
    const float* a3    = (const float*)d_in[20];
    const float* b3    = (const float*)d_in[21];
    const float* bn3_g = (const float*)d_in[22];
    const float* bn3_b = (const float*)d_in[23];
    const float* W4l   = (const float*)d_in[24];
    const float* W4r   = (const float*)d_in[25];
    const float* a4    = (const float*)d_in[26];
    const float* b4    = (const float*)d_in[27];
    const float* Wh    = (const float*)d_in[28];
    const float* bh    = (const float*)d_in[29];
    float* out = (float*)d_out;
    int ntr = in_sizes[3];

    cudaFuncSetAttribute(k_gemm3bf, cudaFuncAttributeMaxDynamicSharedMemorySize,
                         GEMM_SMEM);

    Ptrs P;
    cudaGetSymbolAddress((void**)&P.Ahi, g_Ahi);
    cudaGetSymbolAddress((void**)&P.Alo, g_Alo);
    cudaGetSymbolAddress((void**)&P.Whi, g_Whi);
    cudaGetSymbolAddress((void**)&P.Wlo, g_Wlo);
    cudaGetSymbolAddress((void**)&P.xlr, g_xlr);
    cudaGetSymbolAddress((void**)&P.h, g_h);
    cudaGetSymbolAddress((void**)&P.psum, g_psum);
    cudaGetSymbolAddress((void**)&P.psq, g_psq);
    cudaGetSymbolAddress((void**)&P.e, g_e);
    cudaGetSymbolAddress((void**)&P.pred, g_pred);
    cudaGetSymbolAddress((void**)&P.src, g_src);
    cudaGetSymbolAddress((void**)&P.dst, g_dst);
    cudaGetSymbolAddress((void**)&P.cnt, g_cnt);
    cudaGetSymbolAddress((void**)&P.rowptr, g_rowptr);
    cudaGetSymbolAddress((void**)&P.wr, g_wr);
    cudaGetSymbolAddress((void**)&P.csrc, g_csrc);
    cudaGetSymbolAddress((void**)&P.cdst, g_cdst);

    // launches 0-2: BN0 path. launch 3: big GEMM (ncu target).
    dim3 sg((FIN + 255) / 256, 32);
    k_col_stats_part<<<sg, 256>>>(x, P.psum, P.psq, NN, FIN);
    split_w(W1l, W1r, FIN, KP1, 1024, P);
    dim3 ag((KP1 + 63) / 64, 32);
    k_bn_apply_split<<<ag, 256>>>(x, P.psum, P.psq, bn0_g, bn0_b, P.Ahi, P.Alo,
                                  NN, FIN, KP1, 0);
    gemm(P, 2048, KP1);

    // CSR build (once)
    k_build_edges<<<(EE + 255) / 256, 256>>>(ei, P.src, P.dst, P.cnt);
    k_count<<<(ET + 255) / 256, 256>>>(P.dst, P.cnt);
    k_scan<<<1, 1024>>>(P.cnt, P.rowptr, P.wr);
    k_scatter<<<(ET + 255) / 256, 256>>>(P.src, P.dst, P.wr, P.csrc, P.cdst);

    // layer 1 edge phase
    edge_phase(a1, b1, 2, P.h, false, P);

    // layer 2
    bn_split(P.h, bn1_g, bn1_b, 1024, 1024, true, P);
    split_w(W2l, W2r, 1024, 1024, 512, P);
    gemm(P, 1024, 1024);
    edge_phase(a2, b2, 1, P.h, false, P);

    // layer 3
    bn_split(P.h, bn2_g, bn2_b, 512, 512, true, P);
    split_w(W3l, W3r, 512, 512, 512, P);
    gemm(P, 1024, 512);
    edge_phase(a3, b3, 1, P.h, false, P);

    // layer 4
    bn_split(P.h, bn3_g, bn3_b, 512, 512, true, P);
    split_w(W4l, W4r, 512, 512, 512, P);
    gemm(P, 1024, 512);
    edge_phase(a4, b4, 1, P.h, true, P);

    // head + gather
    k_head<<<(NN * 32 + 255) / 256, 256>>>(P.h, Wh, bh, P.pred);
    k_gather<<<(ntr + 255) / 256, 256>>>(P.pred, y, tidx, out, ntr);
}

// round 14
// speedup vs baseline: 5.5374x; 1.4573x over previous
#include <cuda_runtime.h>
#include <cuda_fp16.h>
#include <cstdint>
#include <cstddef>

static constexpr int NN  = 8000;
static constexpr int EE  = 64000;
static constexpr int ET  = 72000;
static constexpr int FIN = 3201;
static constexpr int KP1 = 3232;    // layer-1 K padded to mult of 32
static constexpr int MT  = 8064;
static constexpr int CH  = 512;

// ---------------- scratch ----------------------------------------------------
__device__ __half g_Ahi[(size_t)MT * KP1];
__device__ __half g_Alo[(size_t)MT * KP1];
__device__ __half g_Wh [(size_t)2048 * KP1];  // transposed [n][k], single fp16 plane
__device__ float g_xlr [(size_t)NN * 2048];   // xl | xr
__device__ float g_h   [(size_t)NN * 1024];
__device__ float g_psum[32 * FIN];
__device__ float g_psq [32 * FIN];
__device__ int   g_src [ET];
__device__ int   g_dst [ET];
__device__ int   g_cnt [NN];
__device__ int   g_rowptr[NN + 1];
__device__ int   g_wr  [NN];
__device__ int   g_csrc[ET];
__device__ int   g_cdst[ET];
__device__ float g_e   [ET * 2];
__device__ float g_pred[NN];

// ---------------- helpers ----------------------------------------------------
__device__ __forceinline__ void cp_async16(unsigned saddr, const void* gptr) {
    asm volatile("cp.async.cg.shared.global [%0], [%1], 16;\n" ::"r"(saddr), "l"(gptr));
}
__device__ __forceinline__ void cp_commit() { asm volatile("cp.async.commit_group;\n"); }
template <int N>
__device__ __forceinline__ void cp_wait() {
    asm volatile("cp.async.wait_group %0;\n" ::"n"(N));
}
__device__ __forceinline__ void ldsm4(unsigned* d, unsigned addr) {
    asm volatile("ldmatrix.sync.aligned.m8n8.x4.shared.b16 {%0,%1,%2,%3}, [%4];\n"
                 : "=r"(d[0]), "=r"(d[1]), "=r"(d[2]), "=r"(d[3]) : "r"(addr));
}

// ---------------- BN: partial stats (no atomics) ------------------------------
__global__ void k_col_stats_part(const float* __restrict__ X, float* __restrict__ psum,
                                 float* __restrict__ psq, int M, int F) {
    int col = blockIdx.x * blockDim.x + threadIdx.x;
    if (col >= F) return;
    int per = (M + 31) / 32;
    int r0 = blockIdx.y * per;
    int r1 = min(M, r0 + per);
    float s = 0.f, q = 0.f;
    for (int r = r0; r < r1; r++) {
        float v = X[(size_t)r * F + col];
        s += v; q += v * v;
    }
    psum[blockIdx.y * F + col] = s;
    psq[blockIdx.y * F + col] = q;
}

// BN apply + fp16 hi/lo split into padded planes
__global__ void k_bn_apply_split(const float* __restrict__ in,
                                 const float* __restrict__ psum,
                                 const float* __restrict__ psq,
                                 const float* __restrict__ g, const float* __restrict__ b,
                                 __half* __restrict__ Ahi, __half* __restrict__ Alo,
                                 int M, int F, int Fp, int relu) {
    __shared__ float ssc[64], ssh[64];
    int tid = threadIdx.x;
    int c0 = blockIdx.x * 64;
    if (tid < 64) {
        int c = c0 + tid;
        float sc = 0.f, sh = 0.f;
        if (c < F) {
            float s = 0.f, q = 0.f;
#pragma unroll
            for (int y = 0; y < 32; y++) { s += psum[y * F + c]; q += psq[y * F + c]; }
            float invM = 1.f / (float)M;
            float m = s * invM;
            float v = q * invM - m * m;
            float r = rsqrtf(v + 1e-5f);
            sc = g[c] * r;
            sh = b[c] - m * sc;
        }
        ssc[tid] = sc; ssh[tid] = sh;
    }
    __syncthreads();
    int cl = tid & 63;
    int c = c0 + cl;
    if (c >= Fp) return;
    int rsub = tid >> 6;
    float sc = ssc[cl], sh = ssh[cl];
    int rows_per = MT / 32;  // 252
    int r0 = blockIdx.y * rows_per;
    bool colv = (c < F);
    for (int i = 0; i < rows_per / 4; i++) {
        int r = r0 + i * 4 + rsub;
        float v = 0.f;
        if (r < M && colv) {
            v = in[(size_t)r * F + c] * sc + sh;
            if (relu) v = fmaxf(v, 0.f);
        }
        __half hi = __float2half_rn(v);
        __half lo = __float2half_rn(v - __half2float(hi));
        size_t o = (size_t)r * Fp + c;
        Ahi[o] = hi;
        Alo[o] = lo;
    }
}

// transpose both weights into single fp16 plane [2N][Kp]
__global__ void k_splitw2(const float* __restrict__ Wl, const float* __restrict__ Wr,
                          __half* __restrict__ Wh, int K, int Kp, int N) {
    __shared__ float tile[32][33];
    int kt = blockIdx.x * 32;
    int nt = blockIdx.y * 32;
    const float* W = (nt < N) ? Wl : Wr;
    int ncol0 = (nt < N) ? nt : nt - N;
    int tx = threadIdx.x, ty = threadIdx.y;
    int k_in = kt + ty;
    tile[ty][tx] = (k_in < K) ? W[(size_t)k_in * N + ncol0 + tx] : 0.f;
    __syncthreads();
    int k_out = kt + tx;
    if (k_out < Kp)
        Wh[(size_t)(nt + ty) * Kp + k_out] = __float2half_rn(tile[tx][ty]);
}

// ---------------- 2xFP16 GEMM: 512 thr, 4x4 warps, BK=32, ldmatrix, 3-stage ---
// stage layout (bytes): A hi 0 | A lo 8192 | B 16384; stage=24KB, 3 stages=72KB
static constexpr int STG_B = 24576;
static constexpr int GEMM_SMEM = 3 * STG_B;   // 72 KB -> 2 CTAs/SM

__device__ __forceinline__ void mma_f16(float* c, const unsigned* a, const unsigned* b) {
    asm volatile(
        "mma.sync.aligned.m16n8k16.row.col.f32.f16.f16.f32 "
        "{%0,%1,%2,%3}, {%4,%5,%6,%7}, {%8,%9}, {%0,%1,%2,%3};\n"
        : "+f"(c[0]), "+f"(c[1]), "+f"(c[2]), "+f"(c[3])
        : "r"(a[0]), "r"(a[1]), "r"(a[2]), "r"(a[3]), "r"(b[0]), "r"(b[1]));
}

__global__ __launch_bounds__(512, 2) void k_gemm2h(
    const __half* __restrict__ Ahi, const __half* __restrict__ Alo,
    const __half* __restrict__ Bh,
    float* __restrict__ C, int M, int Ncols, int Kp) {
    extern __shared__ unsigned char smraw[];
    unsigned smb = (unsigned)__cvta_generic_to_shared(smraw);

    int tid = threadIdx.x;
    int lane = tid & 31;
    int warp = tid >> 5;
    int wm = warp >> 2;        // 0..3
    int wn = warp & 3;         // 0..3
    int gid = lane >> 2;
    int tig = lane & 3;

    int row0 = blockIdx.y * 128;
    int col0 = blockIdx.x * 128;

    // ---- loader mapping: 3 chunks (16B) per thread per stage ----
    // regions: 0 = A hi, 1 = A lo, 2 = B  (512 chunks each)
    int l_reg[3], l_r[3], l_c[3];
    unsigned l_dst[3];
#pragma unroll
    for (int i = 0; i < 3; i++) {
        int ch = i * 512 + tid;
        l_reg[i] = ch >> 9;
        int rem = ch & 511;
        l_r[i] = rem >> 2;
        l_c[i] = rem & 3;
        int cs = l_c[i] ^ ((l_r[i] >> 1) & 3);
        l_dst[i] = (unsigned)(l_reg[i] * 8192 + l_r[i] * 64 + cs * 16);
    }

    // ---- ldmatrix addresses per warp (stage-relative, hi plane / B) ----
    unsigned aAddr[2][2], bAddr[2][2];  // [mt][kg], [pr][kg]
    {
        int arow = (lane & 7) + (((lane >> 3) & 1) << 3);
        int acb = (lane >> 4) & 1;
#pragma unroll
        for (int mt = 0; mt < 2; mt++) {
            int r = wm * 32 + mt * 16 + arow;
#pragma unroll
            for (int kg = 0; kg < 2; kg++) {
                int c = kg * 2 + acb;
                aAddr[mt][kg] = (unsigned)(r * 64 + ((c ^ ((r >> 1) & 3)) * 16));
            }
        }
        int brow = (lane & 7) + (((lane >> 4) & 1) << 3);
        int bcb = (lane >> 3) & 1;
#pragma unroll
        for (int pr = 0; pr < 2; pr++) {
            int r = wn * 32 + pr * 16 + brow;
#pragma unroll
            for (int kg = 0; kg < 2; kg++) {
                int c = kg * 2 + bcb;
                bAddr[pr][kg] = (unsigned)(16384 + r * 64 + ((c ^ ((r >> 1) & 3)) * 16));
            }
        }
    }

    float acc[2][4][4];
#pragma unroll
    for (int i = 0; i < 2; i++)
#pragma unroll
        for (int j = 0; j < 4; j++)
#pragma unroll
            for (int q = 0; q < 4; q++) acc[i][j][q] = 0.f;

    int niter = Kp >> 5;

    auto prefetch = [&](int s) {
        unsigned sb = smb + (unsigned)(s % 3) * STG_B;
        int k0 = s << 5;
#pragma unroll
        for (int i = 0; i < 3; i++) {
            const __half* base = (l_reg[i] == 0) ? Ahi : (l_reg[i] == 1 ? Alo : Bh);
            int g0 = (l_reg[i] == 2) ? col0 : row0;
            const __half* src = base + (size_t)(g0 + l_r[i]) * Kp + k0 + l_c[i] * 8;
            cp_async16(sb + l_dst[i], src);
        }
        cp_commit();
    };

    prefetch(0);
    if (niter > 1) prefetch(1);

    for (int it = 0; it < niter; it++) {
        if (it + 2 < niter) {
            prefetch(it + 2);
            cp_wait<2>();
        } else if (it + 1 < niter) {
            cp_wait<1>();
        } else {
            cp_wait<0>();
        }
        __syncthreads();

        unsigned sb = smb + (unsigned)(it % 3) * STG_B;

#pragma unroll
        for (int kg = 0; kg < 2; kg++) {
            unsigned ah[2][4], al[2][4], bf[2][4];
#pragma unroll
            for (int mt = 0; mt < 2; mt++) {
                ldsm4(ah[mt], sb + aAddr[mt][kg]);
                ldsm4(al[mt], sb + aAddr[mt][kg] + 8192);
            }
#pragma unroll
            for (int pr = 0; pr < 2; pr++)
                ldsm4(bf[pr], sb + bAddr[pr][kg]);
#pragma unroll
            for (int mt = 0; mt < 2; mt++)
#pragma unroll
                for (int nt = 0; nt < 4; nt++) {
                    int pr = nt >> 1, of = (nt & 1) * 2;
                    mma_f16(acc[mt][nt], al[mt], &bf[pr][of]);
                    mma_f16(acc[mt][nt], ah[mt], &bf[pr][of]);
                }
        }
        __syncthreads();
    }

#pragma unroll
    for (int mt = 0; mt < 2; mt++) {
        int gr0 = row0 + wm * 32 + mt * 16 + gid;
#pragma unroll
        for (int nt = 0; nt < 4; nt++) {
            int gc = col0 + wn * 32 + nt * 8 + tig * 2;
            if (gr0 < M) {
                C[(size_t)gr0 * Ncols + gc]     = acc[mt][nt][0];
                C[(size_t)gr0 * Ncols + gc + 1] = acc[mt][nt][1];
            }
            if (gr0 + 8 < M) {
                C[(size_t)(gr0 + 8) * Ncols + gc]     = acc[mt][nt][2];
                C[(size_t)(gr0 + 8) * Ncols + gc + 1] = acc[mt][nt][3];
            }
        }
    }
}

// ---------------- CSR construction -------------------------------------------
__global__ void k_build_edges(const int* __restrict__ ei, int* src, int* dst, int* cnt) {
    int i = blockIdx.x * blockDim.x + threadIdx.x;
    if (i < EE) { src[i] = ei[i]; dst[i] = ei[EE + i]; }
    if (i < NN) { src[EE + i] = i; dst[EE + i] = i; cnt[i] = 0; }
}
__global__ void k_count(const int* __restrict__ dst, int* cnt) {
    int i = blockIdx.x * blockDim.x + threadIdx.x;
    if (i < ET) atomicAdd(&cnt[dst[i]], 1);
}
__global__ void k_scan(const int* __restrict__ cnt, int* rowptr, int* wr) {
    __shared__ int sm[1024];
    __shared__ int carry;
    int tid = threadIdx.x;
    if (tid == 0) carry = 0;
    __syncthreads();
    for (int base = 0; base < NN; base += 1024) {
        int i = base + tid;
        int x = (i < NN) ? cnt[i] : 0;
        sm[tid] = x;
        __syncthreads();
        for (int off = 1; off < 1024; off <<= 1) {
            int v = (tid >= off) ? sm[tid - off] : 0;
            __syncthreads();
            sm[tid] += v;
            __syncthreads();
        }
        int excl = sm[tid] - x + carry;
        if (i < NN) { rowptr[i] = excl; wr[i] = excl; }
        __syncthreads();
        if (tid == 1023) carry += sm[1023];
        __syncthreads();
    }
    if (tid == 0) rowptr[NN] = carry;
}
__global__ void k_scatter(const int* __restrict__ src, const int* __restrict__ dst,
                          int* wr, int* csrc, int* cdst) {
    int i = blockIdx.x * blockDim.x + threadIdx.x;
    if (i >= ET) return;
    int d = dst[i];
    int pos = atomicAdd(&wr[d], 1);
    csrc[pos] = src[i];
    cdst[pos] = d;
}

// ---------------- GATv2 edge scores ------------------------------------------
template <int H>
__global__ void k_edge_scores(const float* __restrict__ xlr,
                              const float* __restrict__ att,
                              const int* __restrict__ csrc, const int* __restrict__ cdst,
                              float* __restrict__ e) {
    int gw = (blockIdx.x * blockDim.x + threadIdx.x) >> 5;
    int lane = threadIdx.x & 31;
    if (gw >= ET * H) return;
    int edge = gw / H, h = gw % H;
    int s = csrc[edge], d = cdst[edge];
    const int stride = 2 * H * CH;
    const float4* pl = (const float4*)(xlr + (size_t)s * stride + h * CH);
    const float4* pr = (const float4*)(xlr + (size_t)d * stride + H * CH + h * CH);
    const float4* pa = (const float4*)(att + h * CH);
    float acc = 0.f;
#pragma unroll
    for (int c = lane; c < CH / 4; c += 32) {
        float4 a = pl[c], b = pr[c], w = pa[c];
        float z0 = a.x + b.x; z0 = z0 > 0.f ? z0 : 0.2f * z0;
        float z1 = a.y + b.y; z1 = z1 > 0.f ? z1 : 0.2f * z1;
        float z2 = a.z + b.z; z2 = z2 > 0.f ? z2 : 0.2f * z2;
        float z3 = a.w + b.w; z3 = z3 > 0.f ? z3 : 0.2f * z3;
        acc += z0 * w.x + z1 * w.y + z2 * w.z + z3 * w.w;
    }
#pragma unroll
    for (int o = 16; o; o >>= 1) acc += __shfl_xor_sync(0xFFFFFFFFu, acc, o);
    if (lane == 0) e[(size_t)edge * H + h] = acc;
}

// ---------------- fused segment softmax + aggregate + bias(+relu) -------------
template <int H>
__global__ void k_seg(const float* __restrict__ xlr, const float* __restrict__ e,
                      const int* __restrict__ rowptr, const int* __restrict__ csrc,
                      const float* __restrict__ bias, float* __restrict__ hout,
                      int relu) {
    int gw = (blockIdx.x * blockDim.x + threadIdx.x) >> 5;
    int lane = threadIdx.x & 31;
    if (gw >= NN * H) return;
    int d = gw / H, h = gw % H;
    int lo = rowptr[d], hi = rowptr[d + 1];

    float m = -3.4e38f;
    for (int p = lo + lane; p < hi; p += 32) m = fmaxf(m, e[(size_t)p * H + h]);
#pragma unroll
    for (int o = 16; o; o >>= 1) m = fmaxf(m, __shfl_xor_sync(0xFFFFFFFFu, m, o));

    float s = 0.f;
    for (int p = lo + lane; p < hi; p += 32) s += expf(e[(size_t)p * H + h] - m);
#pragma unroll
    for (int o = 16; o; o >>= 1) s += __shfl_xor_sync(0xFFFFFFFFu, s, o);
    float inv = 1.f / s;

    const int stride = 2 * H * CH;
    float4 acc[4];
#pragma unroll
    for (int j = 0; j < 4; j++) acc[j] = make_float4(0.f, 0.f, 0.f, 0.f);

    for (int p = lo; p < hi; p++) {
        float a = expf(e[(size_t)p * H + h] - m) * inv;
        const float4* pl = (const float4*)(xlr + (size_t)csrc[p] * stride + h * CH);
#pragma unroll
        for (int j = 0; j < 4; j++) {
            float4 v = pl[lane + 32 * j];
            acc[j].x += a * v.x;
            acc[j].y += a * v.y;
            acc[j].z += a * v.z;
            acc[j].w += a * v.w;
        }
    }

    float invdeg = 1.f / (float)(hi - lo);
    float4* po = (float4*)(hout + (size_t)d * (H * CH) + h * CH);
    const float4* pb = (const float4*)(bias + h * CH);
#pragma unroll
    for (int j = 0; j < 4; j++) {
        float4 b4 = pb[lane + 32 * j];
        float4 w;
        w.x = acc[j].x * invdeg + b4.x;
        w.y = acc[j].y * invdeg + b4.y;
        w.z = acc[j].z * invdeg + b4.z;
        w.w = acc[j].w * invdeg + b4.w;
        if (relu) {
            w.x = fmaxf(w.x, 0.f); w.y = fmaxf(w.y, 0.f);
            w.z = fmaxf(w.z, 0.f); w.w = fmaxf(w.w, 0.f);
        }
        po[lane + 32 * j] = w;
    }
}

// ---------------- head + gather ----------------------------------------------
__global__ void k_head(const float* __restrict__ h, const float* __restrict__ Wh,
                       const float* __restrict__ bh, float* __restrict__ pred) {
    int gw = (blockIdx.x * blockDim.x + threadIdx.x) >> 5;
    int lane = threadIdx.x & 31;
    if (gw >= NN) return;
    const float* ph = h + (size_t)gw * CH;
    float acc = 0.f;
#pragma unroll
    for (int c = lane; c < CH; c += 32) acc += ph[c] * Wh[c];
#pragma unroll
    for (int o = 16; o; o >>= 1) acc += __shfl_xor_sync(0xFFFFFFFFu, acc, o);
    if (lane == 0) {
        float t = acc + bh[0];
        pred[gw] = 1.f / (1.f + expf(-t));
    }
}
__global__ void k_gather(const float* __restrict__ pred, const float* __restrict__ y,
                         const int* __restrict__ tidx, float* __restrict__ out, int ntr) {
    int i = blockIdx.x * blockDim.x + threadIdx.x;
    if (i >= ntr) return;
    int j = tidx[i];
    out[i] = pred[j];
    out[ntr + i] = y[j];
}

// ---------------- host orchestration ------------------------------------------
struct Ptrs {
    __half *Ahi, *Alo, *Wh;
    float *xlr, *h, *psum, *psq, *e, *pred;
    int *src, *dst, *cnt, *rowptr, *wr, *csrc, *cdst;
};

static void bn_split(const float* in, const float* g, const float* b, int F, int Fp,
                     bool relu, Ptrs& P) {
    dim3 sg((F + 255) / 256, 32);
    k_col_stats_part<<<sg, 256>>>(in, P.psum, P.psq, NN, F);
    dim3 ag((Fp + 63) / 64, 32);
    k_bn_apply_split<<<ag, 256>>>(in, P.psum, P.psq, g, b, P.Ahi, P.Alo, NN, F, Fp,
                                  relu ? 1 : 0);
}

static void split_w(const float* Wl, const float* Wr, int K, int Kp, int N, Ptrs& P) {
    dim3 g((Kp + 31) / 32, (2 * N) / 32);
    k_splitw2<<<g, dim3(32, 32)>>>(Wl, Wr, P.Wh, K, Kp, N);
}

static void gemm(Ptrs& P, int Ncols, int Kp) {
    dim3 gg(Ncols / 128, MT / 128);
    k_gemm2h<<<gg, 512, GEMM_SMEM>>>(P.Ahi, P.Alo, P.Wh, P.xlr, NN, Ncols, Kp);
}

static void edge_phase(const float* att, const float* bias, int H, float* hout,
                       bool relu_out, Ptrs& P) {
    int bl = (ET * H * 32 + 255) / 256;
    int sb = (NN * H * 32 + 255) / 256;
    if (H == 2) {
        k_edge_scores<2><<<bl, 256>>>(P.xlr, att, P.csrc, P.cdst, P.e);
        k_seg<2><<<sb, 256>>>(P.xlr, P.e, P.rowptr, P.csrc, bias, hout, relu_out ? 1 : 0);
    } else {
        k_edge_scores<1><<<bl, 256>>>(P.xlr, att, P.csrc, P.cdst, P.e);
        k_seg<1><<<sb, 256>>>(P.xlr, P.e, P.rowptr, P.csrc, bias, hout, relu_out ? 1 : 0);
    }
}

extern "C" void kernel_launch(void* const* d_in, const int* in_sizes, int n_in,
                              void* d_out, int out_size) {
    const float* x     = (const float*)d_in[0];
    const int*   ei    = (const int*)d_in[1];
    const float* y     = (const float*)d_in[2];
    const int*   tidx  = (const int*)d_in[3];
    const float* bn0_g = (const float*)d_in[4];
    const float* bn0_b = (const float*)d_in[5];
    const float* W1l   = (const float*)d_in[6];
    const float* W1r   = (const float*)d_in[7];
    const float* a1    = (const float*)d_in[8];
    const float* b1    = (const float*)d_in[9];
    const float* bn1_g = (const float*)d_in[10];
    const float* bn1_b = (const float*)d_in[11];
    const float* W2l   = (const float*)d_in[12];
    const float* W2r   = (const float*)d_in[13];
    const float* a2    = (const float*)d_in[14];
    const float* b2    = (const float*)d_in[15];
    const float* bn2_g = (const float*)d_in[16];
    const float* bn2_b = (const float*)d_in[17];
    const float* W3l   = (const float*)d_in[18];
    const float* W3r   = (const float*)d_in[19];
    const float* a3    = (const float*)d_in[20];
    const float* b3    = (const float*)d_in[21];
    const float* bn3_g = (const float*)d_in[22];
    const float* bn3_b = (const float*)d_in[23];
    const float* W4l   = (const float*)d_in[24];
    const float* W4r   = (const float*)d_in[25];
    const float* a4    = (const float*)d_in[26];
    const float* b4    = (const float*)d_in[27];
    const float* Wh    = (const float*)d_in[28];
    const float* bh    = (const float*)d_in[29];
    float* out = (float*)d_out;
    int ntr = in_sizes[3];

    cudaFuncSetAttribute(k_gemm2h, cudaFuncAttributeMaxDynamicSharedMemorySize,
                         GEMM_SMEM);

    Ptrs P;
    cudaGetSymbolAddress((void**)&P.Ahi, g_Ahi);
    cudaGetSymbolAddress((void**)&P.Alo, g_Alo);
    cudaGetSymbolAddress((void**)&P.Wh, g_Wh);
    cudaGetSymbolAddress((void**)&P.xlr, g_xlr);
    cudaGetSymbolAddress((void**)&P.h, g_h);
    cudaGetSymbolAddress((void**)&P.psum, g_psum);
    cudaGetSymbolAddress((void**)&P.psq, g_psq);
    cudaGetSymbolAddress((void**)&P.e, g_e);
    cudaGetSymbolAddress((void**)&P.pred, g_pred);
    cudaGetSymbolAddress((void**)&P.src, g_src);
    cudaGetSymbolAddress((void**)&P.dst, g_dst);
    cudaGetSymbolAddress((void**)&P.cnt, g_cnt);
    cudaGetSymbolAddress((void**)&P.rowptr, g_rowptr);
    cudaGetSymbolAddress((void**)&P.wr, g_wr);
    cudaGetSymbolAddress((void**)&P.csrc, g_csrc);
    cudaGetSymbolAddress((void**)&P.cdst, g_cdst);

    // launches 0-2: BN0 path. launch 3: big GEMM (ncu target).
    dim3 sg((FIN + 255) / 256, 32);
    k_col_stats_part<<<sg, 256>>>(x, P.psum, P.psq, NN, FIN);
    split_w(W1l, W1r, FIN, KP1, 1024, P);
    dim3 ag((KP1 + 63) / 64, 32);
    k_bn_apply_split<<<ag, 256>>>(x, P.psum, P.psq, bn0_g, bn0_b, P.Ahi, P.Alo,
                                  NN, FIN, KP1, 0);
    gemm(P, 2048, KP1);

    // CSR build (once)
    k_build_edges<<<(EE + 255) / 256, 256>>>(ei, P.src, P.dst, P.cnt);
    k_count<<<(ET + 255) / 256, 256>>>(P.dst, P.cnt);
    k_scan<<<1, 1024>>>(P.cnt, P.rowptr, P.wr);
    k_scatter<<<(ET + 255) / 256, 256>>>(P.src, P.dst, P.wr, P.csrc, P.cdst);

    // layer 1 edge phase
    edge_phase(a1, b1, 2, P.h, false, P);

    // layer 2
    bn_split(P.h, bn1_g, bn1_b, 1024, 1024, true, P);
    split_w(W2l, W2r, 1024, 1024, 512, P);
    gemm(P, 1024, 1024);
    edge_phase(a2, b2, 1, P.h, false, P);

    // layer 3
    bn_split(P.h, bn2_g, bn2_b, 512, 512, true, P);
    split_w(W3l, W3r, 512, 512, 512, P);
    gemm(P, 1024, 512);
    edge_phase(a3, b3, 1, P.h, false, P);

    // layer 4
    bn_split(P.h, bn3_g, bn3_b, 512, 512, true, P);
    split_w(W4l, W4r, 512, 512, 512, P);
    gemm(P, 1024, 512);
    edge_phase(a4, b4, 1, P.h, true, P);

    // head + gather
    k_head<<<(NN * 32 + 255) / 256, 256>>>(P.h, Wh, bh, P.pred);
    k_gather<<<(ntr + 255) / 256, 256>>>(P.pred, y, tidx, out, ntr);
}

// round 15
// speedup vs baseline: 7.2931x; 1.3171x over previous
#include <cuda_runtime.h>
#include <cuda_fp16.h>
#include <cstdint>
#include <cstddef>

static constexpr int NN  = 8000;
static constexpr int EE  = 64000;
static constexpr int ET  = 72000;
static constexpr int FIN = 3201;
static constexpr int KP1 = 3232;    // layer-1 K padded to mult of 32
static constexpr int MT  = 8064;
static constexpr int CH  = 512;

// ---------------- scratch ----------------------------------------------------
__device__ __half g_Ah [(size_t)MT * KP1];
__device__ __half g_Wh [(size_t)2048 * KP1];  // transposed [n][k], fp16
__device__ float g_xlr [(size_t)NN * 2048];   // xl | xr
__device__ float g_h   [(size_t)NN * 1024];
__device__ float g_psum[32 * FIN];
__device__ float g_psq [32 * FIN];
__device__ int   g_src [ET];
__device__ int   g_dst [ET];
__device__ int   g_cnt [NN];
__device__ int   g_rowptr[NN + 1];
__device__ int   g_wr  [NN];
__device__ int   g_csrc[ET];
__device__ int   g_cdst[ET];
__device__ float g_e   [ET * 2];
__device__ float g_pred[NN];

// ---------------- helpers ----------------------------------------------------
__device__ __forceinline__ void cp_async16(unsigned saddr, const void* gptr) {
    asm volatile("cp.async.cg.shared.global [%0], [%1], 16;\n" ::"r"(saddr), "l"(gptr));
}
__device__ __forceinline__ void cp_commit() { asm volatile("cp.async.commit_group;\n"); }
template <int N>
__device__ __forceinline__ void cp_wait() {
    asm volatile("cp.async.wait_group %0;\n" ::"n"(N));
}
__device__ __forceinline__ void ldsm4(unsigned* d, unsigned addr) {
    asm volatile("ldmatrix.sync.aligned.m8n8.x4.shared.b16 {%0,%1,%2,%3}, [%4];\n"
                 : "=r"(d[0]), "=r"(d[1]), "=r"(d[2]), "=r"(d[3]) : "r"(addr));
}

// ---------------- BN: partial stats (no atomics) ------------------------------
__global__ void k_col_stats_part(const float* __restrict__ X, float* __restrict__ psum,
                                 float* __restrict__ psq, int M, int F) {
    int col = blockIdx.x * blockDim.x + threadIdx.x;
    if (col >= F) return;
    int per = (M + 31) / 32;
    int r0 = blockIdx.y * per;
    int r1 = min(M, r0 + per);
    float s = 0.f, q = 0.f;
    for (int r = r0; r < r1; r++) {
        float v = X[(size_t)r * F + col];
        s += v; q += v * v;
    }
    psum[blockIdx.y * F + col] = s;
    psq[blockIdx.y * F + col] = q;
}

// BN apply + single fp16 plane
__global__ void k_bn_apply_split(const float* __restrict__ in,
                                 const float* __restrict__ psum,
                                 const float* __restrict__ psq,
                                 const float* __restrict__ g, const float* __restrict__ b,
                                 __half* __restrict__ Ah,
                                 int M, int F, int Fp, int relu) {
    __shared__ float ssc[64], ssh[64];
    int tid = threadIdx.x;
    int c0 = blockIdx.x * 64;
    if (tid < 64) {
        int c = c0 + tid;
        float sc = 0.f, sh = 0.f;
        if (c < F) {
            float s = 0.f, q = 0.f;
#pragma unroll
            for (int y = 0; y < 32; y++) { s += psum[y * F + c]; q += psq[y * F + c]; }
            float invM = 1.f / (float)M;
            float m = s * invM;
            float v = q * invM - m * m;
            float r = rsqrtf(v + 1e-5f);
            sc = g[c] * r;
            sh = b[c] - m * sc;
        }
        ssc[tid] = sc; ssh[tid] = sh;
    }
    __syncthreads();
    int cl = tid & 63;
    int c = c0 + cl;
    if (c >= Fp) return;
    int rsub = tid >> 6;
    float sc = ssc[cl], sh = ssh[cl];
    int rows_per = MT / 32;  // 252
    int r0 = blockIdx.y * rows_per;
    bool colv = (c < F);
    for (int i = 0; i < rows_per / 4; i++) {
        int r = r0 + i * 4 + rsub;
        float v = 0.f;
        if (r < M && colv) {
            v = in[(size_t)r * F + c] * sc + sh;
            if (relu) v = fmaxf(v, 0.f);
        }
        Ah[(size_t)r * Fp + c] = __float2half_rn(v);
    }
}

// transpose both weights into single fp16 plane [2N][Kp]
__global__ void k_splitw2(const float* __restrict__ Wl, const float* __restrict__ Wr,
                          __half* __restrict__ Wh, int K, int Kp, int N) {
    __shared__ float tile[32][33];
    int kt = blockIdx.x * 32;
    int nt = blockIdx.y * 32;
    const float* W = (nt < N) ? Wl : Wr;
    int ncol0 = (nt < N) ? nt : nt - N;
    int tx = threadIdx.x, ty = threadIdx.y;
    int k_in = kt + ty;
    tile[ty][tx] = (k_in < K) ? W[(size_t)k_in * N + ncol0 + tx] : 0.f;
    __syncthreads();
    int k_out = kt + tx;
    if (k_out < Kp)
        Wh[(size_t)(nt + ty) * Kp + k_out] = __float2half_rn(tile[tx][ty]);
}

// ---------------- FP16 GEMM: 512 thr, 4x4 warps, BK=32, ldmatrix, 3-stage -----
// stage layout (bytes): A 0 | B 8192; stage=16KB, 3 stages=48KB
static constexpr int STG_B = 16384;
static constexpr int GEMM_SMEM = 3 * STG_B;   // 48 KB -> 2 CTAs/SM

__device__ __forceinline__ void mma_f16(float* c, const unsigned* a, const unsigned* b) {
    asm volatile(
        "mma.sync.aligned.m16n8k16.row.col.f32.f16.f16.f32 "
        "{%0,%1,%2,%3}, {%4,%5,%6,%7}, {%8,%9}, {%0,%1,%2,%3};\n"
        : "+f"(c[0]), "+f"(c[1]), "+f"(c[2]), "+f"(c[3])
        : "r"(a[0]), "r"(a[1]), "r"(a[2]), "r"(a[3]), "r"(b[0]), "r"(b[1]));
}

__global__ __launch_bounds__(512, 2) void k_gemmh(
    const __half* __restrict__ Ah, const __half* __restrict__ Bh,
    float* __restrict__ C, int M, int Ncols, int Kp) {
    extern __shared__ unsigned char smraw[];
    unsigned smb = (unsigned)__cvta_generic_to_shared(smraw);

    int tid = threadIdx.x;
    int lane = tid & 31;
    int warp = tid >> 5;
    int wm = warp >> 2;        // 0..3
    int wn = warp & 3;         // 0..3
    int gid = lane >> 2;
    int tig = lane & 3;

    int row0 = blockIdx.y * 128;
    int col0 = blockIdx.x * 128;

    // ---- loader mapping: 2 chunks (16B) per thread per stage ----
    // regions: 0 = A, 1 = B  (512 chunks each)
    int l_reg[2], l_r[2], l_c[2];
    unsigned l_dst[2];
#pragma unroll
    for (int i = 0; i < 2; i++) {
        int ch = i * 512 + tid;
        l_reg[i] = ch >> 9;
        int rem = ch & 511;
        l_r[i] = rem >> 2;
        l_c[i] = rem & 3;
        int cs = l_c[i] ^ ((l_r[i] >> 1) & 3);
        l_dst[i] = (unsigned)(l_reg[i] * 8192 + l_r[i] * 64 + cs * 16);
    }

    // ---- ldmatrix addresses per warp (stage-relative) ----
    unsigned aAddr[2][2], bAddr[2][2];  // [mt][kg], [pr][kg]
    {
        int arow = (lane & 7) + (((lane >> 3) & 1) << 3);
        int acb = (lane >> 4) & 1;
#pragma unroll
        for (int mt = 0; mt < 2; mt++) {
            int r = wm * 32 + mt * 16 + arow;
#pragma unroll
            for (int kg = 0; kg < 2; kg++) {
                int c = kg * 2 + acb;
                aAddr[mt][kg] = (unsigned)(r * 64 + ((c ^ ((r >> 1) & 3)) * 16));
            }
        }
        int brow = (lane & 7) + (((lane >> 4) & 1) << 3);
        int bcb = (lane >> 3) & 1;
#pragma unroll
        for (int pr = 0; pr < 2; pr++) {
            int r = wn * 32 + pr * 16 + brow;
#pragma unroll
            for (int kg = 0; kg < 2; kg++) {
                int c = kg * 2 + bcb;
                bAddr[pr][kg] = (unsigned)(8192 + r * 64 + ((c ^ ((r >> 1) & 3)) * 16));
            }
        }
    }

    float acc[2][4][4];
#pragma unroll
    for (int i = 0; i < 2; i++)
#pragma unroll
        for (int j = 0; j < 4; j++)
#pragma unroll
            for (int q = 0; q < 4; q++) acc[i][j][q] = 0.f;

    int niter = Kp >> 5;

    auto prefetch = [&](int s) {
        unsigned sb = smb + (unsigned)(s % 3) * STG_B;
        int k0 = s << 5;
#pragma unroll
        for (int i = 0; i < 2; i++) {
            const __half* base = l_reg[i] ? Bh : Ah;
            int g0 = l_reg[i] ? col0 : row0;
            const __half* src = base + (size_t)(g0 + l_r[i]) * Kp + k0 + l_c[i] * 8;
            cp_async16(sb + l_dst[i], src);
        }
        cp_commit();
    };

    prefetch(0);
    if (niter > 1) prefetch(1);

    for (int it = 0; it < niter; it++) {
        if (it + 2 < niter) {
            prefetch(it + 2);
            cp_wait<2>();
        } else if (it + 1 < niter) {
            cp_wait<1>();
        } else {
            cp_wait<0>();
        }
        __syncthreads();

        unsigned sb = smb + (unsigned)(it % 3) * STG_B;

#pragma unroll
        for (int kg = 0; kg < 2; kg++) {
            unsigned af[2][4], bf[2][4];
#pragma unroll
            for (int mt = 0; mt < 2; mt++)
                ldsm4(af[mt], sb + aAddr[mt][kg]);
#pragma unroll
            for (int pr = 0; pr < 2; pr++)
                ldsm4(bf[pr], sb + bAddr[pr][kg]);
#pragma unroll
            for (int mt = 0; mt < 2; mt++)
#pragma unroll
                for (int nt = 0; nt < 4; nt++) {
                    int pr = nt >> 1, of = (nt & 1) * 2;
                    mma_f16(acc[mt][nt], af[mt], &bf[pr][of]);
                }
        }
        __syncthreads();
    }

#pragma unroll
    for (int mt = 0; mt < 2; mt++) {
        int gr0 = row0 + wm * 32 + mt * 16 + gid;
#pragma unroll
        for (int nt = 0; nt < 4; nt++) {
            int gc = col0 + wn * 32 + nt * 8 + tig * 2;
            if (gr0 < M) {
                C[(size_t)gr0 * Ncols + gc]     = acc[mt][nt][0];
                C[(size_t)gr0 * Ncols + gc + 1] = acc[mt][nt][1];
            }
            if (gr0 + 8 < M) {
                C[(size_t)(gr0 + 8) * Ncols + gc]     = acc[mt][nt][2];
                C[(size_t)(gr0 + 8) * Ncols + gc + 1] = acc[mt][nt][3];
            }
        }
    }
}

// ---------------- CSR construction -------------------------------------------
__global__ void k_build_edges(const int* __restrict__ ei, int* src, int* dst, int* cnt) {
    int i = blockIdx.x * blockDim.x + threadIdx.x;
    if (i < EE) { src[i] = ei[i]; dst[i] = ei[EE + i]; }
    if (i < NN) { src[EE + i] = i; dst[EE + i] = i; cnt[i] = 0; }
}
__global__ void k_count(const int* __restrict__ dst, int* cnt) {
    int i = blockIdx.x * blockDim.x + threadIdx.x;
    if (i < ET) atomicAdd(&cnt[dst[i]], 1);
}
__global__ void k_scan(const int* __restrict__ cnt, int* rowptr, int* wr) {
    __shared__ int sm[1024];
    __shared__ int carry;
    int tid = threadIdx.x;
    if (tid == 0) carry = 0;
    __syncthreads();
    for (int base = 0; base < NN; base += 1024) {
        int i = base + tid;
        int x = (i < NN) ? cnt[i] : 0;
        sm[tid] = x;
        __syncthreads();
        for (int off = 1; off < 1024; off <<= 1) {
            int v = (tid >= off) ? sm[tid - off] : 0;
            __syncthreads();
            sm[tid] += v;
            __syncthreads();
        }
        int excl = sm[tid] - x + carry;
        if (i < NN) { rowptr[i] = excl; wr[i] = excl; }
        __syncthreads();
        if (tid == 1023) carry += sm[1023];
        __syncthreads();
    }
    if (tid == 0) rowptr[NN] = carry;
}
__global__ void k_scatter(const int* __restrict__ src, const int* __restrict__ dst,
                          int* wr, int* csrc, int* cdst) {
    int i = blockIdx.x * blockDim.x + threadIdx.x;
    if (i >= ET) return;
    int d = dst[i];
    int pos = atomicAdd(&wr[d], 1);
    csrc[pos] = src[i];
    cdst[pos] = d;
}

// ---------------- GATv2 edge scores ------------------------------------------
template <int H>
__global__ void k_edge_scores(const float* __restrict__ xlr,
                              const float* __restrict__ att,
                              const int* __restrict__ csrc, const int* __restrict__ cdst,
                              float* __restrict__ e) {
    int gw = (blockIdx.x * blockDim.x + threadIdx.x) >> 5;
    int lane = threadIdx.x & 31;
    if (gw >= ET * H) return;
    int edge = gw / H, h = gw % H;
    int s = csrc[edge], d = cdst[edge];
    const int stride = 2 * H * CH;
    const float4* pl = (const float4*)(xlr + (size_t)s * stride + h * CH);
    const float4* pr = (const float4*)(xlr + (size_t)d * stride + H * CH + h * CH);
    const float4* pa = (const float4*)(att + h * CH);
    float acc = 0.f;
#pragma unroll
    for (int c = lane; c < CH / 4; c += 32) {
        float4 a = pl[c], b = pr[c], w = pa[c];
        float z0 = a.x + b.x; z0 = z0 > 0.f ? z0 : 0.2f * z0;
        float z1 = a.y + b.y; z1 = z1 > 0.f ? z1 : 0.2f * z1;
        float z2 = a.z + b.z; z2 = z2 > 0.f ? z2 : 0.2f * z2;
        float z3 = a.w + b.w; z3 = z3 > 0.f ? z3 : 0.2f * z3;
        acc += z0 * w.x + z1 * w.y + z2 * w.z + z3 * w.w;
    }
#pragma unroll
    for (int o = 16; o; o >>= 1) acc += __shfl_xor_sync(0xFFFFFFFFu, acc, o);
    if (lane == 0) e[(size_t)edge * H + h] = acc;
}

// ---------------- fused segment softmax + aggregate + bias(+relu) -------------
template <int H>
__global__ void k_seg(const float* __restrict__ xlr, const float* __restrict__ e,
                      const int* __restrict__ rowptr, const int* __restrict__ csrc,
                      const float* __restrict__ bias, float* __restrict__ hout,
                      int relu) {
    int gw = (blockIdx.x * blockDim.x + threadIdx.x) >> 5;
    int lane = threadIdx.x & 31;
    if (gw >= NN * H) return;
    int d = gw / H, h = gw % H;
    int lo = rowptr[d], hi = rowptr[d + 1];

    float m = -3.4e38f;
    for (int p = lo + lane; p < hi; p += 32) m = fmaxf(m, e[(size_t)p * H + h]);
#pragma unroll
    for (int o = 16; o; o >>= 1) m = fmaxf(m, __shfl_xor_sync(0xFFFFFFFFu, m, o));

    float s = 0.f;
    for (int p = lo + lane; p < hi; p += 32) s += expf(e[(size_t)p * H + h] - m);
#pragma unroll
    for (int o = 16; o; o >>= 1) s += __shfl_xor_sync(0xFFFFFFFFu, s, o);
    float inv = 1.f / s;

    const int stride = 2 * H * CH;
    float4 acc[4];
#pragma unroll
    for (int j = 0; j < 4; j++) acc[j] = make_float4(0.f, 0.f, 0.f, 0.f);

    for (int p = lo; p < hi; p++) {
        float a = expf(e[(size_t)p * H + h] - m) * inv;
        const float4* pl = (const float4*)(xlr + (size_t)csrc[p] * stride + h * CH);
#pragma unroll
        for (int j = 0; j < 4; j++) {
            float4 v = pl[lane + 32 * j];
            acc[j].x += a * v.x;
            acc[j].y += a * v.y;
            acc[j].z += a * v.z;
            acc[j].w += a * v.w;
        }
    }

    float invdeg = 1.f / (float)(hi - lo);
    float4* po = (float4*)(hout + (size_t)d * (H * CH) + h * CH);
    const float4* pb = (const float4*)(bias + h * CH);
#pragma unroll
    for (int j = 0; j < 4; j++) {
        float4 b4 = pb[lane + 32 * j];
        float4 w;
        w.x = acc[j].x * invdeg + b4.x;
        w.y = acc[j].y * invdeg + b4.y;
        w.z = acc[j].z * invdeg + b4.z;
        w.w = acc[j].w * invdeg + b4.w;
        if (relu) {
            w.x = fmaxf(w.x, 0.f); w.y = fmaxf(w.y, 0.f);
            w.z = fmaxf(w.z, 0.f); w.w = fmaxf(w.w, 0.f);
        }
        po[lane + 32 * j] = w;
    }
}

// ---------------- head + gather ----------------------------------------------
__global__ void k_head(const float* __restrict__ h, const float* __restrict__ Wh,
                       const float* __restrict__ bh, float* __restrict__ pred) {
    int gw = (blockIdx.x * blockDim.x + threadIdx.x) >> 5;
    int lane = threadIdx.x & 31;
    if (gw >= NN) return;
    const float* ph = h + (size_t)gw * CH;
    float acc = 0.f;
#pragma unroll
    for (int c = lane; c < CH; c += 32) acc += ph[c] * Wh[c];
#pragma unroll
    for (int o = 16; o; o >>= 1) acc += __shfl_xor_sync(0xFFFFFFFFu, acc, o);
    if (lane == 0) {
        float t = acc + bh[0];
        pred[gw] = 1.f / (1.f + expf(-t));
    }
}
__global__ void k_gather(const float* __restrict__ pred, const float* __restrict__ y,
                         const int* __restrict__ tidx, float* __restrict__ out, int ntr) {
    int i = blockIdx.x * blockDim.x + threadIdx.x;
    if (i >= ntr) return;
    int j = tidx[i];
    out[i] = pred[j];
    out[ntr + i] = y[j];
}

// ---------------- host orchestration ------------------------------------------
struct Ptrs {
    __half *Ah, *Wh;
    float *xlr, *h, *psum, *psq, *e, *pred;
    int *src, *dst, *cnt, *rowptr, *wr, *csrc, *cdst;
};

static void bn_split(const float* in, const float* g, const float* b, int F, int Fp,
                     bool relu, Ptrs& P) {
    dim3 sg((F + 255) / 256, 32);
    k_col_stats_part<<<sg, 256>>>(in, P.psum, P.psq, NN, F);
    dim3 ag((Fp + 63) / 64, 32);
    k_bn_apply_split<<<ag, 256>>>(in, P.psum, P.psq, g, b, P.Ah, NN, F, Fp,
                                  relu ? 1 : 0);
}

static void split_w(const float* Wl, const float* Wr, int K, int Kp, int N, Ptrs& P) {
    dim3 g((Kp + 31) / 32, (2 * N) / 32);
    k_splitw2<<<g, dim3(32, 32)>>>(Wl, Wr, P.Wh, K, Kp, N);
}

static void gemm(Ptrs& P, int Ncols, int Kp) {
    dim3 gg(Ncols / 128, MT / 128);
    k_gemmh<<<gg, 512, GEMM_SMEM>>>(P.Ah, P.Wh, P.xlr, NN, Ncols, Kp);
}

static void edge_phase(const float* att, const float* bias, int H, float* hout,
                       bool relu_out, Ptrs& P) {
    int bl = (ET * H * 32 + 255) / 256;
    int sb = (NN * H * 32 + 255) / 256;
    if (H == 2) {
        k_edge_scores<2><<<bl, 256>>>(P.xlr, att, P.csrc, P.cdst, P.e);
        k_seg<2><<<sb, 256>>>(P.xlr, P.e, P.rowptr, P.csrc, bias, hout, relu_out ? 1 : 0);
    } else {
        k_edge_scores<1><<<bl, 256>>>(P.xlr, att, P.csrc, P.cdst, P.e);
        k_seg<1><<<sb, 256>>>(P.xlr, P.e, P.rowptr, P.csrc, bias, hout, relu_out ? 1 : 0);
    }
}

extern "C" void kernel_launch(void* const* d_in, const int* in_sizes, int n_in,
                              void* d_out, int out_size) {
    const float* x     = (const float*)d_in[0];
    const int*   ei    = (const int*)d_in[1];
    const float* y     = (const float*)d_in[2];
    const int*   tidx  = (const int*)d_in[3];
    const float* bn0_g = (const float*)d_in[4];
    const float* bn0_b = (const float*)d_in[5];
    const float* W1l   = (const float*)d_in[6];
    const float* W1r   = (const float*)d_in[7];
    const float* a1    = (const float*)d_in[8];
    const float* b1    = (const float*)d_in[9];
    const float* bn1_g = (const float*)d_in[10];
    const float* bn1_b = (const float*)d_in[11];
    const float* W2l   = (const float*)d_in[12];
    const float* W2r   = (const float*)d_in[13];
    const float* a2    = (const float*)d_in[14];
    const float* b2    = (const float*)d_in[15];
    const float* bn2_g = (const float*)d_in[16];
    const float* bn2_b = (const float*)d_in[17];
    const float* W3l   = (const float*)d_in[18];
    const float* W3r   = (const float*)d_in[19];
    const float* a3    = (const float*)d_in[20];
    const float* b3    = (const float*)d_in[21];
    const float* bn3_g = (const float*)d_in[22];
    const float* bn3_b = (const float*)d_in[23];
    const float* W4l   = (const float*)d_in[24];
    const float* W4r   = (const float*)d_in[25];
    const float* a4    = (const float*)d_in[26];
    const float* b4    = (const float*)d_in[27];
    const float* Wh    = (const float*)d_in[28];
    const float* bh    = (const float*)d_in[29];
    float* out = (float*)d_out;
    int ntr = in_sizes[3];

    cudaFuncSetAttribute(k_gemmh, cudaFuncAttributeMaxDynamicSharedMemorySize,
                         GEMM_SMEM);

    Ptrs P;
    cudaGetSymbolAddress((void**)&P.Ah, g_Ah);
    cudaGetSymbolAddress((void**)&P.Wh, g_Wh);
    cudaGetSymbolAddress((void**)&P.xlr, g_xlr);
    cudaGetSymbolAddress((void**)&P.h, g_h);
    cudaGetSymbolAddress((void**)&P.psum, g_psum);
    cudaGetSymbolAddress((void**)&P.psq, g_psq);
    cudaGetSymbolAddress((void**)&P.e, g_e);
    cudaGetSymbolAddress((void**)&P.pred, g_pred);
    cudaGetSymbolAddress((void**)&P.src, g_src);
    cudaGetSymbolAddress((void**)&P.dst, g_dst);
    cudaGetSymbolAddress((void**)&P.cnt, g_cnt);
    cudaGetSymbolAddress((void**)&P.rowptr, g_rowptr);
    cudaGetSymbolAddress((void**)&P.wr, g_wr);
    cudaGetSymbolAddress((void**)&P.csrc, g_csrc);
    cudaGetSymbolAddress((void**)&P.cdst, g_cdst);

    // launches 0-2: BN0 path. launch 3: big GEMM (ncu target).
    dim3 sg((FIN + 255) / 256, 32);
    k_col_stats_part<<<sg, 256>>>(x, P.psum, P.psq, NN, FIN);
    split_w(W1l, W1r, FIN, KP1, 1024, P);
    dim3 ag((KP1 + 63) / 64, 32);
    k_bn_apply_split<<<ag, 256>>>(x, P.psum, P.psq, bn0_g, bn0_b, P.Ah,
                                  NN, FIN, KP1, 0);
    gemm(P, 2048, KP1);

    // CSR build (once)
    k_build_edges<<<(EE + 255) / 256, 256>>>(ei, P.src, P.dst, P.cnt);
    k_count<<<(ET + 255) / 256, 256>>>(P.dst, P.cnt);
    k_scan<<<1, 1024>>>(P.cnt, P.rowptr, P.wr);
    k_scatter<<<(ET + 255) / 256, 256>>>(P.src, P.dst, P.wr, P.csrc, P.cdst);

    // layer 1 edge phase
    edge_phase(a1, b1, 2, P.h, false, P);

    // layer 2
    bn_split(P.h, bn1_g, bn1_b, 1024, 1024, true, P);
    split_w(W2l, W2r, 1024, 1024, 512, P);
    gemm(P, 1024, 1024);
    edge_phase(a2, b2, 1, P.h, false, P);

    // layer 3
    bn_split(P.h, bn2_g, bn2_b, 512, 512, true, P);
    split_w(W3l, W3r, 512, 512, 512, P);
    gemm(P, 1024, 512);
    edge_phase(a3, b3, 1, P.h, false, P);

    // layer 4
    bn_split(P.h, bn3_g, bn3_b, 512, 512, true, P);
    split_w(W4l, W4r, 512, 512, 512, P);
    gemm(P, 1024, 512);
    edge_phase(a4, b4, 1, P.h, true, P);

    // head + gather
    k_head<<<(NN * 32 + 255) / 256, 256>>>(P.h, Wh, bh, P.pred);
    k_gather<<<(ntr + 255) / 256, 256>>>(P.pred, y, tidx, out, ntr);
}

// round 16
// speedup vs baseline: 7.6289x; 1.0460x over previous
#include <cuda_runtime.h>
#include <cuda_fp16.h>
#include <cstdint>
#include <cstddef>

static constexpr int NN  = 8000;
static constexpr int EE  = 64000;
static constexpr int ET  = 72000;
static constexpr int FIN = 3201;
static constexpr int KP1 = 3232;    // layer-1 K padded to mult of 32
static constexpr int MT  = 8064;
static constexpr int CH  = 512;

// ---------------- scratch ----------------------------------------------------
__device__ __half g_Ah [(size_t)MT * KP1];
__device__ __half g_Wh [(size_t)2048 * KP1];  // transposed [n][k], fp16
__device__ __half g_xlr[(size_t)NN * 2048];   // xl | xr  (fp16)
__device__ float g_h   [(size_t)NN * 1024];
__device__ float g_psum[32 * FIN];
__device__ float g_psq [32 * FIN];
__device__ int   g_src [ET];
__device__ int   g_dst [ET];
__device__ int   g_cnt [NN];
__device__ int   g_rowptr[NN + 1];
__device__ int   g_wr  [NN];
__device__ int   g_csrc[ET];
__device__ int   g_cdst[ET];
__device__ float g_e   [ET * 2];
__device__ float g_pred[NN];

// ---------------- helpers ----------------------------------------------------
__device__ __forceinline__ void cp_async16(unsigned saddr, const void* gptr) {
    asm volatile("cp.async.cg.shared.global [%0], [%1], 16;\n" ::"r"(saddr), "l"(gptr));
}
__device__ __forceinline__ void cp_commit() { asm volatile("cp.async.commit_group;\n"); }
template <int N>
__device__ __forceinline__ void cp_wait() {
    asm volatile("cp.async.wait_group %0;\n" ::"n"(N));
}
__device__ __forceinline__ void ldsm4(unsigned* d, unsigned addr) {
    asm volatile("ldmatrix.sync.aligned.m8n8.x4.shared.b16 {%0,%1,%2,%3}, [%4];\n"
                 : "=r"(d[0]), "=r"(d[1]), "=r"(d[2]), "=r"(d[3]) : "r"(addr));
}

// ---------------- BN: partial stats (no atomics) ------------------------------
__global__ void k_col_stats_part(const float* __restrict__ X, float* __restrict__ psum,
                                 float* __restrict__ psq, int M, int F) {
    int col = blockIdx.x * blockDim.x + threadIdx.x;
    if (col >= F) return;
    int per = (M + 31) / 32;
    int r0 = blockIdx.y * per;
    int r1 = min(M, r0 + per);
    float s = 0.f, q = 0.f;
    for (int r = r0; r < r1; r++) {
        float v = X[(size_t)r * F + col];
        s += v; q += v * v;
    }
    psum[blockIdx.y * F + col] = s;
    psq[blockIdx.y * F + col] = q;
}

// BN apply + single fp16 plane
__global__ void k_bn_apply_split(const float* __restrict__ in,
                                 const float* __restrict__ psum,
                                 const float* __restrict__ psq,
                                 const float* __restrict__ g, const float* __restrict__ b,
                                 __half* __restrict__ Ah,
                                 int M, int F, int Fp, int relu) {
    __shared__ float ssc[64], ssh[64];
    int tid = threadIdx.x;
    int c0 = blockIdx.x * 64;
    if (tid < 64) {
        int c = c0 + tid;
        float sc = 0.f, sh = 0.f;
        if (c < F) {
            float s = 0.f, q = 0.f;
#pragma unroll
            for (int y = 0; y < 32; y++) { s += psum[y * F + c]; q += psq[y * F + c]; }
            float invM = 1.f / (float)M;
            float m = s * invM;
            float v = q * invM - m * m;
            float r = rsqrtf(v + 1e-5f);
            sc = g[c] * r;
            sh = b[c] - m * sc;
        }
        ssc[tid] = sc; ssh[tid] = sh;
    }
    __syncthreads();
    int cl = tid & 63;
    int c = c0 + cl;
    if (c >= Fp) return;
    int rsub = tid >> 6;
    float sc = ssc[cl], sh = ssh[cl];
    int rows_per = MT / 32;  // 252
    int r0 = blockIdx.y * rows_per;
    bool colv = (c < F);
    for (int i = 0; i < rows_per / 4; i++) {
        int r = r0 + i * 4 + rsub;
        float v = 0.f;
        if (r < M && colv) {
            v = in[(size_t)r * F + c] * sc + sh;
            if (relu) v = fmaxf(v, 0.f);
        }
        Ah[(size_t)r * Fp + c] = __float2half_rn(v);
    }
}

// transpose both weights into single fp16 plane [2N][Kp]
__global__ void k_splitw2(const float* __restrict__ Wl, const float* __restrict__ Wr,
                          __half* __restrict__ Wh, int K, int Kp, int N) {
    __shared__ float tile[32][33];
    int kt = blockIdx.x * 32;
    int nt = blockIdx.y * 32;
    const float* W = (nt < N) ? Wl : Wr;
    int ncol0 = (nt < N) ? nt : nt - N;
    int tx = threadIdx.x, ty = threadIdx.y;
    int k_in = kt + ty;
    tile[ty][tx] = (k_in < K) ? W[(size_t)k_in * N + ncol0 + tx] : 0.f;
    __syncthreads();
    int k_out = kt + tx;
    if (k_out < Kp)
        Wh[(size_t)(nt + ty) * Kp + k_out] = __float2half_rn(tile[tx][ty]);
}

// ---------------- FP16 GEMM: 512 thr, 4x4 warps, BK=32, ldmatrix, 3-stage -----
// stage layout (bytes): A 0 | B 8192; stage=16KB, 3 stages=48KB
static constexpr int STG_B = 16384;
static constexpr int GEMM_SMEM = 3 * STG_B;   // 48 KB -> 2 CTAs/SM

__device__ __forceinline__ void mma_f16(float* c, const unsigned* a, const unsigned* b) {
    asm volatile(
        "mma.sync.aligned.m16n8k16.row.col.f32.f16.f16.f32 "
        "{%0,%1,%2,%3}, {%4,%5,%6,%7}, {%8,%9}, {%0,%1,%2,%3};\n"
        : "+f"(c[0]), "+f"(c[1]), "+f"(c[2]), "+f"(c[3])
        : "r"(a[0]), "r"(a[1]), "r"(a[2]), "r"(a[3]), "r"(b[0]), "r"(b[1]));
}

__global__ __launch_bounds__(512, 2) void k_gemmh(
    const __half* __restrict__ Ah, const __half* __restrict__ Bh,
    __half* __restrict__ C, int M, int Ncols, int Kp) {
    extern __shared__ unsigned char smraw[];
    unsigned smb = (unsigned)__cvta_generic_to_shared(smraw);

    int tid = threadIdx.x;
    int lane = tid & 31;
    int warp = tid >> 5;
    int wm = warp >> 2;        // 0..3
    int wn = warp & 3;         // 0..3
    int gid = lane >> 2;
    int tig = lane & 3;

    int row0 = blockIdx.y * 128;
    int col0 = blockIdx.x * 128;

    // ---- loader mapping: 2 chunks (16B) per thread per stage ----
    int l_reg[2], l_r[2], l_c[2];
    unsigned l_dst[2];
#pragma unroll
    for (int i = 0; i < 2; i++) {
        int ch = i * 512 + tid;
        l_reg[i] = ch >> 9;
        int rem = ch & 511;
        l_r[i] = rem >> 2;
        l_c[i] = rem & 3;
        int cs = l_c[i] ^ ((l_r[i] >> 1) & 3);
        l_dst[i] = (unsigned)(l_reg[i] * 8192 + l_r[i] * 64 + cs * 16);
    }

    // ---- ldmatrix addresses per warp (stage-relative) ----
    unsigned aAddr[2][2], bAddr[2][2];  // [mt][kg], [pr][kg]
    {
        int arow = (lane & 7) + (((lane >> 3) & 1) << 3);
        int acb = (lane >> 4) & 1;
#pragma unroll
        for (int mt = 0; mt < 2; mt++) {
            int r = wm * 32 + mt * 16 + arow;
#pragma unroll
            for (int kg = 0; kg < 2; kg++) {
                int c = kg * 2 + acb;
                aAddr[mt][kg] = (unsigned)(r * 64 + ((c ^ ((r >> 1) & 3)) * 16));
            }
        }
        int brow = (lane & 7) + (((lane >> 4) & 1) << 3);
        int bcb = (lane >> 3) & 1;
#pragma unroll
        for (int pr = 0; pr < 2; pr++) {
            int r = wn * 32 + pr * 16 + brow;
#pragma unroll
            for (int kg = 0; kg < 2; kg++) {
                int c = kg * 2 + bcb;
                bAddr[pr][kg] = (unsigned)(8192 + r * 64 + ((c ^ ((r >> 1) & 3)) * 16));
            }
        }
    }

    float acc[2][4][4];
#pragma unroll
    for (int i = 0; i < 2; i++)
#pragma unroll
        for (int j = 0; j < 4; j++)
#pragma unroll
            for (int q = 0; q < 4; q++) acc[i][j][q] = 0.f;

    int niter = Kp >> 5;

    auto prefetch = [&](int s) {
        unsigned sb = smb + (unsigned)(s % 3) * STG_B;
        int k0 = s << 5;
#pragma unroll
        for (int i = 0; i < 2; i++) {
            const __half* base = l_reg[i] ? Bh : Ah;
            int g0 = l_reg[i] ? col0 : row0;
            const __half* src = base + (size_t)(g0 + l_r[i]) * Kp + k0 + l_c[i] * 8;
            cp_async16(sb + l_dst[i], src);
        }
        cp_commit();
    };

    prefetch(0);
    if (niter > 1) prefetch(1);

    for (int it = 0; it < niter; it++) {
        if (it + 2 < niter) {
            prefetch(it + 2);
            cp_wait<2>();
        } else if (it + 1 < niter) {
            cp_wait<1>();
        } else {
            cp_wait<0>();
        }
        __syncthreads();

        unsigned sb = smb + (unsigned)(it % 3) * STG_B;

#pragma unroll
        for (int kg = 0; kg < 2; kg++) {
            unsigned af[2][4], bf[2][4];
#pragma unroll
            for (int mt = 0; mt < 2; mt++)
                ldsm4(af[mt], sb + aAddr[mt][kg]);
#pragma unroll
            for (int pr = 0; pr < 2; pr++)
                ldsm4(bf[pr], sb + bAddr[pr][kg]);
#pragma unroll
            for (int mt = 0; mt < 2; mt++)
#pragma unroll
                for (int nt = 0; nt < 4; nt++) {
                    int pr = nt >> 1, of = (nt & 1) * 2;
                    mma_f16(acc[mt][nt], af[mt], &bf[pr][of]);
                }
        }
        __syncthreads();
    }

    // epilogue: pack to half2 and store
    __half2* Ch = (__half2*)C;
#pragma unroll
    for (int mt = 0; mt < 2; mt++) {
        int gr0 = row0 + wm * 32 + mt * 16 + gid;
#pragma unroll
        for (int nt = 0; nt < 4; nt++) {
            int gc = col0 + wn * 32 + nt * 8 + tig * 2;
            if (gr0 < M)
                Ch[((size_t)gr0 * Ncols + gc) >> 1] =
                    __floats2half2_rn(acc[mt][nt][0], acc[mt][nt][1]);
            if (gr0 + 8 < M)
                Ch[((size_t)(gr0 + 8) * Ncols + gc) >> 1] =
                    __floats2half2_rn(acc[mt][nt][2], acc[mt][nt][3]);
        }
    }
}

// ---------------- CSR construction -------------------------------------------
__global__ void k_build_edges(const int* __restrict__ ei, int* src, int* dst, int* cnt) {
    int i = blockIdx.x * blockDim.x + threadIdx.x;
    if (i < EE) { src[i] = ei[i]; dst[i] = ei[EE + i]; }
    if (i < NN) { src[EE + i] = i; dst[EE + i] = i; cnt[i] = 0; }
}
__global__ void k_count(const int* __restrict__ dst, int* cnt) {
    int i = blockIdx.x * blockDim.x + threadIdx.x;
    if (i < ET) atomicAdd(&cnt[dst[i]], 1);
}
__global__ void k_scan(const int* __restrict__ cnt, int* rowptr, int* wr) {
    __shared__ int sm[1024];
    __shared__ int carry;
    int tid = threadIdx.x;
    if (tid == 0) carry = 0;
    __syncthreads();
    for (int base = 0; base < NN; base += 1024) {
        int i = base + tid;
        int x = (i < NN) ? cnt[i] : 0;
        sm[tid] = x;
        __syncthreads();
        for (int off = 1; off < 1024; off <<= 1) {
            int v = (tid >= off) ? sm[tid - off] : 0;
            __syncthreads();
            sm[tid] += v;
            __syncthreads();
        }
        int excl = sm[tid] - x + carry;
        if (i < NN) { rowptr[i] = excl; wr[i] = excl; }
        __syncthreads();
        if (tid == 1023) carry += sm[1023];
        __syncthreads();
    }
    if (tid == 0) rowptr[NN] = carry;
}
__global__ void k_scatter(const int* __restrict__ src, const int* __restrict__ dst,
                          int* wr, int* csrc, int* cdst) {
    int i = blockIdx.x * blockDim.x + threadIdx.x;
    if (i >= ET) return;
    int d = dst[i];
    int pos = atomicAdd(&wr[d], 1);
    csrc[pos] = src[i];
    cdst[pos] = d;
}

// ---------------- GATv2 edge scores (fp16 gathers) ----------------------------
template <int H>
__global__ void k_edge_scores(const __half* __restrict__ xlr,
                              const float* __restrict__ att,
                              const int* __restrict__ csrc, const int* __restrict__ cdst,
                              float* __restrict__ e) {
    int gw = (blockIdx.x * blockDim.x + threadIdx.x) >> 5;
    int lane = threadIdx.x & 31;
    if (gw >= ET * H) return;
    int edge = gw / H, h = gw % H;
    int s = csrc[edge], d = cdst[edge];
    const int stride = 2 * H * CH;
    const __half2* pl = (const __half2*)(xlr + (size_t)s * stride + h * CH);
    const __half2* pr = (const __half2*)(xlr + (size_t)d * stride + H * CH + h * CH);
    const float2* pa = (const float2*)(att + h * CH);
    float acc = 0.f;
#pragma unroll
    for (int c = lane; c < CH / 2; c += 32) {
        float2 a = __half22float2(pl[c]);
        float2 b = __half22float2(pr[c]);
        float2 w = pa[c];
        float z0 = a.x + b.x; z0 = z0 > 0.f ? z0 : 0.2f * z0;
        float z1 = a.y + b.y; z1 = z1 > 0.f ? z1 : 0.2f * z1;
        acc += z0 * w.x + z1 * w.y;
    }
#pragma unroll
    for (int o = 16; o; o >>= 1) acc += __shfl_xor_sync(0xFFFFFFFFu, acc, o);
    if (lane == 0) e[(size_t)edge * H + h] = acc;
}

// ---------------- fused segment softmax + aggregate + bias(+relu) -------------
template <int H>
__global__ void k_seg(const __half* __restrict__ xlr, const float* __restrict__ e,
                      const int* __restrict__ rowptr, const int* __restrict__ csrc,
                      const float* __restrict__ bias, float* __restrict__ hout,
                      int relu) {
    int gw = (blockIdx.x * blockDim.x + threadIdx.x) >> 5;
    int lane = threadIdx.x & 31;
    if (gw >= NN * H) return;
    int d = gw / H, h = gw % H;
    int lo = rowptr[d], hi = rowptr[d + 1];

    float m = -3.4e38f;
    for (int p = lo + lane; p < hi; p += 32) m = fmaxf(m, e[(size_t)p * H + h]);
#pragma unroll
    for (int o = 16; o; o >>= 1) m = fmaxf(m, __shfl_xor_sync(0xFFFFFFFFu, m, o));

    float s = 0.f;
    for (int p = lo + lane; p < hi; p += 32) s += expf(e[(size_t)p * H + h] - m);
#pragma unroll
    for (int o = 16; o; o >>= 1) s += __shfl_xor_sync(0xFFFFFFFFu, s, o);
    float inv = 1.f / s;

    const int stride = 2 * H * CH;
    float2 acc[8];
#pragma unroll
    for (int j = 0; j < 8; j++) acc[j] = make_float2(0.f, 0.f);

    for (int p = lo; p < hi; p++) {
        float a = expf(e[(size_t)p * H + h] - m) * inv;
        const __half2* pl = (const __half2*)(xlr + (size_t)csrc[p] * stride + h * CH);
#pragma unroll
        for (int j = 0; j < 8; j++) {
            float2 v = __half22float2(pl[lane + 32 * j]);
            acc[j].x += a * v.x;
            acc[j].y += a * v.y;
        }
    }

    float invdeg = 1.f / (float)(hi - lo);
    float2* po = (float2*)(hout + (size_t)d * (H * CH) + h * CH);
    const float2* pb = (const float2*)(bias + h * CH);
#pragma unroll
    for (int j = 0; j < 8; j++) {
        float2 b2 = pb[lane + 32 * j];
        float2 w;
        w.x = acc[j].x * invdeg + b2.x;
        w.y = acc[j].y * invdeg + b2.y;
        if (relu) { w.x = fmaxf(w.x, 0.f); w.y = fmaxf(w.y, 0.f); }
        po[lane + 32 * j] = w;
    }
}

// ---------------- head + gather ----------------------------------------------
__global__ void k_head(const float* __restrict__ h, const float* __restrict__ Wh,
                       const float* __restrict__ bh, float* __restrict__ pred) {
    int gw = (blockIdx.x * blockDim.x + threadIdx.x) >> 5;
    int lane = threadIdx.x & 31;
    if (gw >= NN) return;
    const float* ph = h + (size_t)gw * CH;
    float acc = 0.f;
#pragma unroll
    for (int c = lane; c < CH; c += 32) acc += ph[c] * Wh[c];
#pragma unroll
    for (int o = 16; o; o >>= 1) acc += __shfl_xor_sync(0xFFFFFFFFu, acc, o);
    if (lane == 0) {
        float t = acc + bh[0];
        pred[gw] = 1.f / (1.f + expf(-t));
    }
}
__global__ void k_gather(const float* __restrict__ pred, const float* __restrict__ y,
                         const int* __restrict__ tidx, float* __restrict__ out, int ntr) {
    int i = blockIdx.x * blockDim.x + threadIdx.x;
    if (i >= ntr) return;
    int j = tidx[i];
    out[i] = pred[j];
    out[ntr + i] = y[j];
}

// ---------------- host orchestration ------------------------------------------
struct Ptrs {
    __half *Ah, *Wh, *xlr;
    float *h, *psum, *psq, *e, *pred;
    int *src, *dst, *cnt, *rowptr, *wr, *csrc, *cdst;
};

static void bn_split(const float* in, const float* g, const float* b, int F, int Fp,
                     bool relu, Ptrs& P) {
    dim3 sg((F + 255) / 256, 32);
    k_col_stats_part<<<sg, 256>>>(in, P.psum, P.psq, NN, F);
    dim3 ag((Fp + 63) / 64, 32);
    k_bn_apply_split<<<ag, 256>>>(in, P.psum, P.psq, g, b, P.Ah, NN, F, Fp,
                                  relu ? 1 : 0);
}

static void split_w(const float* Wl, const float* Wr, int K, int Kp, int N, Ptrs& P) {
    dim3 g((Kp + 31) / 32, (2 * N) / 32);
    k_splitw2<<<g, dim3(32, 32)>>>(Wl, Wr, P.Wh, K, Kp, N);
}

static void gemm(Ptrs& P, int Ncols, int Kp) {
    dim3 gg(Ncols / 128, MT / 128);
    k_gemmh<<<gg, 512, GEMM_SMEM>>>(P.Ah, P.Wh, P.xlr, NN, Ncols, Kp);
}

static void edge_phase(const float* att, const float* bias, int H, float* hout,
                       bool relu_out, Ptrs& P) {
    int bl = (ET * H * 32 + 255) / 256;
    int sb = (NN * H * 32 + 255) / 256;
    if (H == 2) {
        k_edge_scores<2><<<bl, 256>>>(P.xlr, att, P.csrc, P.cdst, P.e);
        k_seg<2><<<sb, 256>>>(P.xlr, P.e, P.rowptr, P.csrc, bias, hout, relu_out ? 1 : 0);
    } else {
        k_edge_scores<1><<<bl, 256>>>(P.xlr, att, P.csrc, P.cdst, P.e);
        k_seg<1><<<sb, 256>>>(P.xlr, P.e, P.rowptr, P.csrc, bias, hout, relu_out ? 1 : 0);
    }
}

extern "C" void kernel_launch(void* const* d_in, const int* in_sizes, int n_in,
                              void* d_out, int out_size) {
    const float* x     = (const float*)d_in[0];
    const int*   ei    = (const int*)d_in[1];
    const float* y     = (const float*)d_in[2];
    const int*   tidx  = (const int*)d_in[3];
    const float* bn0_g = (const float*)d_in[4];
    const float* bn0_b = (const float*)d_in[5];
    const float* W1l   = (const float*)d_in[6];
    const float* W1r   = (const float*)d_in[7];
    const float* a1    = (const float*)d_in[8];
    const float* b1    = (const float*)d_in[9];
    const float* bn1_g = (const float*)d_in[10];
    const float* bn1_b = (const float*)d_in[11];
    const float* W2l   = (const float*)d_in[12];
    const float* W2r   = (const float*)d_in[13];
    const float* a2    = (const float*)d_in[14];
    const float* b2    = (const float*)d_in[15];
    const float* bn2_g = (const float*)d_in[16];
    const float* bn2_b = (const float*)d_in[17];
    const float* W3l   = (const float*)d_in[18];
    const float* W3r   = (const float*)d_in[19];
    const float* a3    = (const float*)d_in[20];
    const float* b3    = (const float*)d_in[21];
    const float* bn3_g = (const float*)d_in[22];
    const float* bn3_b = (const float*)d_in[23];
    const float* W4l   = (const float*)d_in[24];
    const float* W4r   = (const float*)d_in[25];
    const float* a4    = (const float*)d_in[26];
    const float* b4    = (const float*)d_in[27];
    const float* Wh    = (const float*)d_in[28];
    const float* bh    = (const float*)d_in[29];
    float* out = (float*)d_out;
    int ntr = in_sizes[3];

    cudaFuncSetAttribute(k_gemmh, cudaFuncAttributeMaxDynamicSharedMemorySize,
                         GEMM_SMEM);

    Ptrs P;
    cudaGetSymbolAddress((void**)&P.Ah, g_Ah);
    cudaGetSymbolAddress((void**)&P.Wh, g_Wh);
    cudaGetSymbolAddress((void**)&P.xlr, g_xlr);
    cudaGetSymbolAddress((void**)&P.h, g_h);
    cudaGetSymbolAddress((void**)&P.psum, g_psum);
    cudaGetSymbolAddress((void**)&P.psq, g_psq);
    cudaGetSymbolAddress((void**)&P.e, g_e);
    cudaGetSymbolAddress((void**)&P.pred, g_pred);
    cudaGetSymbolAddress((void**)&P.src, g_src);
    cudaGetSymbolAddress((void**)&P.dst, g_dst);
    cudaGetSymbolAddress((void**)&P.cnt, g_cnt);
    cudaGetSymbolAddress((void**)&P.rowptr, g_rowptr);
    cudaGetSymbolAddress((void**)&P.wr, g_wr);
    cudaGetSymbolAddress((void**)&P.csrc, g_csrc);
    cudaGetSymbolAddress((void**)&P.cdst, g_cdst);

    // launches 0-2: BN0 path. launch 3: big GEMM (ncu target).
    dim3 sg((FIN + 255) / 256, 32);
    k_col_stats_part<<<sg, 256>>>(x, P.psum, P.psq, NN, FIN);
    split_w(W1l, W1r, FIN, KP1, 1024, P);
    dim3 ag((KP1 + 63) / 64, 32);
    k_bn_apply_split<<<ag, 256>>>(x, P.psum, P.psq, bn0_g, bn0_b, P.Ah,
                                  NN, FIN, KP1, 0);
    gemm(P, 2048, KP1);

    // CSR build (once)
    k_build_edges<<<(EE + 255) / 256, 256>>>(ei, P.src, P.dst, P.cnt);
    k_count<<<(ET + 255) / 256, 256>>>(P.dst, P.cnt);
    k_scan<<<1, 1024>>>(P.cnt, P.rowptr, P.wr);
    k_scatter<<<(ET + 255) / 256, 256>>>(P.src, P.dst, P.wr, P.csrc, P.cdst);

    // layer 1 edge phase
    edge_phase(a1, b1, 2, P.h, false, P);

    // layer 2
    bn_split(P.h, bn1_g, bn1_b, 1024, 1024, true, P);
    split_w(W2l, W2r, 1024, 1024, 512, P);
    gemm(P, 1024, 1024);
    edge_phase(a2, b2, 1, P.h, false, P);

    // layer 3
    bn_split(P.h, bn2_g, bn2_b, 512, 512, true, P);
    split_w(W3l, W3r, 512, 512, 512, P);
    gemm(P, 1024, 512);
    edge_phase(a3, b3, 1, P.h, false, P);

    // layer 4
    bn_split(P.h, bn3_g, bn3_b, 512, 512, true, P);
    split_w(W4l, W4r, 512, 512, 512, P);
    gemm(P, 1024, 512);
    edge_phase(a4, b4, 1, P.h, true, P);

    // head + gather
    k_head<<<(NN * 32 + 255) / 256, 256>>>(P.h, Wh, bh, P.pred);
    k_gather<<<(ntr + 255) / 256, 256>>>(P.pred, y, tidx, out, ntr);
}